// round 3
// baseline (speedup 1.0000x reference)
#include <cuda_runtime.h>

#define NTOK 16384          // B*N = 2*8192
#define NSEQ 8192
#define DM   768
#define DFF  3072
#define NH   12
#define HD   64

// ---------------- scratch (device globals; no allocation allowed) ----------
__device__ float g_x [NTOK * DM];
__device__ float g_q [NTOK * DM];
__device__ float g_k [NTOK * DM];
__device__ float g_v [NTOK * DM];
__device__ float g_f1[NTOK * DFF];
__device__ float g_f2[NTOK * DFF];

// ---------------- LayerNorm: one block per row ----------------------------
__global__ void ln_kernel(const float* __restrict__ x, const float* __restrict__ w,
                          const float* __restrict__ b, float* __restrict__ y, int C) {
    long row = blockIdx.x;
    const float* xr = x + row * (long)C;
    float s = 0.f, ss = 0.f;
    for (int c = threadIdx.x; c < C; c += 256) {
        float v = xr[c];
        s += v; ss += v * v;
    }
    for (int o = 16; o; o >>= 1) {
        s  += __shfl_xor_sync(0xffffffffu, s,  o);
        ss += __shfl_xor_sync(0xffffffffu, ss, o);
    }
    __shared__ float sh[2][8];
    int wi = threadIdx.x >> 5, li = threadIdx.x & 31;
    if (li == 0) { sh[0][wi] = s; sh[1][wi] = ss; }
    __syncthreads();
    if (threadIdx.x < 32) {
        s  = (li < 8) ? sh[0][li] : 0.f;
        ss = (li < 8) ? sh[1][li] : 0.f;
        for (int o = 4; o; o >>= 1) {
            s  += __shfl_xor_sync(0xffffffffu, s,  o);
            ss += __shfl_xor_sync(0xffffffffu, ss, o);
        }
        if (li == 0) { sh[0][0] = s; sh[1][0] = ss; }
    }
    __syncthreads();
    float mean = sh[0][0] / (float)C;
    float var  = sh[1][0] / (float)C - mean * mean;
    float rstd = rsqrtf(var + 1e-5f);
    float* yr = y + row * (long)C;
    for (int c = threadIdx.x; c < C; c += 256)
        yr[c] = (xr[c] - mean) * rstd * w[c] + b[c];
}

// ---------------- zero fill ------------------------------------------------
__global__ void zero_kernel(float4* __restrict__ p, long n4) {
    long i = (long)blockIdx.x * blockDim.x + threadIdx.x;
    long stride = (long)gridDim.x * blockDim.x;
    float4 z = make_float4(0.f, 0.f, 0.f, 0.f);
    for (; i < n4; i += stride) p[i] = z;
}

// ---------------- SGEMM: C = A[M,K] @ B[K,N] + bias (opt relu) -------------
// BM=BN=128, BK=8, 256 threads, 8x8 microtile.
template <bool RELU>
__global__ void sgemm_kernel(const float* __restrict__ A, const float* __restrict__ B,
                             const float* __restrict__ bias, float* __restrict__ C,
                             int M, int N, int K) {
    const int BM = 128, BN = 128, BK = 8;
    __shared__ float As[BK][BM];
    __shared__ float Bs[BK][BN];

    int tid = threadIdx.x;
    const float* Ap = A + (long)blockIdx.y * BM * K;
    const float* Bp = B + (long)blockIdx.x * BN;
    float* Cp = C + (long)blockIdx.y * BM * N + (long)blockIdx.x * BN;
    const float* bp = bias + (long)blockIdx.x * BN;

    int aRow = tid >> 1, aCol = (tid & 1) * 4;      // 128 rows x 8 cols, float4
    int bRow = tid >> 5, bCol = (tid & 31) * 4;     // 8 rows x 128 cols, float4
    int ty = tid >> 4, tx = tid & 15;

    float acc[8][8];
#pragma unroll
    for (int i = 0; i < 8; i++)
#pragma unroll
        for (int j = 0; j < 8; j++) acc[i][j] = 0.f;

    float ar[8], br[8];
    for (int k0 = 0; k0 < K; k0 += BK) {
        float4 a4 = *(const float4*)(Ap + (long)aRow * K + k0 + aCol);
        As[aCol + 0][aRow] = a4.x;
        As[aCol + 1][aRow] = a4.y;
        As[aCol + 2][aRow] = a4.z;
        As[aCol + 3][aRow] = a4.w;
        *(float4*)&Bs[bRow][bCol] = *(const float4*)(Bp + (long)(k0 + bRow) * N + bCol);
        __syncthreads();
#pragma unroll
        for (int kk = 0; kk < BK; kk++) {
            *(float4*)&ar[0] = *(float4*)&As[kk][ty * 8];
            *(float4*)&ar[4] = *(float4*)&As[kk][ty * 8 + 4];
            *(float4*)&br[0] = *(float4*)&Bs[kk][tx * 8];
            *(float4*)&br[4] = *(float4*)&Bs[kk][tx * 8 + 4];
#pragma unroll
            for (int i = 0; i < 8; i++)
#pragma unroll
                for (int j = 0; j < 8; j++) acc[i][j] += ar[i] * br[j];
        }
        __syncthreads();
    }
#pragma unroll
    for (int i = 0; i < 8; i++) {
        long row = ty * 8 + i;
#pragma unroll
        for (int j = 0; j < 8; j += 4) {
            int col = tx * 8 + j;
            float4 o;
            o.x = acc[i][j + 0] + bp[col + 0];
            o.y = acc[i][j + 1] + bp[col + 1];
            o.z = acc[i][j + 2] + bp[col + 2];
            o.w = acc[i][j + 3] + bp[col + 3];
            if (RELU) {
                o.x = fmaxf(o.x, 0.f); o.y = fmaxf(o.y, 0.f);
                o.z = fmaxf(o.z, 0.f); o.w = fmaxf(o.w, 0.f);
            }
            *(float4*)(Cp + row * N + col) = o;
        }
    }
}

// ---------------- dilated flash attention ----------------------------------
// All groups: effective segment length 2048. Block = 64 queries of one
// (batch, group, segment, head); streams 32 KV tiles of 64 with online softmax.
// smem: Qs [d][68], Ks [d][68] (reused as Ps [kv][68]), Vs [kv][68].
__constant__ int c_seg[3] = {2048, 4096, 8192};
__constant__ int c_dil[3] = {1, 2, 4};

__global__ void attn_kernel(const float* __restrict__ Q, const float* __restrict__ K,
                            const float* __restrict__ V, float* __restrict__ O) {
    extern __shared__ float sm[];
    float* Qs = sm;                 // [64][68], d-major
    float* Ks = sm + 64 * 68;       // [64][68], d-major; reused as Ps [kv][68]
    float* Vs = sm + 2 * 64 * 68;   // [kv][68]

    int z = blockIdx.z;
    int bb = z / 7, t = z % 7;
    int grp, seg;
    if (t < 4)       { grp = 0; seg = t; }
    else if (t < 6)  { grp = 1; seg = t - 4; }
    else             { grp = 2; seg = 0; }
    int s = c_seg[grp], r = c_dil[grp];
    int off = grp % r;
    int head = grp * 4 + blockIdx.y;
    int q0 = blockIdx.x * 64;
    long segbase = (long)bb * NSEQ + (long)seg * s;

    int tid = threadIdx.x;
    int ty = tid >> 4, tx = tid & 15;

    // ---- load Q tile (scaled by 1/sqrt(64)) into Qs[d][q] ----
    {
        int qi = tid >> 2, lane = tid & 3;
        long n = segbase + off + (long)(q0 + qi) * r;
        const float* src = Q + (n * NH + head) * HD;
#pragma unroll
        for (int u = 0; u < 4; u++) {
            int d = u * 16 + lane * 4;
            float4 a = *(const float4*)(src + d);
            Qs[(d + 0) * 68 + qi] = a.x * 0.125f;
            Qs[(d + 1) * 68 + qi] = a.y * 0.125f;
            Qs[(d + 2) * 68 + qi] = a.z * 0.125f;
            Qs[(d + 3) * 68 + qi] = a.w * 0.125f;
        }
    }

    float Oa[4][4];
    float m[4], l[4];
#pragma unroll
    for (int i = 0; i < 4; i++) {
        m[i] = -1e30f; l[i] = 0.f;
#pragma unroll
        for (int j = 0; j < 4; j++) Oa[i][j] = 0.f;
    }

    for (int kt = 0; kt < 32; kt++) {
        __syncthreads();   // protect Qs fill (iter 0) / prior Ps,Vs reads
        // ---- load K tile into Ks[d][kv], V tile into Vs[kv][d] ----
        {
            int ki = tid >> 2, lane = tid & 3;
            long n = segbase + off + (long)(kt * 64 + ki) * r;
            const float* ksrc = K + (n * NH + head) * HD;
            const float* vsrc = V + (n * NH + head) * HD;
#pragma unroll
            for (int u = 0; u < 4; u++) {
                int d = u * 16 + lane * 4;
                float4 a = *(const float4*)(ksrc + d);
                Ks[(d + 0) * 68 + ki] = a.x;
                Ks[(d + 1) * 68 + ki] = a.y;
                Ks[(d + 2) * 68 + ki] = a.z;
                Ks[(d + 3) * 68 + ki] = a.w;
                *(float4*)&Vs[ki * 68 + d] = *(const float4*)(vsrc + d);
            }
        }
        __syncthreads();

        // ---- S = Q @ K^T (per-thread 4x4) ----
        float S[4][4];
#pragma unroll
        for (int i = 0; i < 4; i++)
#pragma unroll
            for (int j = 0; j < 4; j++) S[i][j] = 0.f;

        for (int kk = 0; kk < 64; kk++) {
            float qa[4], kb[4];
            *(float4*)qa = *(float4*)&Qs[kk * 68 + 4 * ty];
            *(float4*)kb = *(float4*)&Ks[kk * 68 + 4 * tx];
#pragma unroll
            for (int i = 0; i < 4; i++)
#pragma unroll
                for (int j = 0; j < 4; j++) S[i][j] += qa[i] * kb[j];
        }

        // ---- online softmax update (row groups of 16 threads share a row) ----
        float fac[4];
#pragma unroll
        for (int i = 0; i < 4; i++) {
            float rm = fmaxf(fmaxf(S[i][0], S[i][1]), fmaxf(S[i][2], S[i][3]));
            for (int o = 8; o; o >>= 1)
                rm = fmaxf(rm, __shfl_xor_sync(0xffffffffu, rm, o, 16));
            float nm = fmaxf(m[i], rm);
            fac[i] = __expf(m[i] - nm);
            m[i] = nm;
            float rs = 0.f;
#pragma unroll
            for (int j = 0; j < 4; j++) { S[i][j] = __expf(S[i][j] - nm); rs += S[i][j]; }
            for (int o = 8; o; o >>= 1)
                rs += __shfl_xor_sync(0xffffffffu, rs, o, 16);
            l[i] = l[i] * fac[i] + rs;
#pragma unroll
            for (int j = 0; j < 4; j++) Oa[i][j] *= fac[i];
        }

        __syncthreads();   // everyone done reading Ks
        // ---- write P into Ks as Ps[kv][q] ----
#pragma unroll
        for (int j = 0; j < 4; j++) {
            float4 p = make_float4(S[0][j], S[1][j], S[2][j], S[3][j]);
            *(float4*)&Ks[(4 * tx + j) * 68 + 4 * ty] = p;
        }
        __syncthreads();

        // ---- O += P @ V ----
        for (int kv = 0; kv < 64; kv++) {
            float pa[4], vb[4];
            *(float4*)pa = *(float4*)&Ks[kv * 68 + 4 * ty];
            *(float4*)vb = *(float4*)&Vs[kv * 68 + 4 * tx];
#pragma unroll
            for (int i = 0; i < 4; i++)
#pragma unroll
                for (int j = 0; j < 4; j++) Oa[i][j] += pa[i] * vb[j];
        }
    }

    // ---- epilogue: normalize and scatter back to dilated positions ----
#pragma unroll
    for (int i = 0; i < 4; i++) {
        float inv = 1.f / l[i];
        long n = segbase + off + (long)(q0 + 4 * ty + i) * r;
        float4 o4 = make_float4(Oa[i][0] * inv, Oa[i][1] * inv,
                                Oa[i][2] * inv, Oa[i][3] * inv);
        *(float4*)(O + (n * NH + head) * HD + 4 * tx) = o4;
    }
}

// ---------------- host orchestration ---------------------------------------
extern "C" void kernel_launch(void* const* d_in, const int* in_sizes, int n_in,
                              void* d_out, int out_size) {
    const float* src  = (const float*)d_in[0];
    const float* ln1w = (const float*)d_in[1];
    const float* ln1b = (const float*)d_in[2];
    const float* Wq   = (const float*)d_in[3];
    const float* bq   = (const float*)d_in[4];
    const float* Wk   = (const float*)d_in[5];
    const float* bk   = (const float*)d_in[6];
    const float* Wv   = (const float*)d_in[7];
    const float* bv   = (const float*)d_in[8];
    const float* lnAw = (const float*)d_in[9];
    const float* lnAb = (const float*)d_in[10];
    const float* Wo   = (const float*)d_in[11];
    const float* bo   = (const float*)d_in[12];
    const float* ln2w = (const float*)d_in[13];
    const float* ln2b = (const float*)d_in[14];
    const float* W1   = (const float*)d_in[15];
    const float* b1   = (const float*)d_in[16];
    const float* ln3w = (const float*)d_in[17];
    const float* ln3b = (const float*)d_in[18];
    const float* W2   = (const float*)d_in[19];
    const float* b2   = (const float*)d_in[20];
    float* out = (float*)d_out;

    float *px, *pq, *pk, *pv, *pf1, *pf2;
    cudaGetSymbolAddress((void**)&px,  g_x);
    cudaGetSymbolAddress((void**)&pq,  g_q);
    cudaGetSymbolAddress((void**)&pk,  g_k);
    cudaGetSymbolAddress((void**)&pv,  g_v);
    cudaGetSymbolAddress((void**)&pf1, g_f1);
    cudaGetSymbolAddress((void**)&pf2, g_f2);

    dim3 g768(DM / 128, NTOK / 128);    // (6, 128)
    dim3 gff(DFF / 128, NTOK / 128);    // (24, 128)

    // x = LN1(src)
    ln_kernel<<<NTOK, 256>>>(src, ln1w, ln1b, px, DM);
    // q, k, v projections
    sgemm_kernel<false><<<g768, 256>>>(px, Wq, bq, pq, NTOK, DM, DM);
    sgemm_kernel<false><<<g768, 256>>>(px, Wk, bk, pk, NTOK, DM, DM);
    sgemm_kernel<false><<<g768, 256>>>(px, Wv, bv, pv, NTOK, DM, DM);
    // attention output buffer (reuse px): zero, then dilated attention scatters
    zero_kernel<<<4096, 256>>>((float4*)px, (long)NTOK * DM / 4);
    const int asmem = 3 * 64 * 68 * 4;  // 52224 B
    cudaFuncSetAttribute(attn_kernel, cudaFuncAttributeMaxDynamicSharedMemorySize, asmem);
    attn_kernel<<<dim3(32, 4, 14), 256, asmem>>>(pq, pk, pv, px);
    // MAGNETO sub-LN + out projection
    ln_kernel<<<NTOK, 256>>>(px, lnAw, lnAb, pq, DM);
    sgemm_kernel<false><<<g768, 256>>>(pq, Wo, bo, pk, NTOK, DM, DM);
    // LN2 + FFN
    ln_kernel<<<NTOK, 256>>>(pk, ln2w, ln2b, pv, DM);
    sgemm_kernel<true><<<gff, 256>>>(pv, W1, b1, pf1, NTOK, DFF, DM);
    ln_kernel<<<NTOK, 256>>>(pf1, ln3w, ln3b, pf2, DFF);
    sgemm_kernel<false><<<g768, 256>>>(pf2, W2, b2, out, NTOK, DM, DFF);
}

// round 7
// speedup vs baseline: 1.8635x; 1.8635x over previous
#include <cuda_runtime.h>
#include <cuda_fp16.h>
#include <cstdint>

#define NTOK 16384          // B*N = 2*8192
#define NSEQ 8192
#define DM   768
#define DFF  3072
#define NH   12
#define HD   64

typedef __half f16;

// ---------------- scratch (device globals; no allocation allowed) ----------
__device__ float g_q  [NTOK * DM];
__device__ float g_k  [NTOK * DM];
__device__ float g_v  [NTOK * DM];
__device__ float g_att[NTOK * DM];
__device__ float g_f1 [NTOK * DFF];
__device__ f16   g_ahi[NTOK * DFF];
__device__ f16   g_alo[NTOK * DFF];
__device__ f16   g_wqh[DM * DM],  g_wql[DM * DM];
__device__ f16   g_wkh[DM * DM],  g_wkl[DM * DM];
__device__ f16   g_wvh[DM * DM],  g_wvl[DM * DM];
__device__ f16   g_woh[DM * DM],  g_wol[DM * DM];
__device__ f16   g_w1h[DM * DFF], g_w1l[DM * DFF];
__device__ f16   g_w2h[DFF * DM], g_w2l[DFF * DM];

// ======================= PTX helpers =======================================
__device__ __forceinline__ uint32_t s2u(const void* p) {
    uint32_t a;
    asm("{ .reg .u64 t; cvta.to.shared.u64 t, %1; cvt.u32.u64 %0, t; }"
        : "=r"(a) : "l"(p));
    return a;
}

#define CP16(dst, src) \
    asm volatile("cp.async.cg.shared.global [%0], [%1], 16;" :: "r"(dst), "l"(src) : "memory")
#define CP_COMMIT() asm volatile("cp.async.commit_group;" ::: "memory")
#define CP_WAIT1()  asm volatile("cp.async.wait_group 1;" ::: "memory")

#define LDSM4(r, a)                                                          \
    asm volatile("ldmatrix.sync.aligned.m8n8.x4.shared.b16 {%0,%1,%2,%3}, [%4];" \
        : "=r"((r)[0]), "=r"((r)[1]), "=r"((r)[2]), "=r"((r)[3]) : "r"(a))

#define MMA16816(c, a, b0, b1)                                               \
    asm volatile("mma.sync.aligned.m16n8k16.row.col.f32.f16.f16.f32 "        \
        "{%0,%1,%2,%3}, {%4,%5,%6,%7}, {%8,%9}, {%0,%1,%2,%3};"              \
        : "+f"((c)[0]), "+f"((c)[1]), "+f"((c)[2]), "+f"((c)[3])             \
        : "r"((a)[0]), "r"((a)[1]), "r"((a)[2]), "r"((a)[3]),                \
          "r"(b0), "r"(b1))

// ================= LayerNorm fused with fp16 hi/lo split ===================
__global__ void ln_split_kernel(const float* __restrict__ x, const float* __restrict__ w,
                                const float* __restrict__ b, f16* __restrict__ hi,
                                f16* __restrict__ lo, int C) {
    long row = blockIdx.x;
    const float* xr = x + row * (long)C;
    float s = 0.f, ss = 0.f;
    for (int c = threadIdx.x; c < C; c += 256) {
        float v = xr[c];
        s += v; ss += v * v;
    }
    for (int o = 16; o; o >>= 1) {
        s  += __shfl_xor_sync(0xffffffffu, s,  o);
        ss += __shfl_xor_sync(0xffffffffu, ss, o);
    }
    __shared__ float sh[2][8];
    int wi = threadIdx.x >> 5, li = threadIdx.x & 31;
    if (li == 0) { sh[0][wi] = s; sh[1][wi] = ss; }
    __syncthreads();
    if (threadIdx.x < 32) {
        s  = (li < 8) ? sh[0][li] : 0.f;
        ss = (li < 8) ? sh[1][li] : 0.f;
        for (int o = 4; o; o >>= 1) {
            s  += __shfl_xor_sync(0xffffffffu, s,  o);
            ss += __shfl_xor_sync(0xffffffffu, ss, o);
        }
        if (li == 0) { sh[0][0] = s; sh[1][0] = ss; }
    }
    __syncthreads();
    float mean = sh[0][0] / (float)C;
    float var  = sh[1][0] / (float)C - mean * mean;
    float rstd = rsqrtf(var + 1e-5f);
    f16* hr = hi + row * (long)C;
    f16* lr = lo + row * (long)C;
    for (int c = threadIdx.x; c < C; c += 256) {
        float y = (xr[c] - mean) * rstd * w[c] + b[c];
        f16 h = __float2half_rn(y);
        hr[c] = h;
        lr[c] = __float2half_rn(y - __half2float(h));
    }
}

// ============ weight transpose + split: W[K,N] -> hi/lo [N,K] ==============
__global__ void splitT_kernel(const float* __restrict__ W, f16* __restrict__ hi,
                              f16* __restrict__ lo, int K, int N) {
    __shared__ float t[32][33];
    int k0 = blockIdx.x * 32, n0 = blockIdx.y * 32;
    int tx = threadIdx.x, ty = threadIdx.y;   // 32 x 8
#pragma unroll
    for (int i = 0; i < 4; i++)
        t[ty + 8 * i][tx] = W[(long)(k0 + ty + 8 * i) * N + n0 + tx];
    __syncthreads();
#pragma unroll
    for (int i = 0; i < 4; i++) {
        float v = t[tx][ty + 8 * i];
        f16 h = __float2half_rn(v);
        long o = (long)(n0 + ty + 8 * i) * K + k0 + tx;
        hi[o] = h;
        lo[o] = __float2half_rn(v - __half2float(h));
    }
}

// ---------------- zero fill ------------------------------------------------
__global__ void zero_kernel(float4* __restrict__ p, long n4) {
    long i = (long)blockIdx.x * blockDim.x + threadIdx.x;
    long stride = (long)gridDim.x * blockDim.x;
    float4 z = make_float4(0.f, 0.f, 0.f, 0.f);
    for (; i < n4; i += stride) p[i] = z;
}

// ================= mma.sync 3x-fp16 GEMM ===================================
// C[M,Ncols] = (Ahi+Alo)[M,K] x ((Bhi+Blo)[Ncols,K])^T + bias, opt relu.
// 128x128 tile, K-chunks of 64 fp16 (128B rows, SW128), 3-stage cp.async.
#define GSTAGES 3
#define TILE_B   16384                   // one operand tile: 128 rows x 128 B
#define GSTAGE_B (4 * TILE_B)            // Ah, Al, Bh, Bl
#define GSMEM    (GSTAGES * GSTAGE_B)    // 196608

__global__ void __launch_bounds__(256, 1)
gemm3x_kernel(const f16* __restrict__ Ahi, const f16* __restrict__ Alo,
              const f16* __restrict__ Bhi, const f16* __restrict__ Blo,
              const float* __restrict__ bias, float* __restrict__ C,
              int Kdim, int Ncols, int relu) {
    extern __shared__ char smraw[];
    const uint32_t sb = s2u(smraw);
    const int tid = threadIdx.x;
    const int m0 = blockIdx.y * 128, n0 = blockIdx.x * 128;
    const int nk = Kdim >> 6;                 // chunks of 64 fp16
    const long rowb = (long)Kdim * 2;         // bytes per gmem row

    const char* pAh = (const char*)Ahi + (long)m0 * rowb;
    const char* pAl = (const char*)Alo + (long)m0 * rowb;
    const char* pBh = (const char*)Bhi + (long)n0 * rowb;
    const char* pBl = (const char*)Blo + (long)n0 * rowb;

    // loader precompute: 4 units of 16B per tile per thread
    int lrow[4], lkb[4];
    uint32_t ldst[4];
#pragma unroll
    for (int j = 0; j < 4; j++) {
        int u = tid + 256 * j;
        lrow[j] = u >> 3;
        lkb[j]  = (u & 7) * 16;
        ldst[j] = (uint32_t)(lrow[j] * 128 + (lkb[j] ^ ((lrow[j] & 7) * 16)));
    }

#define LOAD_CHUNK(slot, ci) do {                                            \
    uint32_t stg_ = sb + (slot) * GSTAGE_B;                                  \
    long koff_ = (long)(ci) * 128;                                           \
    _Pragma("unroll")                                                        \
    for (int j = 0; j < 4; j++) {                                            \
        long go = (long)lrow[j] * rowb + koff_ + lkb[j];                     \
        CP16(stg_ + ldst[j],              pAh + go);                         \
        CP16(stg_ + TILE_B + ldst[j],     pAl + go);                         \
        CP16(stg_ + 2 * TILE_B + ldst[j], pBh + go);                         \
        CP16(stg_ + 3 * TILE_B + ldst[j], pBl + go);                         \
    }                                                                        \
} while (0)

    // warp layout: wm in 0..3 (32 rows each), wn in 0..1 (64 cols each)
    const int wid = tid >> 5, l = tid & 31;
    const int wm = wid & 3, wn = wid >> 2;
    const int quad = l >> 3, rim = l & 7;
    const int rimx = rim * 16;
    const int kbq = (quad >> 1) * 16;

    uint32_t aoff[2], boff[4];
#pragma unroll
    for (int mf = 0; mf < 2; mf++)
        aoff[mf] = (uint32_t)((wm * 32 + mf * 16 + (quad & 1) * 8 + rim) * 128);
#pragma unroll
    for (int np = 0; np < 4; np++)
        boff[np] = (uint32_t)((wn * 64 + np * 16 + (quad & 1) * 8 + rim) * 128);

    float acc[2][8][4];
#pragma unroll
    for (int mf = 0; mf < 2; mf++)
#pragma unroll
        for (int nf = 0; nf < 8; nf++)
#pragma unroll
            for (int c = 0; c < 4; c++) acc[mf][nf][c] = 0.f;

    // prefetch
#pragma unroll
    for (int s = 0; s < GSTAGES - 1; s++) {
        LOAD_CHUNK(s, s);
        CP_COMMIT();
    }

    int slot = 0;
    for (int i = 0; i < nk; i++) {
        CP_WAIT1();
        __syncthreads();
        // issue next load (into the slot freed by chunk i-1)
        int nc = i + GSTAGES - 1;
        if (nc < nk) LOAD_CHUNK((nc % GSTAGES), nc);
        CP_COMMIT();

        const uint32_t stg = sb + slot * GSTAGE_B;
        const uint32_t aH = stg, aL = stg + TILE_B;
        const uint32_t bH = stg + 2 * TILE_B, bL = stg + 3 * TILE_B;

#pragma unroll
        for (int ks = 0; ks < 4; ks++) {
            const uint32_t kx = (uint32_t)((ks * 32 + kbq) ^ rimx);
            uint32_t ah[2][4], al[2][4], bh[4][4], bl[4][4];
#pragma unroll
            for (int mf = 0; mf < 2; mf++) {
                LDSM4(ah[mf], aH + aoff[mf] + kx);
                LDSM4(al[mf], aL + aoff[mf] + kx);
            }
#pragma unroll
            for (int np = 0; np < 4; np++) {
                LDSM4(bh[np], bH + boff[np] + kx);
                LDSM4(bl[np], bL + boff[np] + kx);
            }
#pragma unroll
            for (int mf = 0; mf < 2; mf++)
#pragma unroll
                for (int nf = 0; nf < 8; nf++) {
                    int np = nf >> 1, hh = nf & 1;
                    uint32_t bh0 = bh[np][hh], bh1 = bh[np][hh + 2];
                    uint32_t bl0 = bl[np][hh], bl1 = bl[np][hh + 2];
                    MMA16816(acc[mf][nf], ah[mf], bh0, bh1);
                    MMA16816(acc[mf][nf], al[mf], bh0, bh1);
                    MMA16816(acc[mf][nf], ah[mf], bl0, bl1);
                }
        }
        __syncthreads();
        slot = (slot + 1 == GSTAGES) ? 0 : slot + 1;
    }

    // ---------------- epilogue: bias (+relu) + store -----------------------
    const int g = l >> 2, t4 = l & 3;
#pragma unroll
    for (int mf = 0; mf < 2; mf++) {
        int row = m0 + wm * 32 + mf * 16 + g;
#pragma unroll
        for (int nf = 0; nf < 8; nf++) {
            int col = n0 + wn * 64 + nf * 8 + 2 * t4;
            float b0v = bias[col], b1v = bias[col + 1];
            float2 v0, v1;
            v0.x = acc[mf][nf][0] + b0v;
            v0.y = acc[mf][nf][1] + b1v;
            v1.x = acc[mf][nf][2] + b0v;
            v1.y = acc[mf][nf][3] + b1v;
            if (relu) {
                v0.x = fmaxf(v0.x, 0.f); v0.y = fmaxf(v0.y, 0.f);
                v1.x = fmaxf(v1.x, 0.f); v1.y = fmaxf(v1.y, 0.f);
            }
            *(float2*)(C + (long)row * Ncols + col)       = v0;
            *(float2*)(C + (long)(row + 8) * Ncols + col) = v1;
        }
    }
#undef LOAD_CHUNK
}

// ---------------- dilated flash attention (fp32 SIMT, proven) --------------
__constant__ int c_seg[3] = {2048, 4096, 8192};
__constant__ int c_dil[3] = {1, 2, 4};

__global__ void attn_kernel(const float* __restrict__ Q, const float* __restrict__ K,
                            const float* __restrict__ V, float* __restrict__ O) {
    extern __shared__ float sm[];
    float* Qs = sm;
    float* Ks = sm + 64 * 68;
    float* Vs = sm + 2 * 64 * 68;

    int z = blockIdx.z;
    int bb = z / 7, t = z % 7;
    int grp, seg;
    if (t < 4)       { grp = 0; seg = t; }
    else if (t < 6)  { grp = 1; seg = t - 4; }
    else             { grp = 2; seg = 0; }
    int s = c_seg[grp], r = c_dil[grp];
    int off = grp % r;
    int head = grp * 4 + blockIdx.y;
    int q0 = blockIdx.x * 64;
    long segbase = (long)bb * NSEQ + (long)seg * s;

    int tid = threadIdx.x;
    int ty = tid >> 4, tx = tid & 15;

    {
        int qi = tid >> 2, lane = tid & 3;
        long n = segbase + off + (long)(q0 + qi) * r;
        const float* src = Q + (n * NH + head) * HD;
#pragma unroll
        for (int u = 0; u < 4; u++) {
            int d = u * 16 + lane * 4;
            float4 a = *(const float4*)(src + d);
            Qs[(d + 0) * 68 + qi] = a.x * 0.125f;
            Qs[(d + 1) * 68 + qi] = a.y * 0.125f;
            Qs[(d + 2) * 68 + qi] = a.z * 0.125f;
            Qs[(d + 3) * 68 + qi] = a.w * 0.125f;
        }
    }

    float Oa[4][4];
    float m[4], l[4];
#pragma unroll
    for (int i = 0; i < 4; i++) {
        m[i] = -1e30f; l[i] = 0.f;
#pragma unroll
        for (int j = 0; j < 4; j++) Oa[i][j] = 0.f;
    }

    for (int kt = 0; kt < 32; kt++) {
        __syncthreads();
        {
            int ki = tid >> 2, lane = tid & 3;
            long n = segbase + off + (long)(kt * 64 + ki) * r;
            const float* ksrc = K + (n * NH + head) * HD;
            const float* vsrc = V + (n * NH + head) * HD;
#pragma unroll
            for (int u = 0; u < 4; u++) {
                int d = u * 16 + lane * 4;
                float4 a = *(const float4*)(ksrc + d);
                Ks[(d + 0) * 68 + ki] = a.x;
                Ks[(d + 1) * 68 + ki] = a.y;
                Ks[(d + 2) * 68 + ki] = a.z;
                Ks[(d + 3) * 68 + ki] = a.w;
                *(float4*)&Vs[ki * 68 + d] = *(const float4*)(vsrc + d);
            }
        }
        __syncthreads();

        float S[4][4];
#pragma unroll
        for (int i = 0; i < 4; i++)
#pragma unroll
            for (int j = 0; j < 4; j++) S[i][j] = 0.f;

        for (int kk = 0; kk < 64; kk++) {
            float qa[4], kb[4];
            *(float4*)qa = *(float4*)&Qs[kk * 68 + 4 * ty];
            *(float4*)kb = *(float4*)&Ks[kk * 68 + 4 * tx];
#pragma unroll
            for (int i = 0; i < 4; i++)
#pragma unroll
                for (int j = 0; j < 4; j++) S[i][j] += qa[i] * kb[j];
        }

        float fac[4];
#pragma unroll
        for (int i = 0; i < 4; i++) {
            float rm = fmaxf(fmaxf(S[i][0], S[i][1]), fmaxf(S[i][2], S[i][3]));
            for (int o = 8; o; o >>= 1)
                rm = fmaxf(rm, __shfl_xor_sync(0xffffffffu, rm, o, 16));
            float nm = fmaxf(m[i], rm);
            fac[i] = __expf(m[i] - nm);
            m[i] = nm;
            float rs = 0.f;
#pragma unroll
            for (int j = 0; j < 4; j++) { S[i][j] = __expf(S[i][j] - nm); rs += S[i][j]; }
            for (int o = 8; o; o >>= 1)
                rs += __shfl_xor_sync(0xffffffffu, rs, o, 16);
            l[i] = l[i] * fac[i] + rs;
#pragma unroll
            for (int j = 0; j < 4; j++) Oa[i][j] *= fac[i];
        }

        __syncthreads();
#pragma unroll
        for (int j = 0; j < 4; j++) {
            float4 p = make_float4(S[0][j], S[1][j], S[2][j], S[3][j]);
            *(float4*)&Ks[(4 * tx + j) * 68 + 4 * ty] = p;
        }
        __syncthreads();

        for (int kv = 0; kv < 64; kv++) {
            float pa[4], vb[4];
            *(float4*)pa = *(float4*)&Ks[kv * 68 + 4 * ty];
            *(float4*)vb = *(float4*)&Vs[kv * 68 + 4 * tx];
#pragma unroll
            for (int i = 0; i < 4; i++)
#pragma unroll
                for (int j = 0; j < 4; j++) Oa[i][j] += pa[i] * vb[j];
        }
    }

#pragma unroll
    for (int i = 0; i < 4; i++) {
        float inv = 1.f / l[i];
        long n = segbase + off + (long)(q0 + 4 * ty + i) * r;
        float4 o4 = make_float4(Oa[i][0] * inv, Oa[i][1] * inv,
                                Oa[i][2] * inv, Oa[i][3] * inv);
        *(float4*)(O + (n * NH + head) * HD + 4 * tx) = o4;
    }
}

// ---------------- host orchestration ---------------------------------------
extern "C" void kernel_launch(void* const* d_in, const int* in_sizes, int n_in,
                              void* d_out, int out_size) {
    const float* src  = (const float*)d_in[0];
    const float* ln1w = (const float*)d_in[1];
    const float* ln1b = (const float*)d_in[2];
    const float* Wq   = (const float*)d_in[3];
    const float* bq   = (const float*)d_in[4];
    const float* Wk   = (const float*)d_in[5];
    const float* bk   = (const float*)d_in[6];
    const float* Wv   = (const float*)d_in[7];
    const float* bv   = (const float*)d_in[8];
    const float* lnAw = (const float*)d_in[9];
    const float* lnAb = (const float*)d_in[10];
    const float* Wo   = (const float*)d_in[11];
    const float* bo   = (const float*)d_in[12];
    const float* ln2w = (const float*)d_in[13];
    const float* ln2b = (const float*)d_in[14];
    const float* W1   = (const float*)d_in[15];
    const float* b1   = (const float*)d_in[16];
    const float* ln3w = (const float*)d_in[17];
    const float* ln3b = (const float*)d_in[18];
    const float* W2   = (const float*)d_in[19];
    const float* b2   = (const float*)d_in[20];
    float* out = (float*)d_out;

    float *pq, *pk, *pv, *patt, *pf1;
    f16 *ahi, *alo;
    f16 *wqh, *wql, *wkh, *wkl, *wvh, *wvl, *woh, *wol, *w1h, *w1l, *w2h, *w2l;
    cudaGetSymbolAddress((void**)&pq,   g_q);
    cudaGetSymbolAddress((void**)&pk,   g_k);
    cudaGetSymbolAddress((void**)&pv,   g_v);
    cudaGetSymbolAddress((void**)&patt, g_att);
    cudaGetSymbolAddress((void**)&pf1,  g_f1);
    cudaGetSymbolAddress((void**)&ahi,  g_ahi);
    cudaGetSymbolAddress((void**)&alo,  g_alo);
    cudaGetSymbolAddress((void**)&wqh,  g_wqh);
    cudaGetSymbolAddress((void**)&wql,  g_wql);
    cudaGetSymbolAddress((void**)&wkh,  g_wkh);
    cudaGetSymbolAddress((void**)&wkl,  g_wkl);
    cudaGetSymbolAddress((void**)&wvh,  g_wvh);
    cudaGetSymbolAddress((void**)&wvl,  g_wvl);
    cudaGetSymbolAddress((void**)&woh,  g_woh);
    cudaGetSymbolAddress((void**)&wol,  g_wol);
    cudaGetSymbolAddress((void**)&w1h,  g_w1h);
    cudaGetSymbolAddress((void**)&w1l,  g_w1l);
    cudaGetSymbolAddress((void**)&w2h,  g_w2h);
    cudaGetSymbolAddress((void**)&w2l,  g_w2l);

    static bool attr_done = false;
    if (!attr_done) {
        cudaFuncSetAttribute(gemm3x_kernel, cudaFuncAttributeMaxDynamicSharedMemorySize, GSMEM);
        cudaFuncSetAttribute(attn_kernel, cudaFuncAttributeMaxDynamicSharedMemorySize, 3 * 64 * 68 * 4);
        attr_done = true;
    }

    dim3 tT(32, 8);
    dim3 gW(DM / 32, DM / 32);
    dim3 gW1(DM / 32, DFF / 32);
    dim3 gW2(DFF / 32, DM / 32);
    dim3 gq(DM / 128, NTOK / 128);      // (6,128)
    dim3 g1(DFF / 128, NTOK / 128);     // (24,128)

    // weight transpose+split
    splitT_kernel<<<gW,  tT>>>(Wq, wqh, wql, DM, DM);
    splitT_kernel<<<gW,  tT>>>(Wk, wkh, wkl, DM, DM);
    splitT_kernel<<<gW,  tT>>>(Wv, wvh, wvl, DM, DM);
    splitT_kernel<<<gW,  tT>>>(Wo, woh, wol, DM, DM);
    splitT_kernel<<<gW1, tT>>>(W1, w1h, w1l, DM, DFF);
    splitT_kernel<<<gW2, tT>>>(W2, w2h, w2l, DFF, DM);

    // LN1 -> split, QKV projections
    ln_split_kernel<<<NTOK, 256>>>(src, ln1w, ln1b, ahi, alo, DM);
    gemm3x_kernel<<<gq, 256, GSMEM>>>(ahi, alo, wqh, wql, bq, pq, DM, DM, 0);
    gemm3x_kernel<<<gq, 256, GSMEM>>>(ahi, alo, wkh, wkl, bk, pk, DM, DM, 0);
    gemm3x_kernel<<<gq, 256, GSMEM>>>(ahi, alo, wvh, wvl, bv, pv, DM, DM, 0);

    // attention (scatter into zeroed buffer)
    zero_kernel<<<4096, 256>>>((float4*)patt, (long)NTOK * DM / 4);
    attn_kernel<<<dim3(32, 4, 14), 256, 3 * 64 * 68 * 4>>>(pq, pk, pv, patt);

    // MAGNETO sub-LN -> split, out projection
    ln_split_kernel<<<NTOK, 256>>>(patt, lnAw, lnAb, ahi, alo, DM);
    gemm3x_kernel<<<gq, 256, GSMEM>>>(ahi, alo, woh, wol, bo, pq, DM, DM, 0);

    // LN2 -> split, FF1 (relu)
    ln_split_kernel<<<NTOK, 256>>>(pq, ln2w, ln2b, ahi, alo, DM);
    gemm3x_kernel<<<g1, 256, GSMEM>>>(ahi, alo, w1h, w1l, b1, pf1, DM, DFF, 1);

    // LN3 -> split, FF2
    ln_split_kernel<<<NTOK, 256>>>(pf1, ln3w, ln3b, ahi, alo, DFF);
    gemm3x_kernel<<<gq, 256, GSMEM>>>(ahi, alo, w2h, w2l, b2, out, DFF, DM, 0);
}

// round 8
// speedup vs baseline: 2.5364x; 1.3611x over previous
#include <cuda_runtime.h>
#include <cuda_fp16.h>
#include <cstdint>

#define NTOK 16384          // B*N = 2*8192
#define NSEQ 8192
#define DM   768
#define DFF  3072
#define NH   12
#define HD   64

typedef __half f16;

// ---------------- scratch (device globals; no allocation allowed) ----------
__device__ float g_x  [NTOK * DM];     // Wo output
__device__ float g_att[NTOK * DM];     // attention output (fp32)
__device__ float g_f1 [NTOK * DFF];
__device__ f16   g_ahi[NTOK * DFF];
__device__ f16   g_alo[NTOK * DFF];
__device__ f16   g_qh [NTOK * DM], g_ql[NTOK * DM];
__device__ f16   g_kh [NTOK * DM], g_kl[NTOK * DM];
__device__ f16   g_vh [NTOK * DM], g_vl[NTOK * DM];
__device__ f16   g_wqh[DM * DM],  g_wql[DM * DM];
__device__ f16   g_wkh[DM * DM],  g_wkl[DM * DM];
__device__ f16   g_wvh[DM * DM],  g_wvl[DM * DM];
__device__ f16   g_woh[DM * DM],  g_wol[DM * DM];
__device__ f16   g_w1h[DM * DFF], g_w1l[DM * DFF];
__device__ f16   g_w2h[DFF * DM], g_w2l[DFF * DM];

// ======================= PTX helpers =======================================
__device__ __forceinline__ uint32_t s2u(const void* p) {
    uint32_t a;
    asm("{ .reg .u64 t; cvta.to.shared.u64 t, %1; cvt.u32.u64 %0, t; }"
        : "=r"(a) : "l"(p));
    return a;
}

#define CP16(dst, src) \
    asm volatile("cp.async.cg.shared.global [%0], [%1], 16;" :: "r"(dst), "l"(src) : "memory")
#define CP_COMMIT() asm volatile("cp.async.commit_group;" ::: "memory")
#define CP_WAIT1()  asm volatile("cp.async.wait_group 1;" ::: "memory")

#define LDSM4(r, a)                                                          \
    asm volatile("ldmatrix.sync.aligned.m8n8.x4.shared.b16 {%0,%1,%2,%3}, [%4];" \
        : "=r"((r)[0]), "=r"((r)[1]), "=r"((r)[2]), "=r"((r)[3]) : "r"(a))

#define LDSM4T(r, a)                                                         \
    asm volatile("ldmatrix.sync.aligned.m8n8.x4.trans.shared.b16 {%0,%1,%2,%3}, [%4];" \
        : "=r"((r)[0]), "=r"((r)[1]), "=r"((r)[2]), "=r"((r)[3]) : "r"(a))

#define MMA16816(c, a, b0, b1)                                               \
    asm volatile("mma.sync.aligned.m16n8k16.row.col.f32.f16.f16.f32 "        \
        "{%0,%1,%2,%3}, {%4,%5,%6,%7}, {%8,%9}, {%0,%1,%2,%3};"              \
        : "+f"((c)[0]), "+f"((c)[1]), "+f"((c)[2]), "+f"((c)[3])             \
        : "r"((a)[0]), "r"((a)[1]), "r"((a)[2]), "r"((a)[3]),                \
          "r"(b0), "r"(b1))

__device__ __forceinline__ uint32_t pack_h2(f16 a, f16 b) {
    __half2 h = __halves2half2(a, b);
    return *reinterpret_cast<uint32_t*>(&h);
}

// ================= LayerNorm fused with fp16 hi/lo split ===================
__global__ void ln_split_kernel(const float* __restrict__ x, const float* __restrict__ w,
                                const float* __restrict__ b, f16* __restrict__ hi,
                                f16* __restrict__ lo, int C) {
    long row = blockIdx.x;
    const float* xr = x + row * (long)C;
    float s = 0.f, ss = 0.f;
    for (int c = threadIdx.x; c < C; c += 256) {
        float v = xr[c];
        s += v; ss += v * v;
    }
    for (int o = 16; o; o >>= 1) {
        s  += __shfl_xor_sync(0xffffffffu, s,  o);
        ss += __shfl_xor_sync(0xffffffffu, ss, o);
    }
    __shared__ float sh[2][8];
    int wi = threadIdx.x >> 5, li = threadIdx.x & 31;
    if (li == 0) { sh[0][wi] = s; sh[1][wi] = ss; }
    __syncthreads();
    if (threadIdx.x < 32) {
        s  = (li < 8) ? sh[0][li] : 0.f;
        ss = (li < 8) ? sh[1][li] : 0.f;
        for (int o = 4; o; o >>= 1) {
            s  += __shfl_xor_sync(0xffffffffu, s,  o);
            ss += __shfl_xor_sync(0xffffffffu, ss, o);
        }
        if (li == 0) { sh[0][0] = s; sh[1][0] = ss; }
    }
    __syncthreads();
    float mean = sh[0][0] / (float)C;
    float var  = sh[1][0] / (float)C - mean * mean;
    float rstd = rsqrtf(var + 1e-5f);
    f16* hr = hi + row * (long)C;
    f16* lr = lo + row * (long)C;
    for (int c = threadIdx.x; c < C; c += 256) {
        float y = (xr[c] - mean) * rstd * w[c] + b[c];
        f16 h = __float2half_rn(y);
        hr[c] = h;
        lr[c] = __float2half_rn(y - __half2float(h));
    }
}

// ============ weight transpose + split: W[K,N] -> hi/lo [N,K] ==============
__global__ void splitT_kernel(const float* __restrict__ W, f16* __restrict__ hi,
                              f16* __restrict__ lo, int K, int N) {
    __shared__ float t[32][33];
    int k0 = blockIdx.x * 32, n0 = blockIdx.y * 32;
    int tx = threadIdx.x, ty = threadIdx.y;   // 32 x 8
#pragma unroll
    for (int i = 0; i < 4; i++)
        t[ty + 8 * i][tx] = W[(long)(k0 + ty + 8 * i) * N + n0 + tx];
    __syncthreads();
#pragma unroll
    for (int i = 0; i < 4; i++) {
        float v = t[tx][ty + 8 * i];
        f16 h = __float2half_rn(v);
        long o = (long)(n0 + ty + 8 * i) * K + k0 + tx;
        hi[o] = h;
        lo[o] = __float2half_rn(v - __half2float(h));
    }
}

// ---------------- zero fill ------------------------------------------------
__global__ void zero_kernel(float4* __restrict__ p, long n4) {
    long i = (long)blockIdx.x * blockDim.x + threadIdx.x;
    long stride = (long)gridDim.x * blockDim.x;
    float4 z = make_float4(0.f, 0.f, 0.f, 0.f);
    for (; i < n4; i += stride) p[i] = z;
}

// ================= mma.sync 3x-fp16 GEMM ===================================
// C = (Ahi+Alo)[M,K] x ((Bhi+Blo)[Ncols,K])^T + bias; output either fp32 (C)
// or fp16 hi/lo pair (Chi/Clo) scaled by alpha.
#define GSTAGES 3
#define TILE_B   16384                   // one operand tile: 128 rows x 128 B
#define GSTAGE_B (4 * TILE_B)            // Ah, Al, Bh, Bl
#define GSMEM    (GSTAGES * GSTAGE_B)    // 196608

__global__ void __launch_bounds__(256, 1)
gemm3x_kernel(const f16* __restrict__ Ahi, const f16* __restrict__ Alo,
              const f16* __restrict__ Bhi, const f16* __restrict__ Blo,
              const float* __restrict__ bias, float* __restrict__ C,
              f16* __restrict__ Chi, f16* __restrict__ Clo,
              float alpha, int Kdim, int Ncols, int relu) {
    extern __shared__ char smraw[];
    const uint32_t sb = s2u(smraw);
    const int tid = threadIdx.x;
    const int m0 = blockIdx.y * 128, n0 = blockIdx.x * 128;
    const int nk = Kdim >> 6;                 // chunks of 64 fp16
    const long rowb = (long)Kdim * 2;         // bytes per gmem row

    const char* pAh = (const char*)Ahi + (long)m0 * rowb;
    const char* pAl = (const char*)Alo + (long)m0 * rowb;
    const char* pBh = (const char*)Bhi + (long)n0 * rowb;
    const char* pBl = (const char*)Blo + (long)n0 * rowb;

    int lrow[4], lkb[4];
    uint32_t ldst[4];
#pragma unroll
    for (int j = 0; j < 4; j++) {
        int u = tid + 256 * j;
        lrow[j] = u >> 3;
        lkb[j]  = (u & 7) * 16;
        ldst[j] = (uint32_t)(lrow[j] * 128 + (lkb[j] ^ ((lrow[j] & 7) * 16)));
    }

#define LOAD_CHUNK(slot, ci) do {                                            \
    uint32_t stg_ = sb + (slot) * GSTAGE_B;                                  \
    long koff_ = (long)(ci) * 128;                                           \
    _Pragma("unroll")                                                        \
    for (int j = 0; j < 4; j++) {                                            \
        long go = (long)lrow[j] * rowb + koff_ + lkb[j];                     \
        CP16(stg_ + ldst[j],              pAh + go);                         \
        CP16(stg_ + TILE_B + ldst[j],     pAl + go);                         \
        CP16(stg_ + 2 * TILE_B + ldst[j], pBh + go);                         \
        CP16(stg_ + 3 * TILE_B + ldst[j], pBl + go);                         \
    }                                                                        \
} while (0)

    const int wid = tid >> 5, l = tid & 31;
    const int wm = wid & 3, wn = wid >> 2;
    const int quad = l >> 3, rim = l & 7;
    const int rimx = rim * 16;
    const int kbq = (quad >> 1) * 16;

    uint32_t aoff[2], boff[4];
#pragma unroll
    for (int mf = 0; mf < 2; mf++)
        aoff[mf] = (uint32_t)((wm * 32 + mf * 16 + (quad & 1) * 8 + rim) * 128);
#pragma unroll
    for (int np = 0; np < 4; np++)
        boff[np] = (uint32_t)((wn * 64 + np * 16 + (quad & 1) * 8 + rim) * 128);

    float acc[2][8][4];
#pragma unroll
    for (int mf = 0; mf < 2; mf++)
#pragma unroll
        for (int nf = 0; nf < 8; nf++)
#pragma unroll
            for (int c = 0; c < 4; c++) acc[mf][nf][c] = 0.f;

#pragma unroll
    for (int s = 0; s < GSTAGES - 1; s++) {
        LOAD_CHUNK(s, s);
        CP_COMMIT();
    }

    int slot = 0;
    for (int i = 0; i < nk; i++) {
        CP_WAIT1();
        __syncthreads();
        int nc = i + GSTAGES - 1;
        if (nc < nk) LOAD_CHUNK((nc % GSTAGES), nc);
        CP_COMMIT();

        const uint32_t stg = sb + slot * GSTAGE_B;
        const uint32_t aH = stg, aL = stg + TILE_B;
        const uint32_t bH = stg + 2 * TILE_B, bL = stg + 3 * TILE_B;

#pragma unroll
        for (int ks = 0; ks < 4; ks++) {
            const uint32_t kx = (uint32_t)((ks * 32 + kbq) ^ rimx);
            uint32_t ah[2][4], al[2][4], bh[4][4], bl[4][4];
#pragma unroll
            for (int mf = 0; mf < 2; mf++) {
                LDSM4(ah[mf], aH + aoff[mf] + kx);
                LDSM4(al[mf], aL + aoff[mf] + kx);
            }
#pragma unroll
            for (int np = 0; np < 4; np++) {
                LDSM4(bh[np], bH + boff[np] + kx);
                LDSM4(bl[np], bL + boff[np] + kx);
            }
#pragma unroll
            for (int mf = 0; mf < 2; mf++)
#pragma unroll
                for (int nf = 0; nf < 8; nf++) {
                    int np = nf >> 1, hh = nf & 1;
                    uint32_t bh0 = bh[np][hh], bh1 = bh[np][hh + 2];
                    uint32_t bl0 = bl[np][hh], bl1 = bl[np][hh + 2];
                    MMA16816(acc[mf][nf], ah[mf], bh0, bh1);
                    MMA16816(acc[mf][nf], al[mf], bh0, bh1);
                    MMA16816(acc[mf][nf], ah[mf], bl0, bl1);
                }
        }
        __syncthreads();
        slot = (slot + 1 == GSTAGES) ? 0 : slot + 1;
    }

    // ---------------- epilogue -----------------------------------------
    const int g = l >> 2, t4 = l & 3;
#pragma unroll
    for (int mf = 0; mf < 2; mf++) {
        int row = m0 + wm * 32 + mf * 16 + g;
#pragma unroll
        for (int nf = 0; nf < 8; nf++) {
            int col = n0 + wn * 64 + nf * 8 + 2 * t4;
            float b0v = bias[col], b1v = bias[col + 1];
            float v0 = acc[mf][nf][0] + b0v;
            float v1 = acc[mf][nf][1] + b1v;
            float v2 = acc[mf][nf][2] + b0v;
            float v3 = acc[mf][nf][3] + b1v;
            if (relu) {
                v0 = fmaxf(v0, 0.f); v1 = fmaxf(v1, 0.f);
                v2 = fmaxf(v2, 0.f); v3 = fmaxf(v3, 0.f);
            }
            if (Chi) {
                v0 *= alpha; v1 *= alpha; v2 *= alpha; v3 *= alpha;
                f16 h0 = __float2half_rn(v0), h1 = __float2half_rn(v1);
                f16 h2 = __float2half_rn(v2), h3 = __float2half_rn(v3);
                f16 r0 = __float2half_rn(v0 - __half2float(h0));
                f16 r1 = __float2half_rn(v1 - __half2float(h1));
                f16 r2 = __float2half_rn(v2 - __half2float(h2));
                f16 r3 = __float2half_rn(v3 - __half2float(h3));
                *(uint32_t*)(Chi + (long)row * Ncols + col)       = pack_h2(h0, h1);
                *(uint32_t*)(Chi + (long)(row + 8) * Ncols + col) = pack_h2(h2, h3);
                *(uint32_t*)(Clo + (long)row * Ncols + col)       = pack_h2(r0, r1);
                *(uint32_t*)(Clo + (long)(row + 8) * Ncols + col) = pack_h2(r2, r3);
            } else {
                float2 w0 = make_float2(v0, v1), w1 = make_float2(v2, v3);
                *(float2*)(C + (long)row * Ncols + col)       = w0;
                *(float2*)(C + (long)(row + 8) * Ncols + col) = w1;
            }
        }
    }
#undef LOAD_CHUNK
}

// ============== tensor-core dilated flash attention ========================
// CTA = 128 threads / 64 queries of one (batch, group-instance, head).
// Q fp16 hi/lo resident in registers (Q pre-scaled by 0.125 at projection);
// K/V hi/lo streamed in 64-row tiles, double-buffered cp.async, SW128 smem.
// S = QhKh + QlKh + QhKl (fp32 acc); fp32 online softmax in C-frag layout;
// P hi/lo in-register; O += PhVh + PlVh + PhVl (V via ldmatrix.trans).
__constant__ int c_seg[3] = {2048, 4096, 8192};
__constant__ int c_dil[3] = {1, 2, 4};

#define ASM_QH  0
#define ASM_QL  8192
#define ASM_KV  16384
#define ASM_BUF 32768       // per KV buffer: Kh 0, Kl 8K, Vh 16K, Vl 24K
#define ASMEM   (ASM_KV + 2 * ASM_BUF)   // 81920

__global__ void __launch_bounds__(128, 2)
attn_tc_kernel(const f16* __restrict__ Qh, const f16* __restrict__ Ql,
               const f16* __restrict__ Kh, const f16* __restrict__ Kl,
               const f16* __restrict__ Vh, const f16* __restrict__ Vl,
               float* __restrict__ O) {
    extern __shared__ char smraw[];
    const uint32_t sb = s2u(smraw);

    int z = blockIdx.z;
    int bb = z / 7, t = z % 7;
    int grp, seg;
    if (t < 4)       { grp = 0; seg = t; }
    else if (t < 6)  { grp = 1; seg = t - 4; }
    else             { grp = 2; seg = 0; }
    const int sl = c_seg[grp], rdil = c_dil[grp];
    const int off = grp % rdil;
    const int head = grp * 4 + blockIdx.y;
    const int q0 = blockIdx.x * 64;
    const long segbase = (long)bb * NSEQ + (long)seg * sl;

    const int tid = threadIdx.x;
    const int lrow = tid >> 1;
    const int kb0 = (tid & 1) * 64;
    uint32_t sdst[4];
#pragma unroll
    for (int j = 0; j < 4; j++) {
        int kb = kb0 + j * 16;
        sdst[j] = (uint32_t)(lrow * 128 + (kb ^ ((lrow & 7) * 16)));
    }

#define ATT_ROWOFF(i0) ((segbase + off + (long)((i0) + lrow) * rdil) * DM + head * HD)

    // ---- load Q tile (hi+lo) ----
    {
        long fo = ATT_ROWOFF(q0);
        const char* gh = (const char*)(Qh + fo);
        const char* gl = (const char*)(Ql + fo);
#pragma unroll
        for (int j = 0; j < 4; j++) {
            CP16(sb + ASM_QH + sdst[j], gh + kb0 + j * 16);
            CP16(sb + ASM_QL + sdst[j], gl + kb0 + j * 16);
        }
    }
    CP_COMMIT();

#define LOAD_KV(ti, buf) do {                                                \
    long fo_ = ATT_ROWOFF((ti) * 64);                                        \
    uint32_t bs_ = sb + ASM_KV + (buf) * ASM_BUF;                            \
    const char* gkh_ = (const char*)(Kh + fo_);                              \
    const char* gkl_ = (const char*)(Kl + fo_);                              \
    const char* gvh_ = (const char*)(Vh + fo_);                              \
    const char* gvl_ = (const char*)(Vl + fo_);                              \
    _Pragma("unroll")                                                        \
    for (int j = 0; j < 4; j++) {                                            \
        CP16(bs_ + sdst[j],         gkh_ + kb0 + j * 16);                    \
        CP16(bs_ + 8192 + sdst[j],  gkl_ + kb0 + j * 16);                    \
        CP16(bs_ + 16384 + sdst[j], gvh_ + kb0 + j * 16);                    \
        CP16(bs_ + 24576 + sdst[j], gvl_ + kb0 + j * 16);                    \
    }                                                                        \
} while (0)

    LOAD_KV(0, 0);
    CP_COMMIT();
    CP_WAIT1();          // Q group retired (<=1 pending = KV tile 0)
    __syncthreads();

    // ---- per-warp fragment addressing ----
    const int l = tid & 31, w = tid >> 5;
    const int mi = l >> 3, rr = l & 7;
    const int rbase = (mi & 1) * 8 + rr;    // row within a 16-row block
    const int cxor = rr * 16;               // SW128 xor term (row&7 == rr)
    const int ksel = (mi >> 1) * 16;        // 8-col (16B) selector

    // Q fragments (resident)
    uint32_t qfh[4][4], qfl[4][4];
    {
        uint32_t qrow = (uint32_t)((w * 16 + rbase) * 128);
#pragma unroll
        for (int ks = 0; ks < 4; ks++) {
            uint32_t cb = (uint32_t)((ks * 32 + ksel) ^ cxor);
            LDSM4(qfh[ks], sb + ASM_QH + qrow + cb);
            LDSM4(qfl[ks], sb + ASM_QL + qrow + cb);
        }
    }

    float Oa[8][4];
#pragma unroll
    for (int nf = 0; nf < 8; nf++)
#pragma unroll
        for (int c = 0; c < 4; c++) Oa[nf][c] = 0.f;
    float m0 = -1e30f, m1 = -1e30f, l0 = 0.f, l1 = 0.f;

    for (int kt = 0; kt < 32; kt++) {
        if (kt + 1 < 32) LOAD_KV(kt + 1, (kt + 1) & 1);
        CP_COMMIT();
        CP_WAIT1();
        __syncthreads();

        const uint32_t bs = sb + ASM_KV + (kt & 1) * ASM_BUF;

        // ---- S = Q K^T (3-pass), fp32 acc; 16q x 64kv per warp ----
        float S[8][4];
#pragma unroll
        for (int nf = 0; nf < 8; nf++)
#pragma unroll
            for (int c = 0; c < 4; c++) S[nf][c] = 0.f;

#pragma unroll
        for (int ks = 0; ks < 4; ks++) {
            uint32_t cb = (uint32_t)((ks * 32 + ksel) ^ cxor);
            uint32_t bh[4][4], bl[4][4];
#pragma unroll
            for (int np = 0; np < 4; np++) {
                uint32_t ro = (uint32_t)((np * 16 + rbase) * 128);
                LDSM4(bh[np], bs + ro + cb);
                LDSM4(bl[np], bs + 8192 + ro + cb);
            }
#pragma unroll
            for (int nf = 0; nf < 8; nf++) {
                int np = nf >> 1, hh = nf & 1;
                uint32_t b0 = bh[np][hh], b1 = bh[np][hh + 2];
                uint32_t c0 = bl[np][hh], c1 = bl[np][hh + 2];
                MMA16816(S[nf], qfh[ks], b0, b1);
                MMA16816(S[nf], qfl[ks], b0, b1);
                MMA16816(S[nf], qfh[ks], c0, c1);
            }
        }

        // ---- online softmax (rows r=l>>2 and r+8) ----
        float mx0 = -1e30f, mx1 = -1e30f;
#pragma unroll
        for (int nf = 0; nf < 8; nf++) {
            mx0 = fmaxf(mx0, fmaxf(S[nf][0], S[nf][1]));
            mx1 = fmaxf(mx1, fmaxf(S[nf][2], S[nf][3]));
        }
        mx0 = fmaxf(mx0, __shfl_xor_sync(0xffffffffu, mx0, 1));
        mx0 = fmaxf(mx0, __shfl_xor_sync(0xffffffffu, mx0, 2));
        mx1 = fmaxf(mx1, __shfl_xor_sync(0xffffffffu, mx1, 1));
        mx1 = fmaxf(mx1, __shfl_xor_sync(0xffffffffu, mx1, 2));
        float nm0 = fmaxf(m0, mx0), nm1 = fmaxf(m1, mx1);
        float fac0 = __expf(m0 - nm0), fac1 = __expf(m1 - nm1);
        m0 = nm0; m1 = nm1;
        float rs0 = 0.f, rs1 = 0.f;
#pragma unroll
        for (int nf = 0; nf < 8; nf++) {
            S[nf][0] = __expf(S[nf][0] - nm0); rs0 += S[nf][0];
            S[nf][1] = __expf(S[nf][1] - nm0); rs0 += S[nf][1];
            S[nf][2] = __expf(S[nf][2] - nm1); rs1 += S[nf][2];
            S[nf][3] = __expf(S[nf][3] - nm1); rs1 += S[nf][3];
        }
        rs0 += __shfl_xor_sync(0xffffffffu, rs0, 1);
        rs0 += __shfl_xor_sync(0xffffffffu, rs0, 2);
        rs1 += __shfl_xor_sync(0xffffffffu, rs1, 1);
        rs1 += __shfl_xor_sync(0xffffffffu, rs1, 2);
        l0 = l0 * fac0 + rs0;
        l1 = l1 * fac1 + rs1;
#pragma unroll
        for (int nf = 0; nf < 8; nf++) {
            Oa[nf][0] *= fac0; Oa[nf][1] *= fac0;
            Oa[nf][2] *= fac1; Oa[nf][3] *= fac1;
        }

        // ---- O += P V (3-pass); P frags from S regs (no smem) ----
#pragma unroll
        for (int j = 0; j < 4; j++) {
            // A-frag (m16 x k16 over kv) from S[2j], S[2j+1]
            uint32_t pah[4], pal[4];
            {
                const float* s0 = S[2 * j];
                const float* s1 = S[2 * j + 1];
                f16 h00 = __float2half_rn(s0[0]), h01 = __float2half_rn(s0[1]);
                f16 h02 = __float2half_rn(s0[2]), h03 = __float2half_rn(s0[3]);
                f16 h10 = __float2half_rn(s1[0]), h11 = __float2half_rn(s1[1]);
                f16 h12 = __float2half_rn(s1[2]), h13 = __float2half_rn(s1[3]);
                pah[0] = pack_h2(h00, h01);
                pah[1] = pack_h2(h02, h03);
                pah[2] = pack_h2(h10, h11);
                pah[3] = pack_h2(h12, h13);
                pal[0] = pack_h2(__float2half_rn(s0[0] - __half2float(h00)),
                                 __float2half_rn(s0[1] - __half2float(h01)));
                pal[1] = pack_h2(__float2half_rn(s0[2] - __half2float(h02)),
                                 __float2half_rn(s0[3] - __half2float(h03)));
                pal[2] = pack_h2(__float2half_rn(s1[0] - __half2float(h10)),
                                 __float2half_rn(s1[1] - __half2float(h11)));
                pal[3] = pack_h2(__float2half_rn(s1[2] - __half2float(h12)),
                                 __float2half_rn(s1[3] - __half2float(h13)));
            }
            // V b-frags via ldmatrix.trans: k = kv (rows), n = d (cols)
            uint32_t vh[4][4], vl[4][4];
#pragma unroll
            for (int np = 0; np < 4; np++) {
                uint32_t ro = (uint32_t)((j * 16 + rbase) * 128);
                uint32_t cb = (uint32_t)((np * 32 + ksel) ^ cxor);
                LDSM4T(vh[np], bs + 16384 + ro + cb);
                LDSM4T(vl[np], bs + 24576 + ro + cb);
            }
#pragma unroll
            for (int nf = 0; nf < 8; nf++) {
                int np = nf >> 1, hh = nf & 1;
                uint32_t b0 = vh[np][hh * 2], b1 = vh[np][hh * 2 + 1];
                uint32_t c0 = vl[np][hh * 2], c1 = vl[np][hh * 2 + 1];
                MMA16816(Oa[nf], pah, b0, b1);
                MMA16816(Oa[nf], pal, b0, b1);
                MMA16816(Oa[nf], pah, c0, c1);
            }
        }
        __syncthreads();
    }

    // ---- epilogue ----
    float inv0 = 1.f / l0, inv1 = 1.f / l1;
    int r0 = q0 + w * 16 + (l >> 2);
    long n0tok = segbase + off + (long)r0 * rdil;
    long n1tok = segbase + off + (long)(r0 + 8) * rdil;
    float* o0 = O + n0tok * DM + head * HD;
    float* o1 = O + n1tok * DM + head * HD;
    int cbase = (l & 3) * 2;
#pragma unroll
    for (int nf = 0; nf < 8; nf++) {
        int col = nf * 8 + cbase;
        *(float2*)(o0 + col) = make_float2(Oa[nf][0] * inv0, Oa[nf][1] * inv0);
        *(float2*)(o1 + col) = make_float2(Oa[nf][2] * inv1, Oa[nf][3] * inv1);
    }
#undef ATT_ROWOFF
#undef LOAD_KV
}

// ---------------- host orchestration ---------------------------------------
extern "C" void kernel_launch(void* const* d_in, const int* in_sizes, int n_in,
                              void* d_out, int out_size) {
    const float* src  = (const float*)d_in[0];
    const float* ln1w = (const float*)d_in[1];
    const float* ln1b = (const float*)d_in[2];
    const float* Wq   = (const float*)d_in[3];
    const float* bq   = (const float*)d_in[4];
    const float* Wk   = (const float*)d_in[5];
    const float* bk   = (const float*)d_in[6];
    const float* Wv   = (const float*)d_in[7];
    const float* bv   = (const float*)d_in[8];
    const float* lnAw = (const float*)d_in[9];
    const float* lnAb = (const float*)d_in[10];
    const float* Wo   = (const float*)d_in[11];
    const float* bo   = (const float*)d_in[12];
    const float* ln2w = (const float*)d_in[13];
    const float* ln2b = (const float*)d_in[14];
    const float* W1   = (const float*)d_in[15];
    const float* b1   = (const float*)d_in[16];
    const float* ln3w = (const float*)d_in[17];
    const float* ln3b = (const float*)d_in[18];
    const float* W2   = (const float*)d_in[19];
    const float* b2   = (const float*)d_in[20];
    float* out = (float*)d_out;

    float *px, *patt, *pf1;
    f16 *ahi, *alo, *qh, *ql, *kh, *kl, *vh, *vl;
    f16 *wqh, *wql, *wkh, *wkl, *wvh, *wvl, *woh, *wol, *w1h, *w1l, *w2h, *w2l;
    cudaGetSymbolAddress((void**)&px,   g_x);
    cudaGetSymbolAddress((void**)&patt, g_att);
    cudaGetSymbolAddress((void**)&pf1,  g_f1);
    cudaGetSymbolAddress((void**)&ahi,  g_ahi);
    cudaGetSymbolAddress((void**)&alo,  g_alo);
    cudaGetSymbolAddress((void**)&qh,   g_qh);
    cudaGetSymbolAddress((void**)&ql,   g_ql);
    cudaGetSymbolAddress((void**)&kh,   g_kh);
    cudaGetSymbolAddress((void**)&kl,   g_kl);
    cudaGetSymbolAddress((void**)&vh,   g_vh);
    cudaGetSymbolAddress((void**)&vl,   g_vl);
    cudaGetSymbolAddress((void**)&wqh,  g_wqh);
    cudaGetSymbolAddress((void**)&wql,  g_wql);
    cudaGetSymbolAddress((void**)&wkh,  g_wkh);
    cudaGetSymbolAddress((void**)&wkl,  g_wkl);
    cudaGetSymbolAddress((void**)&wvh,  g_wvh);
    cudaGetSymbolAddress((void**)&wvl,  g_wvl);
    cudaGetSymbolAddress((void**)&woh,  g_woh);
    cudaGetSymbolAddress((void**)&wol,  g_wol);
    cudaGetSymbolAddress((void**)&w1h,  g_w1h);
    cudaGetSymbolAddress((void**)&w1l,  g_w1l);
    cudaGetSymbolAddress((void**)&w2h,  g_w2h);
    cudaGetSymbolAddress((void**)&w2l,  g_w2l);

    static bool attr_done = false;
    if (!attr_done) {
        cudaFuncSetAttribute(gemm3x_kernel, cudaFuncAttributeMaxDynamicSharedMemorySize, GSMEM);
        cudaFuncSetAttribute(attn_tc_kernel, cudaFuncAttributeMaxDynamicSharedMemorySize, ASMEM);
        attr_done = true;
    }

    dim3 tT(32, 8);
    dim3 gW(DM / 32, DM / 32);
    dim3 gW1(DM / 32, DFF / 32);
    dim3 gW2(DFF / 32, DM / 32);
    dim3 gq(DM / 128, NTOK / 128);      // (6,128)
    dim3 g1(DFF / 128, NTOK / 128);     // (24,128)

    // weight transpose+split
    splitT_kernel<<<gW,  tT>>>(Wq, wqh, wql, DM, DM);
    splitT_kernel<<<gW,  tT>>>(Wk, wkh, wkl, DM, DM);
    splitT_kernel<<<gW,  tT>>>(Wv, wvh, wvl, DM, DM);
    splitT_kernel<<<gW,  tT>>>(Wo, woh, wol, DM, DM);
    splitT_kernel<<<gW1, tT>>>(W1, w1h, w1l, DM, DFF);
    splitT_kernel<<<gW2, tT>>>(W2, w2h, w2l, DFF, DM);

    // LN1 -> split, QKV projections straight to fp16 hi/lo (Q pre-scaled)
    ln_split_kernel<<<NTOK, 256>>>(src, ln1w, ln1b, ahi, alo, DM);
    gemm3x_kernel<<<gq, 256, GSMEM>>>(ahi, alo, wqh, wql, bq, nullptr, qh, ql, 0.125f, DM, DM, 0);
    gemm3x_kernel<<<gq, 256, GSMEM>>>(ahi, alo, wkh, wkl, bk, nullptr, kh, kl, 1.0f,   DM, DM, 0);
    gemm3x_kernel<<<gq, 256, GSMEM>>>(ahi, alo, wvh, wvl, bv, nullptr, vh, vl, 1.0f,   DM, DM, 0);

    // attention: zero + tensor-core dilated flash attention
    zero_kernel<<<4096, 256>>>((float4*)patt, (long)NTOK * DM / 4);
    attn_tc_kernel<<<dim3(32, 4, 14), 128, ASMEM>>>(qh, ql, kh, kl, vh, vl, patt);

    // MAGNETO sub-LN -> split, out projection
    ln_split_kernel<<<NTOK, 256>>>(patt, lnAw, lnAb, ahi, alo, DM);
    gemm3x_kernel<<<gq, 256, GSMEM>>>(ahi, alo, woh, wol, bo, px, nullptr, nullptr, 1.0f, DM, DM, 0);

    // LN2 -> split, FF1 (relu)
    ln_split_kernel<<<NTOK, 256>>>(px, ln2w, ln2b, ahi, alo, DM);
    gemm3x_kernel<<<g1, 256, GSMEM>>>(ahi, alo, w1h, w1l, b1, pf1, nullptr, nullptr, 1.0f, DM, DFF, 1);

    // LN3 -> split, FF2
    ln_split_kernel<<<NTOK, 256>>>(pf1, ln3w, ln3b, ahi, alo, DFF);
    gemm3x_kernel<<<gq, 256, GSMEM>>>(ahi, alo, w2h, w2l, b2, out, nullptr, nullptr, 1.0f, DFF, DM, 0);
}

// round 10
// speedup vs baseline: 2.6531x; 1.0460x over previous
#include <cuda_runtime.h>
#include <cuda_fp16.h>
#include <cstdint>

#define NTOK 16384          // B*N = 2*8192
#define NSEQ 8192
#define DM   768
#define DFF  3072
#define NH   12
#define HD   64

typedef __half f16;

// ---------------- scratch (device globals; no allocation allowed) ----------
__device__ float g_x  [NTOK * DM];     // Wo output
__device__ float g_att[NTOK * DM];     // attention output (fp32)
__device__ float g_f1 [NTOK * DFF];
__device__ f16   g_ahi[NTOK * DFF];
__device__ f16   g_alo[NTOK * DFF];
__device__ f16   g_qh [NTOK * DM], g_ql[NTOK * DM];
__device__ f16   g_kh [NTOK * DM], g_kl[NTOK * DM];
__device__ f16   g_vh [NTOK * DM], g_vl[NTOK * DM];
__device__ f16   g_wqkvh[3 * DM * DM], g_wqkvl[3 * DM * DM];   // packed Q,K,V
__device__ f16   g_woh[DM * DM],  g_wol[DM * DM];
__device__ f16   g_w1h[DM * DFF], g_w1l[DM * DFF];
__device__ f16   g_w2h[DFF * DM], g_w2l[DFF * DM];

// ======================= PTX helpers =======================================
__device__ __forceinline__ uint32_t s2u(const void* p) {
    uint32_t a;
    asm("{ .reg .u64 t; cvta.to.shared.u64 t, %1; cvt.u32.u64 %0, t; }"
        : "=r"(a) : "l"(p));
    return a;
}

#define CP16(dst, src) \
    asm volatile("cp.async.cg.shared.global [%0], [%1], 16;" :: "r"(dst), "l"(src) : "memory")
#define CP_COMMIT() asm volatile("cp.async.commit_group;" ::: "memory")
#define CP_WAIT1()  asm volatile("cp.async.wait_group 1;" ::: "memory")

#define LDSM4(r, a)                                                          \
    asm volatile("ldmatrix.sync.aligned.m8n8.x4.shared.b16 {%0,%1,%2,%3}, [%4];" \
        : "=r"((r)[0]), "=r"((r)[1]), "=r"((r)[2]), "=r"((r)[3]) : "r"(a))

#define LDSM4T(r, a)                                                         \
    asm volatile("ldmatrix.sync.aligned.m8n8.x4.trans.shared.b16 {%0,%1,%2,%3}, [%4];" \
        : "=r"((r)[0]), "=r"((r)[1]), "=r"((r)[2]), "=r"((r)[3]) : "r"(a))

#define MMA16816(c, a, b0, b1)                                               \
    asm volatile("mma.sync.aligned.m16n8k16.row.col.f32.f16.f16.f32 "        \
        "{%0,%1,%2,%3}, {%4,%5,%6,%7}, {%8,%9}, {%0,%1,%2,%3};"              \
        : "+f"((c)[0]), "+f"((c)[1]), "+f"((c)[2]), "+f"((c)[3])             \
        : "r"((a)[0]), "r"((a)[1]), "r"((a)[2]), "r"((a)[3]),                \
          "r"(b0), "r"(b1))

__device__ __forceinline__ uint32_t pack_h2(f16 a, f16 b) {
    __half2 h = __halves2half2(a, b);
    return *reinterpret_cast<uint32_t*>(&h);
}

// ================= LayerNorm fused with fp16 hi/lo split ===================
__global__ void ln_split_kernel(const float* __restrict__ x, const float* __restrict__ w,
                                const float* __restrict__ b, f16* __restrict__ hi,
                                f16* __restrict__ lo, int C) {
    long row = blockIdx.x;
    const float* xr = x + row * (long)C;
    float s = 0.f, ss = 0.f;
    for (int c = threadIdx.x; c < C; c += 256) {
        float v = xr[c];
        s += v; ss += v * v;
    }
    for (int o = 16; o; o >>= 1) {
        s  += __shfl_xor_sync(0xffffffffu, s,  o);
        ss += __shfl_xor_sync(0xffffffffu, ss, o);
    }
    __shared__ float sh[2][8];
    int wi = threadIdx.x >> 5, li = threadIdx.x & 31;
    if (li == 0) { sh[0][wi] = s; sh[1][wi] = ss; }
    __syncthreads();
    if (threadIdx.x < 32) {
        s  = (li < 8) ? sh[0][li] : 0.f;
        ss = (li < 8) ? sh[1][li] : 0.f;
        for (int o = 4; o; o >>= 1) {
            s  += __shfl_xor_sync(0xffffffffu, s,  o);
            ss += __shfl_xor_sync(0xffffffffu, ss, o);
        }
        if (li == 0) { sh[0][0] = s; sh[1][0] = ss; }
    }
    __syncthreads();
    float mean = sh[0][0] / (float)C;
    float var  = sh[1][0] / (float)C - mean * mean;
    float rstd = rsqrtf(var + 1e-5f);
    f16* hr = hi + row * (long)C;
    f16* lr = lo + row * (long)C;
    for (int c = threadIdx.x; c < C; c += 256) {
        float y = (xr[c] - mean) * rstd * w[c] + b[c];
        f16 h = __float2half_rn(y);
        hr[c] = h;
        lr[c] = __float2half_rn(y - __half2float(h));
    }
}

// ============ weight transpose + split: W[K,N] -> hi/lo [N,K] ==============
__global__ void splitT_kernel(const float* __restrict__ W, f16* __restrict__ hi,
                              f16* __restrict__ lo, int K, int N) {
    __shared__ float t[32][33];
    int k0 = blockIdx.x * 32, n0 = blockIdx.y * 32;
    int tx = threadIdx.x, ty = threadIdx.y;   // 32 x 8
#pragma unroll
    for (int i = 0; i < 4; i++)
        t[ty + 8 * i][tx] = W[(long)(k0 + ty + 8 * i) * N + n0 + tx];
    __syncthreads();
#pragma unroll
    for (int i = 0; i < 4; i++) {
        float v = t[tx][ty + 8 * i];
        f16 h = __float2half_rn(v);
        long o = (long)(n0 + ty + 8 * i) * K + k0 + tx;
        hi[o] = h;
        lo[o] = __float2half_rn(v - __half2float(h));
    }
}

// ---------------- zero fill ------------------------------------------------
__global__ void zero_kernel(float4* __restrict__ p, long n4) {
    long i = (long)blockIdx.x * blockDim.x + threadIdx.x;
    long stride = (long)gridDim.x * blockDim.x;
    float4 z = make_float4(0.f, 0.f, 0.f, 0.f);
    for (; i < n4; i += stride) p[i] = z;
}

// ================= mma.sync 3x-fp16 GEMM ===================================
// D = (Ahi+Alo)[M,K] x ((Bhi+Blo)[Nrows,K])^T + bias.
// MODE 0: fp32 out (C, bias0, optional relu).
// MODE 2: fused QKV — B is packed [3*DM, K]; per-128-block output goes to
//         (h0/l0, h1/l1, h2/l2) with bias (b0/b1/b2); Q block scaled 0.125.
#define GSTAGES 3
#define TILE_B   16384                   // one operand tile: 128 rows x 128 B
#define GSTAGE_B (4 * TILE_B)            // Ah, Al, Bh, Bl
#define GSMEM    (GSTAGES * GSTAGE_B)    // 196608

template <int MODE>
__global__ void __launch_bounds__(256, 1)
gemm3x_kernel(const f16* __restrict__ Ahi, const f16* __restrict__ Alo,
              const f16* __restrict__ Bhi, const f16* __restrict__ Blo,
              const float* __restrict__ bias0, const float* __restrict__ bias1,
              const float* __restrict__ bias2, float* __restrict__ C,
              f16* __restrict__ h0, f16* __restrict__ l0,
              f16* __restrict__ h1, f16* __restrict__ l1,
              f16* __restrict__ h2, f16* __restrict__ l2,
              int Kdim, int Ncols, int relu) {
    extern __shared__ char smraw[];
    const uint32_t sb = s2u(smraw);
    const int tid = threadIdx.x;
    const int m0 = blockIdx.y * 128, n0 = blockIdx.x * 128;
    const int nk = Kdim >> 6;                 // chunks of 64 fp16
    const long rowb = (long)Kdim * 2;         // bytes per gmem row

    const char* pAh = (const char*)Ahi + (long)m0 * rowb;
    const char* pAl = (const char*)Alo + (long)m0 * rowb;
    const char* pBh = (const char*)Bhi + (long)n0 * rowb;
    const char* pBl = (const char*)Blo + (long)n0 * rowb;

    int lrow[4], lkb[4];
    uint32_t ldst[4];
#pragma unroll
    for (int j = 0; j < 4; j++) {
        int u = tid + 256 * j;
        lrow[j] = u >> 3;
        lkb[j]  = (u & 7) * 16;
        ldst[j] = (uint32_t)(lrow[j] * 128 + (lkb[j] ^ ((lrow[j] & 7) * 16)));
    }

#define LOAD_CHUNK(slot, ci) do {                                            \
    uint32_t stg_ = sb + (slot) * GSTAGE_B;                                  \
    long koff_ = (long)(ci) * 128;                                           \
    _Pragma("unroll")                                                        \
    for (int j = 0; j < 4; j++) {                                            \
        long go = (long)lrow[j] * rowb + koff_ + lkb[j];                     \
        CP16(stg_ + ldst[j],              pAh + go);                         \
        CP16(stg_ + TILE_B + ldst[j],     pAl + go);                         \
        CP16(stg_ + 2 * TILE_B + ldst[j], pBh + go);                         \
        CP16(stg_ + 3 * TILE_B + ldst[j], pBl + go);                         \
    }                                                                        \
} while (0)

    const int wid = tid >> 5, l = tid & 31;
    const int wm = wid & 3, wn = wid >> 2;
    const int quad = l >> 3, rim = l & 7;
    const int rimx = rim * 16;
    const int kbq = (quad >> 1) * 16;

    uint32_t aoff[2], boff[4];
#pragma unroll
    for (int mf = 0; mf < 2; mf++)
        aoff[mf] = (uint32_t)((wm * 32 + mf * 16 + (quad & 1) * 8 + rim) * 128);
#pragma unroll
    for (int np = 0; np < 4; np++)
        boff[np] = (uint32_t)((wn * 64 + np * 16 + (quad & 1) * 8 + rim) * 128);

    float acc[2][8][4];
#pragma unroll
    for (int mf = 0; mf < 2; mf++)
#pragma unroll
        for (int nf = 0; nf < 8; nf++)
#pragma unroll
            for (int c = 0; c < 4; c++) acc[mf][nf][c] = 0.f;

#pragma unroll
    for (int s = 0; s < GSTAGES - 1; s++) {
        LOAD_CHUNK(s, s);
        CP_COMMIT();
    }

    int slot = 0;
    for (int i = 0; i < nk; i++) {
        CP_WAIT1();
        __syncthreads();
        int nc = i + GSTAGES - 1;
        if (nc < nk) LOAD_CHUNK((nc % GSTAGES), nc);
        CP_COMMIT();

        const uint32_t stg = sb + slot * GSTAGE_B;
        const uint32_t aH = stg, aL = stg + TILE_B;
        const uint32_t bH = stg + 2 * TILE_B, bL = stg + 3 * TILE_B;

#pragma unroll
        for (int ks = 0; ks < 4; ks++) {
            const uint32_t kx = (uint32_t)((ks * 32 + kbq) ^ rimx);
            uint32_t ah[2][4], al[2][4], bh[4][4], bl[4][4];
#pragma unroll
            for (int mf = 0; mf < 2; mf++) {
                LDSM4(ah[mf], aH + aoff[mf] + kx);
                LDSM4(al[mf], aL + aoff[mf] + kx);
            }
#pragma unroll
            for (int np = 0; np < 4; np++) {
                LDSM4(bh[np], bH + boff[np] + kx);
                LDSM4(bl[np], bL + boff[np] + kx);
            }
            // pass-outer ordering: 16 independent accumulators between every
            // same-acc reuse (kills the 3-deep HMMA dependency chain)
#pragma unroll
            for (int mf = 0; mf < 2; mf++)
#pragma unroll
                for (int nf = 0; nf < 8; nf++) {
                    int np = nf >> 1, hh = nf & 1;
                    MMA16816(acc[mf][nf], ah[mf], bh[np][hh], bh[np][hh + 2]);
                }
#pragma unroll
            for (int mf = 0; mf < 2; mf++)
#pragma unroll
                for (int nf = 0; nf < 8; nf++) {
                    int np = nf >> 1, hh = nf & 1;
                    MMA16816(acc[mf][nf], al[mf], bh[np][hh], bh[np][hh + 2]);
                }
#pragma unroll
            for (int mf = 0; mf < 2; mf++)
#pragma unroll
                for (int nf = 0; nf < 8; nf++) {
                    int np = nf >> 1, hh = nf & 1;
                    MMA16816(acc[mf][nf], ah[mf], bl[np][hh], bl[np][hh + 2]);
                }
        }
        __syncthreads();
        slot = (slot + 1 == GSTAGES) ? 0 : slot + 1;
    }

    // ---------------- epilogue -----------------------------------------
    const float* bp = bias0;
    f16 *chi = h0, *clo = l0;
    float alpha = 1.f;
    int outb = n0;
    if (MODE == 2) {
        int mat = n0 / DM;
        outb = n0 - mat * DM;
        bp  = (mat == 0) ? bias0 : (mat == 1) ? bias1 : bias2;
        chi = (mat == 0) ? h0 : (mat == 1) ? h1 : h2;
        clo = (mat == 0) ? l0 : (mat == 1) ? l1 : l2;
        alpha = (mat == 0) ? 0.125f : 1.f;
    }
    const int g = l >> 2, t4 = l & 3;
#pragma unroll
    for (int mf = 0; mf < 2; mf++) {
        int row = m0 + wm * 32 + mf * 16 + g;
#pragma unroll
        for (int nf = 0; nf < 8; nf++) {
            int col = outb + wn * 64 + nf * 8 + 2 * t4;
            float b0v = bp[col], b1v = bp[col + 1];
            float v0 = acc[mf][nf][0] + b0v;
            float v1 = acc[mf][nf][1] + b1v;
            float v2 = acc[mf][nf][2] + b0v;
            float v3 = acc[mf][nf][3] + b1v;
            if (MODE == 0 && relu) {
                v0 = fmaxf(v0, 0.f); v1 = fmaxf(v1, 0.f);
                v2 = fmaxf(v2, 0.f); v3 = fmaxf(v3, 0.f);
            }
            if (MODE == 2) {
                v0 *= alpha; v1 *= alpha; v2 *= alpha; v3 *= alpha;
                f16 c0 = __float2half_rn(v0), c1 = __float2half_rn(v1);
                f16 c2 = __float2half_rn(v2), c3 = __float2half_rn(v3);
                f16 r0 = __float2half_rn(v0 - __half2float(c0));
                f16 r1 = __float2half_rn(v1 - __half2float(c1));
                f16 r2 = __float2half_rn(v2 - __half2float(c2));
                f16 r3 = __float2half_rn(v3 - __half2float(c3));
                *(uint32_t*)(chi + (long)row * Ncols + col)       = pack_h2(c0, c1);
                *(uint32_t*)(chi + (long)(row + 8) * Ncols + col) = pack_h2(c2, c3);
                *(uint32_t*)(clo + (long)row * Ncols + col)       = pack_h2(r0, r1);
                *(uint32_t*)(clo + (long)(row + 8) * Ncols + col) = pack_h2(r2, r3);
            } else {
                *(float2*)(C + (long)row * Ncols + col)       = make_float2(v0, v1);
                *(float2*)(C + (long)(row + 8) * Ncols + col) = make_float2(v2, v3);
            }
        }
    }
#undef LOAD_CHUNK
}

// ============== tensor-core dilated flash attention ========================
// CTA = 256 threads / 128 queries of one (batch, group-instance, head).
// 8 warps x 16 queries; Q fp16 hi/lo resident in registers (pre-scaled 0.125);
// K/V hi/lo streamed in 64-row tiles, double-buffered cp.async, SW128 smem.
__constant__ int c_seg[3] = {2048, 4096, 8192};
__constant__ int c_dil[3] = {1, 2, 4};

#define ASM_QH  0
#define ASM_QL  16384
#define ASM_KV  32768
#define ASM_BUF 32768       // per KV buffer: Kh 0, Kl 8K, Vh 16K, Vl 24K
#define ASMEM   (ASM_KV + 2 * ASM_BUF)   // 98304

__global__ void __launch_bounds__(256, 1)
attn_tc_kernel(const f16* __restrict__ Qh, const f16* __restrict__ Ql,
               const f16* __restrict__ Kh, const f16* __restrict__ Kl,
               const f16* __restrict__ Vh, const f16* __restrict__ Vl,
               float* __restrict__ O) {
    extern __shared__ char smraw[];
    const uint32_t sb = s2u(smraw);

    int z = blockIdx.z;
    int bb = z / 7, t = z % 7;
    int grp, seg;
    if (t < 4)       { grp = 0; seg = t; }
    else if (t < 6)  { grp = 1; seg = t - 4; }
    else             { grp = 2; seg = 0; }
    const int sl = c_seg[grp], rdil = c_dil[grp];
    const int off = grp % rdil;
    const int head = grp * 4 + blockIdx.y;
    const int q0 = blockIdx.x * 128;
    const long segbase = (long)bb * NSEQ + (long)seg * sl;

    const int tid = threadIdx.x;
    // Q loader: 256 threads cover 128 rows x 128 B
    const int qrow_l = tid >> 1;
    const int qkb0 = (tid & 1) * 64;
    uint32_t qdst[4];
#pragma unroll
    for (int j = 0; j < 4; j++) {
        int kb = qkb0 + j * 16;
        qdst[j] = (uint32_t)(qrow_l * 128 + (kb ^ ((qrow_l & 7) * 16)));
    }
    // KV loader: 256 threads cover 64 rows x 128 B per operand
    const int krow_l = tid >> 2;
    const int kkb0 = (tid & 3) * 32;
    uint32_t kdst[2];
#pragma unroll
    for (int j = 0; j < 2; j++) {
        int kb = kkb0 + j * 16;
        kdst[j] = (uint32_t)(krow_l * 128 + (kb ^ ((krow_l & 7) * 16)));
    }

    // ---- load Q tile (hi+lo) ----
    {
        long fo = (segbase + off + (long)(q0 + qrow_l) * rdil) * DM + head * HD;
        const char* gh = (const char*)(Qh + fo);
        const char* gl = (const char*)(Ql + fo);
#pragma unroll
        for (int j = 0; j < 4; j++) {
            CP16(sb + ASM_QH + qdst[j], gh + qkb0 + j * 16);
            CP16(sb + ASM_QL + qdst[j], gl + qkb0 + j * 16);
        }
    }
    CP_COMMIT();

#define LOAD_KV(ti, buf) do {                                                \
    long fo_ = (segbase + off + (long)((ti) * 64 + krow_l) * rdil) * DM + head * HD; \
    uint32_t bs_ = sb + ASM_KV + (buf) * ASM_BUF;                            \
    const char* gkh_ = (const char*)(Kh + fo_);                              \
    const char* gkl_ = (const char*)(Kl + fo_);                              \
    const char* gvh_ = (const char*)(Vh + fo_);                              \
    const char* gvl_ = (const char*)(Vl + fo_);                              \
    _Pragma("unroll")                                                        \
    for (int j = 0; j < 2; j++) {                                            \
        CP16(bs_ + kdst[j],         gkh_ + kkb0 + j * 16);                   \
        CP16(bs_ + 8192 + kdst[j],  gkl_ + kkb0 + j * 16);                   \
        CP16(bs_ + 16384 + kdst[j], gvh_ + kkb0 + j * 16);                   \
        CP16(bs_ + 24576 + kdst[j], gvl_ + kkb0 + j * 16);                   \
    }                                                                        \
} while (0)

    LOAD_KV(0, 0);
    CP_COMMIT();
    CP_WAIT1();          // Q group retired (<=1 pending = KV tile 0)
    __syncthreads();

    // ---- per-warp fragment addressing ----
    const int l = tid & 31, w = tid >> 5;
    const int mi = l >> 3, rr = l & 7;
    const int rbase = (mi & 1) * 8 + rr;    // row within a 16-row block
    const int cxor = rr * 16;               // SW128 xor term
    const int ksel = (mi >> 1) * 16;        // 8-col (16B) selector

    // Q fragments (resident)
    uint32_t qfh[4][4], qfl[4][4];
    {
        uint32_t qrow = (uint32_t)((w * 16 + rbase) * 128);
#pragma unroll
        for (int ks = 0; ks < 4; ks++) {
            uint32_t cb = (uint32_t)((ks * 32 + ksel) ^ cxor);
            LDSM4(qfh[ks], sb + ASM_QH + qrow + cb);
            LDSM4(qfl[ks], sb + ASM_QL + qrow + cb);
        }
    }

    float Oa[8][4];
#pragma unroll
    for (int nf = 0; nf < 8; nf++)
#pragma unroll
        for (int c = 0; c < 4; c++) Oa[nf][c] = 0.f;
    float m0 = -1e30f, m1 = -1e30f, l0 = 0.f, l1 = 0.f;

    for (int kt = 0; kt < 32; kt++) {
        if (kt + 1 < 32) LOAD_KV(kt + 1, (kt + 1) & 1);
        CP_COMMIT();
        CP_WAIT1();
        __syncthreads();

        const uint32_t bs = sb + ASM_KV + (kt & 1) * ASM_BUF;

        // ---- S = Q K^T (3-pass), fp32 acc; 16q x 64kv per warp ----
        float S[8][4];
#pragma unroll
        for (int nf = 0; nf < 8; nf++)
#pragma unroll
            for (int c = 0; c < 4; c++) S[nf][c] = 0.f;

#pragma unroll
        for (int ks = 0; ks < 4; ks++) {
            uint32_t cb = (uint32_t)((ks * 32 + ksel) ^ cxor);
            uint32_t bh[4][4], bl[4][4];
#pragma unroll
            for (int np = 0; np < 4; np++) {
                uint32_t ro = (uint32_t)((np * 16 + rbase) * 128);
                LDSM4(bh[np], bs + ro + cb);
                LDSM4(bl[np], bs + 8192 + ro + cb);
            }
#pragma unroll
            for (int nf = 0; nf < 8; nf++) {
                int np = nf >> 1, hh = nf & 1;
                MMA16816(S[nf], qfh[ks], bh[np][hh], bh[np][hh + 2]);
            }
#pragma unroll
            for (int nf = 0; nf < 8; nf++) {
                int np = nf >> 1, hh = nf & 1;
                MMA16816(S[nf], qfl[ks], bh[np][hh], bh[np][hh + 2]);
            }
#pragma unroll
            for (int nf = 0; nf < 8; nf++) {
                int np = nf >> 1, hh = nf & 1;
                MMA16816(S[nf], qfh[ks], bl[np][hh], bl[np][hh + 2]);
            }
        }

        // ---- online softmax (rows r=l>>2 and r+8) ----
        float mx0 = -1e30f, mx1 = -1e30f;
#pragma unroll
        for (int nf = 0; nf < 8; nf++) {
            mx0 = fmaxf(mx0, fmaxf(S[nf][0], S[nf][1]));
            mx1 = fmaxf(mx1, fmaxf(S[nf][2], S[nf][3]));
        }
        mx0 = fmaxf(mx0, __shfl_xor_sync(0xffffffffu, mx0, 1));
        mx0 = fmaxf(mx0, __shfl_xor_sync(0xffffffffu, mx0, 2));
        mx1 = fmaxf(mx1, __shfl_xor_sync(0xffffffffu, mx1, 1));
        mx1 = fmaxf(mx1, __shfl_xor_sync(0xffffffffu, mx1, 2));
        float nm0 = fmaxf(m0, mx0), nm1 = fmaxf(m1, mx1);
        float fac0 = __expf(m0 - nm0), fac1 = __expf(m1 - nm1);
        m0 = nm0; m1 = nm1;
        float rs0 = 0.f, rs1 = 0.f;
#pragma unroll
        for (int nf = 0; nf < 8; nf++) {
            S[nf][0] = __expf(S[nf][0] - nm0); rs0 += S[nf][0];
            S[nf][1] = __expf(S[nf][1] - nm0); rs0 += S[nf][1];
            S[nf][2] = __expf(S[nf][2] - nm1); rs1 += S[nf][2];
            S[nf][3] = __expf(S[nf][3] - nm1); rs1 += S[nf][3];
        }
        rs0 += __shfl_xor_sync(0xffffffffu, rs0, 1);
        rs0 += __shfl_xor_sync(0xffffffffu, rs0, 2);
        rs1 += __shfl_xor_sync(0xffffffffu, rs1, 1);
        rs1 += __shfl_xor_sync(0xffffffffu, rs1, 2);
        l0 = l0 * fac0 + rs0;
        l1 = l1 * fac1 + rs1;
#pragma unroll
        for (int nf = 0; nf < 8; nf++) {
            Oa[nf][0] *= fac0; Oa[nf][1] *= fac0;
            Oa[nf][2] *= fac1; Oa[nf][3] *= fac1;
        }

        // ---- O += P V (3-pass); P frags from S regs (no smem) ----
#pragma unroll
        for (int j = 0; j < 4; j++) {
            uint32_t pah[4], pal[4];
            {
                const float* s0 = S[2 * j];
                const float* s1 = S[2 * j + 1];
                f16 h00 = __float2half_rn(s0[0]), h01 = __float2half_rn(s0[1]);
                f16 h02 = __float2half_rn(s0[2]), h03 = __float2half_rn(s0[3]);
                f16 h10 = __float2half_rn(s1[0]), h11 = __float2half_rn(s1[1]);
                f16 h12 = __float2half_rn(s1[2]), h13 = __float2half_rn(s1[3]);
                pah[0] = pack_h2(h00, h01);
                pah[1] = pack_h2(h02, h03);
                pah[2] = pack_h2(h10, h11);
                pah[3] = pack_h2(h12, h13);
                pal[0] = pack_h2(__float2half_rn(s0[0] - __half2float(h00)),
                                 __float2half_rn(s0[1] - __half2float(h01)));
                pal[1] = pack_h2(__float2half_rn(s0[2] - __half2float(h02)),
                                 __float2half_rn(s0[3] - __half2float(h03)));
                pal[2] = pack_h2(__float2half_rn(s1[0] - __half2float(h10)),
                                 __float2half_rn(s1[1] - __half2float(h11)));
                pal[3] = pack_h2(__float2half_rn(s1[2] - __half2float(h12)),
                                 __float2half_rn(s1[3] - __half2float(h13)));
            }
            uint32_t vh[4][4], vl[4][4];
#pragma unroll
            for (int np = 0; np < 4; np++) {
                uint32_t ro = (uint32_t)((j * 16 + rbase) * 128);
                uint32_t cb = (uint32_t)((np * 32 + ksel) ^ cxor);
                LDSM4T(vh[np], bs + 16384 + ro + cb);
                LDSM4T(vl[np], bs + 24576 + ro + cb);
            }
#pragma unroll
            for (int nf = 0; nf < 8; nf++) {
                int np = nf >> 1, hh = nf & 1;
                MMA16816(Oa[nf], pah, vh[np][hh * 2], vh[np][hh * 2 + 1]);
            }
#pragma unroll
            for (int nf = 0; nf < 8; nf++) {
                int np = nf >> 1, hh = nf & 1;
                MMA16816(Oa[nf], pal, vh[np][hh * 2], vh[np][hh * 2 + 1]);
            }
#pragma unroll
            for (int nf = 0; nf < 8; nf++) {
                int np = nf >> 1, hh = nf & 1;
                MMA16816(Oa[nf], pah, vl[np][hh * 2], vl[np][hh * 2 + 1]);
            }
        }
        __syncthreads();
    }

    // ---- epilogue ----
    float inv0 = 1.f / l0, inv1 = 1.f / l1;
    int r0 = q0 + w * 16 + (l >> 2);
    long n0tok = segbase + off + (long)r0 * rdil;
    long n1tok = segbase + off + (long)(r0 + 8) * rdil;
    float* o0 = O + n0tok * DM + head * HD;
    float* o1 = O + n1tok * DM + head * HD;
    int cbase = (l & 3) * 2;
#pragma unroll
    for (int nf = 0; nf < 8; nf++) {
        int col = nf * 8 + cbase;
        *(float2*)(o0 + col) = make_float2(Oa[nf][0] * inv0, Oa[nf][1] * inv0);
        *(float2*)(o1 + col) = make_float2(Oa[nf][2] * inv1, Oa[nf][3] * inv1);
    }
#undef LOAD_KV
}

// ---------------- host orchestration ---------------------------------------
extern "C" void kernel_launch(void* const* d_in, const int* in_sizes, int n_in,
                              void* d_out, int out_size) {
    const float* src  = (const float*)d_in[0];
    const float* ln1w = (const float*)d_in[1];
    const float* ln1b = (const float*)d_in[2];
    const float* Wq   = (const float*)d_in[3];
    const float* bq   = (const float*)d_in[4];
    const float* Wk   = (const float*)d_in[5];
    const float* bk   = (const float*)d_in[6];
    const float* Wv   = (const float*)d_in[7];
    const float* bv   = (const float*)d_in[8];
    const float* lnAw = (const float*)d_in[9];
    const float* lnAb = (const float*)d_in[10];
    const float* Wo   = (const float*)d_in[11];
    const float* bo   = (const float*)d_in[12];
    const float* ln2w = (const float*)d_in[13];
    const float* ln2b = (const float*)d_in[14];
    const float* W1   = (const float*)d_in[15];
    const float* b1   = (const float*)d_in[16];
    const float* ln3w = (const float*)d_in[17];
    const float* ln3b = (const float*)d_in[18];
    const float* W2   = (const float*)d_in[19];
    const float* b2   = (const float*)d_in[20];
    float* out = (float*)d_out;

    float *px, *patt, *pf1;
    f16 *ahi, *alo, *qh, *ql, *kh, *kl, *vh, *vl;
    f16 *wqkvh, *wqkvl, *woh, *wol, *w1h, *w1l, *w2h, *w2l;
    cudaGetSymbolAddress((void**)&px,    g_x);
    cudaGetSymbolAddress((void**)&patt,  g_att);
    cudaGetSymbolAddress((void**)&pf1,   g_f1);
    cudaGetSymbolAddress((void**)&ahi,   g_ahi);
    cudaGetSymbolAddress((void**)&alo,   g_alo);
    cudaGetSymbolAddress((void**)&qh,    g_qh);
    cudaGetSymbolAddress((void**)&ql,    g_ql);
    cudaGetSymbolAddress((void**)&kh,    g_kh);
    cudaGetSymbolAddress((void**)&kl,    g_kl);
    cudaGetSymbolAddress((void**)&vh,    g_vh);
    cudaGetSymbolAddress((void**)&vl,    g_vl);
    cudaGetSymbolAddress((void**)&wqkvh, g_wqkvh);
    cudaGetSymbolAddress((void**)&wqkvl, g_wqkvl);
    cudaGetSymbolAddress((void**)&woh,   g_woh);
    cudaGetSymbolAddress((void**)&wol,   g_wol);
    cudaGetSymbolAddress((void**)&w1h,   g_w1h);
    cudaGetSymbolAddress((void**)&w1l,   g_w1l);
    cudaGetSymbolAddress((void**)&w2h,   g_w2h);
    cudaGetSymbolAddress((void**)&w2l,   g_w2l);

    static bool attr_done = false;
    if (!attr_done) {
        cudaFuncSetAttribute(gemm3x_kernel<0>, cudaFuncAttributeMaxDynamicSharedMemorySize, GSMEM);
        cudaFuncSetAttribute(gemm3x_kernel<2>, cudaFuncAttributeMaxDynamicSharedMemorySize, GSMEM);
        cudaFuncSetAttribute(attn_tc_kernel, cudaFuncAttributeMaxDynamicSharedMemorySize, ASMEM);
        attr_done = true;
    }

    dim3 tT(32, 8);
    dim3 gW(DM / 32, DM / 32);
    dim3 gW1(DM / 32, DFF / 32);
    dim3 gW2(DFF / 32, DM / 32);
    dim3 gq(DM / 128, NTOK / 128);        // (6,128)
    dim3 gqkv(3 * DM / 128, NTOK / 128);  // (18,128)
    dim3 g1(DFF / 128, NTOK / 128);       // (24,128)

    // weight transpose+split (QKV packed along N)
    splitT_kernel<<<gW,  tT>>>(Wq, wqkvh,              wqkvl,              DM, DM);
    splitT_kernel<<<gW,  tT>>>(Wk, wqkvh + DM * DM,    wqkvl + DM * DM,    DM, DM);
    splitT_kernel<<<gW,  tT>>>(Wv, wqkvh + 2 * DM * DM, wqkvl + 2 * DM * DM, DM, DM);
    splitT_kernel<<<gW,  tT>>>(Wo, woh, wol, DM, DM);
    splitT_kernel<<<gW1, tT>>>(W1, w1h, w1l, DM, DFF);
    splitT_kernel<<<gW2, tT>>>(W2, w2h, w2l, DFF, DM);

    // LN1 -> split, fused QKV projection (Q pre-scaled 0.125, fp16 hi/lo out)
    ln_split_kernel<<<NTOK, 256>>>(src, ln1w, ln1b, ahi, alo, DM);
    gemm3x_kernel<2><<<gqkv, 256, GSMEM>>>(ahi, alo, wqkvh, wqkvl,
                                           bq, bk, bv, nullptr,
                                           qh, ql, kh, kl, vh, vl, DM, DM, 0);

    // attention: zero + tensor-core dilated flash attention (128-q tiles)
    zero_kernel<<<4096, 256>>>((float4*)patt, (long)NTOK * DM / 4);
    attn_tc_kernel<<<dim3(16, 4, 14), 256, ASMEM>>>(qh, ql, kh, kl, vh, vl, patt);

    // MAGNETO sub-LN -> split, out projection
    ln_split_kernel<<<NTOK, 256>>>(patt, lnAw, lnAb, ahi, alo, DM);
    gemm3x_kernel<0><<<gq, 256, GSMEM>>>(ahi, alo, woh, wol,
                                         bo, nullptr, nullptr, px,
                                         nullptr, nullptr, nullptr, nullptr,
                                         nullptr, nullptr, DM, DM, 0);

    // LN2 -> split, FF1 (relu)
    ln_split_kernel<<<NTOK, 256>>>(px, ln2w, ln2b, ahi, alo, DM);
    gemm3x_kernel<0><<<g1, 256, GSMEM>>>(ahi, alo, w1h, w1l,
                                         b1, nullptr, nullptr, pf1,
                                         nullptr, nullptr, nullptr, nullptr,
                                         nullptr, nullptr, DM, DFF, 1);

    // LN3 -> split, FF2
    ln_split_kernel<<<NTOK, 256>>>(pf1, ln3w, ln3b, ahi, alo, DFF);
    gemm3x_kernel<0><<<gq, 256, GSMEM>>>(ahi, alo, w2h, w2l,
                                         b2, nullptr, nullptr, out,
                                         nullptr, nullptr, nullptr, nullptr,
                                         nullptr, nullptr, DFF, DM, 0);
}

// round 11
// speedup vs baseline: 3.6103x; 1.3608x over previous
#include <cuda_runtime.h>
#include <cuda_fp16.h>
#include <cstdint>

#define NTOK 16384          // B*N = 2*8192
#define NSEQ 8192
#define DM   768
#define DFF  3072
#define NH   12
#define HD   64

typedef __half f16;

// ---------------- scratch (device globals; no allocation allowed) ----------
__device__ float g_x  [NTOK * DM];     // Wo output
__device__ float g_att[NTOK * DM];     // attention output (fp32)
__device__ float g_f1 [NTOK * DFF];
__device__ f16   g_ahi[NTOK * DFF];
__device__ f16   g_alo[NTOK * DFF];
__device__ f16   g_qh [NTOK * DM], g_ql[NTOK * DM];
__device__ f16   g_kh [NTOK * DM];
__device__ f16   g_vh [NTOK * DM];
__device__ f16   g_wqkvh[3 * DM * DM];     // packed Q,K,V weights (hi only)
__device__ f16   g_woh[DM * DM];
__device__ f16   g_w1h[DM * DFF];
__device__ f16   g_w2h[DFF * DM];

// ======================= PTX helpers =======================================
__device__ __forceinline__ uint32_t s2u(const void* p) {
    uint32_t a;
    asm("{ .reg .u64 t; cvta.to.shared.u64 t, %1; cvt.u32.u64 %0, t; }"
        : "=r"(a) : "l"(p));
    return a;
}

#define CP16(dst, src) \
    asm volatile("cp.async.cg.shared.global [%0], [%1], 16;" :: "r"(dst), "l"(src) : "memory")
#define CP_COMMIT() asm volatile("cp.async.commit_group;" ::: "memory")
#define CP_WAIT1()  asm volatile("cp.async.wait_group 1;" ::: "memory")
#define CP_WAIT2()  asm volatile("cp.async.wait_group 2;" ::: "memory")

#define LDSM4(r, a)                                                          \
    asm volatile("ldmatrix.sync.aligned.m8n8.x4.shared.b16 {%0,%1,%2,%3}, [%4];" \
        : "=r"((r)[0]), "=r"((r)[1]), "=r"((r)[2]), "=r"((r)[3]) : "r"(a))

#define LDSM4T(r, a)                                                         \
    asm volatile("ldmatrix.sync.aligned.m8n8.x4.trans.shared.b16 {%0,%1,%2,%3}, [%4];" \
        : "=r"((r)[0]), "=r"((r)[1]), "=r"((r)[2]), "=r"((r)[3]) : "r"(a))

#define MMA16816(c, a, b0, b1)                                               \
    asm volatile("mma.sync.aligned.m16n8k16.row.col.f32.f16.f16.f32 "        \
        "{%0,%1,%2,%3}, {%4,%5,%6,%7}, {%8,%9}, {%0,%1,%2,%3};"              \
        : "+f"((c)[0]), "+f"((c)[1]), "+f"((c)[2]), "+f"((c)[3])             \
        : "r"((a)[0]), "r"((a)[1]), "r"((a)[2]), "r"((a)[3]),                \
          "r"(b0), "r"(b1))

__device__ __forceinline__ uint32_t pack_h2(f16 a, f16 b) {
    __half2 h = __halves2half2(a, b);
    return *reinterpret_cast<uint32_t*>(&h);
}

// ================= LayerNorm fused with fp16 hi/lo split ===================
__global__ void ln_split_kernel(const float* __restrict__ x, const float* __restrict__ w,
                                const float* __restrict__ b, f16* __restrict__ hi,
                                f16* __restrict__ lo, int C) {
    long row = blockIdx.x;
    const float* xr = x + row * (long)C;
    float s = 0.f, ss = 0.f;
    for (int c = threadIdx.x; c < C; c += 256) {
        float v = xr[c];
        s += v; ss += v * v;
    }
    for (int o = 16; o; o >>= 1) {
        s  += __shfl_xor_sync(0xffffffffu, s,  o);
        ss += __shfl_xor_sync(0xffffffffu, ss, o);
    }
    __shared__ float sh[2][8];
    int wi = threadIdx.x >> 5, li = threadIdx.x & 31;
    if (li == 0) { sh[0][wi] = s; sh[1][wi] = ss; }
    __syncthreads();
    if (threadIdx.x < 32) {
        s  = (li < 8) ? sh[0][li] : 0.f;
        ss = (li < 8) ? sh[1][li] : 0.f;
        for (int o = 4; o; o >>= 1) {
            s  += __shfl_xor_sync(0xffffffffu, s,  o);
            ss += __shfl_xor_sync(0xffffffffu, ss, o);
        }
        if (li == 0) { sh[0][0] = s; sh[1][0] = ss; }
    }
    __syncthreads();
    float mean = sh[0][0] / (float)C;
    float var  = sh[1][0] / (float)C - mean * mean;
    float rstd = rsqrtf(var + 1e-5f);
    f16* hr = hi + row * (long)C;
    f16* lr = lo + row * (long)C;
    for (int c = threadIdx.x; c < C; c += 256) {
        float y = (xr[c] - mean) * rstd * w[c] + b[c];
        f16 h = __float2half_rn(y);
        hr[c] = h;
        lr[c] = __float2half_rn(y - __half2float(h));
    }
}

// ======= weight transpose (hi only): W[K,N] -> fp16 [N,K] ==================
__global__ void splitT_kernel(const float* __restrict__ W, f16* __restrict__ hi,
                              int K, int N) {
    __shared__ float t[32][33];
    int k0 = blockIdx.x * 32, n0 = blockIdx.y * 32;
    int tx = threadIdx.x, ty = threadIdx.y;   // 32 x 8
#pragma unroll
    for (int i = 0; i < 4; i++)
        t[ty + 8 * i][tx] = W[(long)(k0 + ty + 8 * i) * N + n0 + tx];
    __syncthreads();
#pragma unroll
    for (int i = 0; i < 4; i++) {
        float v = t[tx][ty + 8 * i];
        hi[(long)(n0 + ty + 8 * i) * K + k0 + tx] = __float2half_rn(v);
    }
}

// ---------------- zero fill ------------------------------------------------
__global__ void zero_kernel(float4* __restrict__ p, long n4) {
    long i = (long)blockIdx.x * blockDim.x + threadIdx.x;
    long stride = (long)gridDim.x * blockDim.x;
    float4 z = make_float4(0.f, 0.f, 0.f, 0.f);
    for (; i < n4; i += stride) p[i] = z;
}

// ================= mma.sync 2x-fp16 GEMM ===================================
// D = (Ahi+Alo)[M,K] x (Bh[Nrows,K])^T + bias   (B fp16 hi only; the Ah*Bl
// correction is dropped — error ~2e-4 RMS, under the 1e-3 gate).
// MODE 0: fp32 out (C, bias0, optional relu).
// MODE 2: fused QKV — B packed [3*DM, K]; block 0 -> Q hi/lo scaled 0.125,
//         block 1 -> K hi, block 2 -> V hi.
#define GSTAGES 4
#define TILE_B   16384                   // one operand tile: 128 rows x 128 B
#define GSTAGE_B (3 * TILE_B)            // Ah, Al, Bh
#define GSMEM    (GSTAGES * GSTAGE_B)    // 196608

template <int MODE>
__global__ void __launch_bounds__(256, 1)
gemm2x_kernel(const f16* __restrict__ Ahi, const f16* __restrict__ Alo,
              const f16* __restrict__ Bh,
              const float* __restrict__ bias0, const float* __restrict__ bias1,
              const float* __restrict__ bias2, float* __restrict__ C,
              f16* __restrict__ h0, f16* __restrict__ l0,
              f16* __restrict__ h1, f16* __restrict__ h2,
              int Kdim, int Ncols, int relu) {
    extern __shared__ char smraw[];
    const uint32_t sb = s2u(smraw);
    const int tid = threadIdx.x;
    const int m0 = blockIdx.y * 128, n0 = blockIdx.x * 128;
    const int nk = Kdim >> 6;                 // chunks of 64 fp16
    const long rowb = (long)Kdim * 2;         // bytes per gmem row

    const char* pAh = (const char*)Ahi + (long)m0 * rowb;
    const char* pAl = (const char*)Alo + (long)m0 * rowb;
    const char* pBh = (const char*)Bh  + (long)n0 * rowb;

    int lrow[4], lkb[4];
    uint32_t ldst[4];
#pragma unroll
    for (int j = 0; j < 4; j++) {
        int u = tid + 256 * j;
        lrow[j] = u >> 3;
        lkb[j]  = (u & 7) * 16;
        ldst[j] = (uint32_t)(lrow[j] * 128 + (lkb[j] ^ ((lrow[j] & 7) * 16)));
    }

#define LOAD_CHUNK(slot, ci) do {                                            \
    uint32_t stg_ = sb + (slot) * GSTAGE_B;                                  \
    long koff_ = (long)(ci) * 128;                                           \
    _Pragma("unroll")                                                        \
    for (int j = 0; j < 4; j++) {                                            \
        long go = (long)lrow[j] * rowb + koff_ + lkb[j];                     \
        CP16(stg_ + ldst[j],              pAh + go);                         \
        CP16(stg_ + TILE_B + ldst[j],     pAl + go);                         \
        CP16(stg_ + 2 * TILE_B + ldst[j], pBh + go);                         \
    }                                                                        \
} while (0)

    const int wid = tid >> 5, l = tid & 31;
    const int wm = wid & 3, wn = wid >> 2;
    const int quad = l >> 3, rim = l & 7;
    const int rimx = rim * 16;
    const int kbq = (quad >> 1) * 16;

    uint32_t aoff[2], boff[4];
#pragma unroll
    for (int mf = 0; mf < 2; mf++)
        aoff[mf] = (uint32_t)((wm * 32 + mf * 16 + (quad & 1) * 8 + rim) * 128);
#pragma unroll
    for (int np = 0; np < 4; np++)
        boff[np] = (uint32_t)((wn * 64 + np * 16 + (quad & 1) * 8 + rim) * 128);

    float acc[2][8][4];
#pragma unroll
    for (int mf = 0; mf < 2; mf++)
#pragma unroll
        for (int nf = 0; nf < 8; nf++)
#pragma unroll
            for (int c = 0; c < 4; c++) acc[mf][nf][c] = 0.f;

#pragma unroll
    for (int s = 0; s < GSTAGES - 1; s++) {
        LOAD_CHUNK(s, s);
        CP_COMMIT();
    }

    int slot = 0;
    for (int i = 0; i < nk; i++) {
        CP_WAIT2();
        __syncthreads();
        int nc = i + GSTAGES - 1;
        if (nc < nk) LOAD_CHUNK((nc & 3), nc);
        CP_COMMIT();

        const uint32_t stg = sb + slot * GSTAGE_B;
        const uint32_t aH = stg, aL = stg + TILE_B, bH = stg + 2 * TILE_B;

#pragma unroll
        for (int ks = 0; ks < 4; ks++) {
            const uint32_t kx = (uint32_t)((ks * 32 + kbq) ^ rimx);
            uint32_t ah[2][4], al[2][4], bh[4][4];
#pragma unroll
            for (int mf = 0; mf < 2; mf++) {
                LDSM4(ah[mf], aH + aoff[mf] + kx);
                LDSM4(al[mf], aL + aoff[mf] + kx);
            }
#pragma unroll
            for (int np = 0; np < 4; np++)
                LDSM4(bh[np], bH + boff[np] + kx);
#pragma unroll
            for (int mf = 0; mf < 2; mf++)
#pragma unroll
                for (int nf = 0; nf < 8; nf++) {
                    int np = nf >> 1, hh = nf & 1;
                    MMA16816(acc[mf][nf], ah[mf], bh[np][hh], bh[np][hh + 2]);
                }
#pragma unroll
            for (int mf = 0; mf < 2; mf++)
#pragma unroll
                for (int nf = 0; nf < 8; nf++) {
                    int np = nf >> 1, hh = nf & 1;
                    MMA16816(acc[mf][nf], al[mf], bh[np][hh], bh[np][hh + 2]);
                }
        }
        __syncthreads();
        slot = (slot + 1) & 3;
    }

    // ---------------- epilogue -----------------------------------------
    const float* bp = bias0;
    f16 *chi = h0, *clo = l0;
    float alpha = 1.f;
    int outb = n0;
    if (MODE == 2) {
        int mat = n0 / DM;
        outb = n0 - mat * DM;
        bp  = (mat == 0) ? bias0 : (mat == 1) ? bias1 : bias2;
        chi = (mat == 0) ? h0 : (mat == 1) ? h1 : h2;
        clo = (mat == 0) ? l0 : nullptr;
        alpha = (mat == 0) ? 0.125f : 1.f;
    }
    const int g = l >> 2, t4 = l & 3;
#pragma unroll
    for (int mf = 0; mf < 2; mf++) {
        int row = m0 + wm * 32 + mf * 16 + g;
#pragma unroll
        for (int nf = 0; nf < 8; nf++) {
            int col = outb + wn * 64 + nf * 8 + 2 * t4;
            float b0v = bp[col], b1v = bp[col + 1];
            float v0 = acc[mf][nf][0] + b0v;
            float v1 = acc[mf][nf][1] + b1v;
            float v2 = acc[mf][nf][2] + b0v;
            float v3 = acc[mf][nf][3] + b1v;
            if (MODE == 0 && relu) {
                v0 = fmaxf(v0, 0.f); v1 = fmaxf(v1, 0.f);
                v2 = fmaxf(v2, 0.f); v3 = fmaxf(v3, 0.f);
            }
            if (MODE == 2) {
                v0 *= alpha; v1 *= alpha; v2 *= alpha; v3 *= alpha;
                f16 c0 = __float2half_rn(v0), c1 = __float2half_rn(v1);
                f16 c2 = __float2half_rn(v2), c3 = __float2half_rn(v3);
                *(uint32_t*)(chi + (long)row * Ncols + col)       = pack_h2(c0, c1);
                *(uint32_t*)(chi + (long)(row + 8) * Ncols + col) = pack_h2(c2, c3);
                if (clo) {
                    f16 r0 = __float2half_rn(v0 - __half2float(c0));
                    f16 r1 = __float2half_rn(v1 - __half2float(c1));
                    f16 r2 = __float2half_rn(v2 - __half2float(c2));
                    f16 r3 = __float2half_rn(v3 - __half2float(c3));
                    *(uint32_t*)(clo + (long)row * Ncols + col)       = pack_h2(r0, r1);
                    *(uint32_t*)(clo + (long)(row + 8) * Ncols + col) = pack_h2(r2, r3);
                }
            } else {
                *(float2*)(C + (long)row * Ncols + col)       = make_float2(v0, v1);
                *(float2*)(C + (long)(row + 8) * Ncols + col) = make_float2(v2, v3);
            }
        }
    }
#undef LOAD_CHUNK
}

// ============== tensor-core dilated flash attention ========================
// CTA = 256 threads / 128 queries. Q hi/lo resident; K/V plain fp16 streamed
// (double-buffered). S = QhKh + QlKh; P split hi/lo; O += PhVh + PlVh.
__constant__ int c_seg[3] = {2048, 4096, 8192};
__constant__ int c_dil[3] = {1, 2, 4};

#define ASM_QH  0
#define ASM_QL  16384
#define ASM_KV  32768
#define ASM_BUF 16384       // per KV buffer: Kh 0-8K, Vh 8K-16K
#define ASMEM   (ASM_KV + 2 * ASM_BUF)   // 65536

__global__ void __launch_bounds__(256, 1)
attn_tc_kernel(const f16* __restrict__ Qh, const f16* __restrict__ Ql,
               const f16* __restrict__ Kh, const f16* __restrict__ Vh,
               float* __restrict__ O) {
    extern __shared__ char smraw[];
    const uint32_t sb = s2u(smraw);

    int z = blockIdx.z;
    int bb = z / 7, t = z % 7;
    int grp, seg;
    if (t < 4)       { grp = 0; seg = t; }
    else if (t < 6)  { grp = 1; seg = t - 4; }
    else             { grp = 2; seg = 0; }
    const int sl = c_seg[grp], rdil = c_dil[grp];
    const int off = grp % rdil;
    const int head = grp * 4 + blockIdx.y;
    const int q0 = blockIdx.x * 128;
    const long segbase = (long)bb * NSEQ + (long)seg * sl;

    const int tid = threadIdx.x;
    // Q loader: 256 threads cover 128 rows x 128 B
    const int qrow_l = tid >> 1;
    const int qkb0 = (tid & 1) * 64;
    uint32_t qdst[4];
#pragma unroll
    for (int j = 0; j < 4; j++) {
        int kb = qkb0 + j * 16;
        qdst[j] = (uint32_t)(qrow_l * 128 + (kb ^ ((qrow_l & 7) * 16)));
    }
    // KV loader: 256 threads cover 64 rows x 128 B per operand
    const int krow_l = tid >> 2;
    const int kkb0 = (tid & 3) * 32;
    uint32_t kdst[2];
#pragma unroll
    for (int j = 0; j < 2; j++) {
        int kb = kkb0 + j * 16;
        kdst[j] = (uint32_t)(krow_l * 128 + (kb ^ ((krow_l & 7) * 16)));
    }

    // ---- load Q tile (hi+lo) ----
    {
        long fo = (segbase + off + (long)(q0 + qrow_l) * rdil) * DM + head * HD;
        const char* gh = (const char*)(Qh + fo);
        const char* gl = (const char*)(Ql + fo);
#pragma unroll
        for (int j = 0; j < 4; j++) {
            CP16(sb + ASM_QH + qdst[j], gh + qkb0 + j * 16);
            CP16(sb + ASM_QL + qdst[j], gl + qkb0 + j * 16);
        }
    }
    CP_COMMIT();

#define LOAD_KV(ti, buf) do {                                                \
    long fo_ = (segbase + off + (long)((ti) * 64 + krow_l) * rdil) * DM + head * HD; \
    uint32_t bs_ = sb + ASM_KV + (buf) * ASM_BUF;                            \
    const char* gkh_ = (const char*)(Kh + fo_);                              \
    const char* gvh_ = (const char*)(Vh + fo_);                              \
    _Pragma("unroll")                                                        \
    for (int j = 0; j < 2; j++) {                                            \
        CP16(bs_ + kdst[j],        gkh_ + kkb0 + j * 16);                    \
        CP16(bs_ + 8192 + kdst[j], gvh_ + kkb0 + j * 16);                    \
    }                                                                        \
} while (0)

    LOAD_KV(0, 0);
    CP_COMMIT();
    CP_WAIT1();          // Q group retired (<=1 pending = KV tile 0)
    __syncthreads();

    // ---- per-warp fragment addressing ----
    const int l = tid & 31, w = tid >> 5;
    const int mi = l >> 3, rr = l & 7;
    const int rbase = (mi & 1) * 8 + rr;    // row within a 16-row block
    const int cxor = rr * 16;               // SW128 xor term
    const int ksel = (mi >> 1) * 16;        // 8-col (16B) selector

    // Q fragments (resident)
    uint32_t qfh[4][4], qfl[4][4];
    {
        uint32_t qrow = (uint32_t)((w * 16 + rbase) * 128);
#pragma unroll
        for (int ks = 0; ks < 4; ks++) {
            uint32_t cb = (uint32_t)((ks * 32 + ksel) ^ cxor);
            LDSM4(qfh[ks], sb + ASM_QH + qrow + cb);
            LDSM4(qfl[ks], sb + ASM_QL + qrow + cb);
        }
    }

    float Oa[8][4];
#pragma unroll
    for (int nf = 0; nf < 8; nf++)
#pragma unroll
        for (int c = 0; c < 4; c++) Oa[nf][c] = 0.f;
    float m0 = -1e30f, m1 = -1e30f, l0 = 0.f, l1 = 0.f;

    for (int kt = 0; kt < 32; kt++) {
        if (kt + 1 < 32) LOAD_KV(kt + 1, (kt + 1) & 1);
        CP_COMMIT();
        CP_WAIT1();
        __syncthreads();

        const uint32_t bs = sb + ASM_KV + (kt & 1) * ASM_BUF;

        // ---- S = Q K^T (2-pass), fp32 acc; 16q x 64kv per warp ----
        float S[8][4];
#pragma unroll
        for (int nf = 0; nf < 8; nf++)
#pragma unroll
            for (int c = 0; c < 4; c++) S[nf][c] = 0.f;

#pragma unroll
        for (int ks = 0; ks < 4; ks++) {
            uint32_t cb = (uint32_t)((ks * 32 + ksel) ^ cxor);
            uint32_t bh[4][4];
#pragma unroll
            for (int np = 0; np < 4; np++) {
                uint32_t ro = (uint32_t)((np * 16 + rbase) * 128);
                LDSM4(bh[np], bs + ro + cb);
            }
#pragma unroll
            for (int nf = 0; nf < 8; nf++) {
                int np = nf >> 1, hh = nf & 1;
                MMA16816(S[nf], qfh[ks], bh[np][hh], bh[np][hh + 2]);
            }
#pragma unroll
            for (int nf = 0; nf < 8; nf++) {
                int np = nf >> 1, hh = nf & 1;
                MMA16816(S[nf], qfl[ks], bh[np][hh], bh[np][hh + 2]);
            }
        }

        // ---- online softmax (rows r=l>>2 and r+8) ----
        float mx0 = -1e30f, mx1 = -1e30f;
#pragma unroll
        for (int nf = 0; nf < 8; nf++) {
            mx0 = fmaxf(mx0, fmaxf(S[nf][0], S[nf][1]));
            mx1 = fmaxf(mx1, fmaxf(S[nf][2], S[nf][3]));
        }
        mx0 = fmaxf(mx0, __shfl_xor_sync(0xffffffffu, mx0, 1));
        mx0 = fmaxf(mx0, __shfl_xor_sync(0xffffffffu, mx0, 2));
        mx1 = fmaxf(mx1, __shfl_xor_sync(0xffffffffu, mx1, 1));
        mx1 = fmaxf(mx1, __shfl_xor_sync(0xffffffffu, mx1, 2));
        float nm0 = fmaxf(m0, mx0), nm1 = fmaxf(m1, mx1);
        float fac0 = __expf(m0 - nm0), fac1 = __expf(m1 - nm1);
        m0 = nm0; m1 = nm1;
        float rs0 = 0.f, rs1 = 0.f;
#pragma unroll
        for (int nf = 0; nf < 8; nf++) {
            S[nf][0] = __expf(S[nf][0] - nm0); rs0 += S[nf][0];
            S[nf][1] = __expf(S[nf][1] - nm0); rs0 += S[nf][1];
            S[nf][2] = __expf(S[nf][2] - nm1); rs1 += S[nf][2];
            S[nf][3] = __expf(S[nf][3] - nm1); rs1 += S[nf][3];
        }
        rs0 += __shfl_xor_sync(0xffffffffu, rs0, 1);
        rs0 += __shfl_xor_sync(0xffffffffu, rs0, 2);
        rs1 += __shfl_xor_sync(0xffffffffu, rs1, 1);
        rs1 += __shfl_xor_sync(0xffffffffu, rs1, 2);
        l0 = l0 * fac0 + rs0;
        l1 = l1 * fac1 + rs1;
#pragma unroll
        for (int nf = 0; nf < 8; nf++) {
            Oa[nf][0] *= fac0; Oa[nf][1] *= fac0;
            Oa[nf][2] *= fac1; Oa[nf][3] *= fac1;
        }

        // ---- O += P V (2-pass: Ph, Pl); P frags from S regs ----
#pragma unroll
        for (int j = 0; j < 4; j++) {
            uint32_t pah[4], pal[4];
            {
                const float* s0 = S[2 * j];
                const float* s1 = S[2 * j + 1];
                f16 h00 = __float2half_rn(s0[0]), h01 = __float2half_rn(s0[1]);
                f16 h02 = __float2half_rn(s0[2]), h03 = __float2half_rn(s0[3]);
                f16 h10 = __float2half_rn(s1[0]), h11 = __float2half_rn(s1[1]);
                f16 h12 = __float2half_rn(s1[2]), h13 = __float2half_rn(s1[3]);
                pah[0] = pack_h2(h00, h01);
                pah[1] = pack_h2(h02, h03);
                pah[2] = pack_h2(h10, h11);
                pah[3] = pack_h2(h12, h13);
                pal[0] = pack_h2(__float2half_rn(s0[0] - __half2float(h00)),
                                 __float2half_rn(s0[1] - __half2float(h01)));
                pal[1] = pack_h2(__float2half_rn(s0[2] - __half2float(h02)),
                                 __float2half_rn(s0[3] - __half2float(h03)));
                pal[2] = pack_h2(__float2half_rn(s1[0] - __half2float(h10)),
                                 __float2half_rn(s1[1] - __half2float(h11)));
                pal[3] = pack_h2(__float2half_rn(s1[2] - __half2float(h12)),
                                 __float2half_rn(s1[3] - __half2float(h13)));
            }
            uint32_t vh[4][4];
#pragma unroll
            for (int np = 0; np < 4; np++) {
                uint32_t ro = (uint32_t)((j * 16 + rbase) * 128);
                uint32_t cb = (uint32_t)((np * 32 + ksel) ^ cxor);
                LDSM4T(vh[np], bs + 8192 + ro + cb);
            }
#pragma unroll
            for (int nf = 0; nf < 8; nf++) {
                int np = nf >> 1, hh = nf & 1;
                MMA16816(Oa[nf], pah, vh[np][hh * 2], vh[np][hh * 2 + 1]);
            }
#pragma unroll
            for (int nf = 0; nf < 8; nf++) {
                int np = nf >> 1, hh = nf & 1;
                MMA16816(Oa[nf], pal, vh[np][hh * 2], vh[np][hh * 2 + 1]);
            }
        }
        __syncthreads();
    }

    // ---- epilogue ----
    float inv0 = 1.f / l0, inv1 = 1.f / l1;
    int r0 = q0 + w * 16 + (l >> 2);
    long n0tok = segbase + off + (long)r0 * rdil;
    long n1tok = segbase + off + (long)(r0 + 8) * rdil;
    float* o0 = O + n0tok * DM + head * HD;
    float* o1 = O + n1tok * DM + head * HD;
    int cbase = (l & 3) * 2;
#pragma unroll
    for (int nf = 0; nf < 8; nf++) {
        int col = nf * 8 + cbase;
        *(float2*)(o0 + col) = make_float2(Oa[nf][0] * inv0, Oa[nf][1] * inv0);
        *(float2*)(o1 + col) = make_float2(Oa[nf][2] * inv1, Oa[nf][3] * inv1);
    }
#undef LOAD_KV
}

// ---------------- host orchestration ---------------------------------------
extern "C" void kernel_launch(void* const* d_in, const int* in_sizes, int n_in,
                              void* d_out, int out_size) {
    const float* src  = (const float*)d_in[0];
    const float* ln1w = (const float*)d_in[1];
    const float* ln1b = (const float*)d_in[2];
    const float* Wq   = (const float*)d_in[3];
    const float* bq   = (const float*)d_in[4];
    const float* Wk   = (const float*)d_in[5];
    const float* bk   = (const float*)d_in[6];
    const float* Wv   = (const float*)d_in[7];
    const float* bv   = (const float*)d_in[8];
    const float* lnAw = (const float*)d_in[9];
    const float* lnAb = (const float*)d_in[10];
    const float* Wo   = (const float*)d_in[11];
    const float* bo   = (const float*)d_in[12];
    const float* ln2w = (const float*)d_in[13];
    const float* ln2b = (const float*)d_in[14];
    const float* W1   = (const float*)d_in[15];
    const float* b1   = (const float*)d_in[16];
    const float* ln3w = (const float*)d_in[17];
    const float* ln3b = (const float*)d_in[18];
    const float* W2   = (const float*)d_in[19];
    const float* b2   = (const float*)d_in[20];
    float* out = (float*)d_out;

    float *px, *patt, *pf1;
    f16 *ahi, *alo, *qh, *ql, *kh, *vh;
    f16 *wqkvh, *woh, *w1h, *w2h;
    cudaGetSymbolAddress((void**)&px,    g_x);
    cudaGetSymbolAddress((void**)&patt,  g_att);
    cudaGetSymbolAddress((void**)&pf1,   g_f1);
    cudaGetSymbolAddress((void**)&ahi,   g_ahi);
    cudaGetSymbolAddress((void**)&alo,   g_alo);
    cudaGetSymbolAddress((void**)&qh,    g_qh);
    cudaGetSymbolAddress((void**)&ql,    g_ql);
    cudaGetSymbolAddress((void**)&kh,    g_kh);
    cudaGetSymbolAddress((void**)&vh,    g_vh);
    cudaGetSymbolAddress((void**)&wqkvh, g_wqkvh);
    cudaGetSymbolAddress((void**)&woh,   g_woh);
    cudaGetSymbolAddress((void**)&w1h,   g_w1h);
    cudaGetSymbolAddress((void**)&w2h,   g_w2h);

    static bool attr_done = false;
    if (!attr_done) {
        cudaFuncSetAttribute(gemm2x_kernel<0>, cudaFuncAttributeMaxDynamicSharedMemorySize, GSMEM);
        cudaFuncSetAttribute(gemm2x_kernel<2>, cudaFuncAttributeMaxDynamicSharedMemorySize, GSMEM);
        cudaFuncSetAttribute(attn_tc_kernel, cudaFuncAttributeMaxDynamicSharedMemorySize, ASMEM);
        attr_done = true;
    }

    dim3 tT(32, 8);
    dim3 gW(DM / 32, DM / 32);
    dim3 gW1(DM / 32, DFF / 32);
    dim3 gW2(DFF / 32, DM / 32);
    dim3 gq(DM / 128, NTOK / 128);        // (6,128)
    dim3 gqkv(3 * DM / 128, NTOK / 128);  // (18,128)
    dim3 g1(DFF / 128, NTOK / 128);       // (24,128)

    // weight transpose (hi only; QKV packed along N)
    splitT_kernel<<<gW,  tT>>>(Wq, wqkvh,               DM, DM);
    splitT_kernel<<<gW,  tT>>>(Wk, wqkvh + DM * DM,     DM, DM);
    splitT_kernel<<<gW,  tT>>>(Wv, wqkvh + 2 * DM * DM, DM, DM);
    splitT_kernel<<<gW,  tT>>>(Wo, woh, DM, DM);
    splitT_kernel<<<gW1, tT>>>(W1, w1h, DM, DFF);
    splitT_kernel<<<gW2, tT>>>(W2, w2h, DFF, DM);

    // LN1 -> split, fused QKV projection (Q hi/lo pre-scaled 0.125; K,V hi)
    ln_split_kernel<<<NTOK, 256>>>(src, ln1w, ln1b, ahi, alo, DM);
    gemm2x_kernel<2><<<gqkv, 256, GSMEM>>>(ahi, alo, wqkvh,
                                           bq, bk, bv, nullptr,
                                           qh, ql, kh, vh, DM, DM, 0);

    // attention: zero + tensor-core dilated flash attention (128-q tiles)
    zero_kernel<<<4096, 256>>>((float4*)patt, (long)NTOK * DM / 4);
    attn_tc_kernel<<<dim3(16, 4, 14), 256, ASMEM>>>(qh, ql, kh, vh, patt);

    // MAGNETO sub-LN -> split, out projection
    ln_split_kernel<<<NTOK, 256>>>(patt, lnAw, lnAb, ahi, alo, DM);
    gemm2x_kernel<0><<<gq, 256, GSMEM>>>(ahi, alo, woh,
                                         bo, nullptr, nullptr, px,
                                         nullptr, nullptr, nullptr, nullptr,
                                         DM, DM, 0);

    // LN2 -> split, FF1 (relu)
    ln_split_kernel<<<NTOK, 256>>>(px, ln2w, ln2b, ahi, alo, DM);
    gemm2x_kernel<0><<<g1, 256, GSMEM>>>(ahi, alo, w1h,
                                         b1, nullptr, nullptr, pf1,
                                         nullptr, nullptr, nullptr, nullptr,
                                         DM, DFF, 1);

    // LN3 -> split, FF2
    ln_split_kernel<<<NTOK, 256>>>(pf1, ln3w, ln3b, ahi, alo, DFF);
    gemm2x_kernel<0><<<gq, 256, GSMEM>>>(ahi, alo, w2h,
                                         b2, nullptr, nullptr, out,
                                         nullptr, nullptr, nullptr, nullptr,
                                         DFF, DM, 0);
}

// round 12
// speedup vs baseline: 3.7243x; 1.0316x over previous
#include <cuda_runtime.h>
#include <cuda_fp16.h>
#include <cstdint>

#define NTOK 16384          // B*N = 2*8192
#define NSEQ 8192
#define DM   768
#define DFF  3072
#define NH   12
#define HD   64

typedef __half f16;

// ---------------- scratch (device globals; no allocation allowed) ----------
__device__ float g_x  [NTOK * DM];     // Wo output
__device__ float g_att[NTOK * DM];     // attention output (fp32)
__device__ float g_f1 [NTOK * DFF];
__device__ f16   g_ahi[NTOK * DFF];
__device__ f16   g_alo[NTOK * DFF];
__device__ f16   g_qh [NTOK * DM], g_ql[NTOK * DM];
__device__ f16   g_kh [NTOK * DM];
__device__ f16   g_vh [NTOK * DM];
__device__ f16   g_wqkvh[3 * DM * DM];     // packed Q,K,V weights (hi only)
__device__ f16   g_woh[DM * DM];
__device__ f16   g_w1h[DM * DFF];
__device__ f16   g_w2h[DFF * DM];

// ======================= PTX helpers =======================================
__device__ __forceinline__ uint32_t s2u(const void* p) {
    uint32_t a;
    asm("{ .reg .u64 t; cvta.to.shared.u64 t, %1; cvt.u32.u64 %0, t; }"
        : "=r"(a) : "l"(p));
    return a;
}

#define CP16(dst, src) \
    asm volatile("cp.async.cg.shared.global [%0], [%1], 16;" :: "r"(dst), "l"(src) : "memory")
#define CP_COMMIT() asm volatile("cp.async.commit_group;" ::: "memory")
#define CP_WAIT1()  asm volatile("cp.async.wait_group 1;" ::: "memory")
#define CP_WAIT2()  asm volatile("cp.async.wait_group 2;" ::: "memory")

#define LDSM4(r, a)                                                          \
    asm volatile("ldmatrix.sync.aligned.m8n8.x4.shared.b16 {%0,%1,%2,%3}, [%4];" \
        : "=r"((r)[0]), "=r"((r)[1]), "=r"((r)[2]), "=r"((r)[3]) : "r"(a))

#define LDSM4T(r, a)                                                         \
    asm volatile("ldmatrix.sync.aligned.m8n8.x4.trans.shared.b16 {%0,%1,%2,%3}, [%4];" \
        : "=r"((r)[0]), "=r"((r)[1]), "=r"((r)[2]), "=r"((r)[3]) : "r"(a))

#define MMA16816(c, a, b0, b1)                                               \
    asm volatile("mma.sync.aligned.m16n8k16.row.col.f32.f16.f16.f32 "        \
        "{%0,%1,%2,%3}, {%4,%5,%6,%7}, {%8,%9}, {%0,%1,%2,%3};"              \
        : "+f"((c)[0]), "+f"((c)[1]), "+f"((c)[2]), "+f"((c)[3])             \
        : "r"((a)[0]), "r"((a)[1]), "r"((a)[2]), "r"((a)[3]),                \
          "r"(b0), "r"(b1))

__device__ __forceinline__ uint32_t pack_h2(f16 a, f16 b) {
    __half2 h = __halves2half2(a, b);
    return *reinterpret_cast<uint32_t*>(&h);
}

// ========== LayerNorm fused with fp16 hi/lo split (vectorized) =============
// float4 loads cached in registers (single gmem pass), packed half2 stores.
// C is 768 or 3072 -> at most 3 float4 per thread at 256 threads.
__global__ void ln_split_kernel(const float* __restrict__ x, const float* __restrict__ w,
                                const float* __restrict__ b, f16* __restrict__ hi,
                                f16* __restrict__ lo, int C) {
    long row = blockIdx.x;
    const float4* xr = (const float4*)(x + row * (long)C);
    const int n4 = C >> 2;
    float4 v[3];
    float s = 0.f, ss = 0.f;
    int cnt = 0;
#pragma unroll 3
    for (int c4 = threadIdx.x; c4 < n4; c4 += 256, cnt++) {
        float4 a = xr[c4];
        v[cnt] = a;
        s  += a.x + a.y + a.z + a.w;
        ss += a.x * a.x + a.y * a.y + a.z * a.z + a.w * a.w;
    }
    for (int o = 16; o; o >>= 1) {
        s  += __shfl_xor_sync(0xffffffffu, s,  o);
        ss += __shfl_xor_sync(0xffffffffu, ss, o);
    }
    __shared__ float sh[2][8];
    int wi = threadIdx.x >> 5, li = threadIdx.x & 31;
    if (li == 0) { sh[0][wi] = s; sh[1][wi] = ss; }
    __syncthreads();
    if (threadIdx.x < 32) {
        s  = (li < 8) ? sh[0][li] : 0.f;
        ss = (li < 8) ? sh[1][li] : 0.f;
        for (int o = 4; o; o >>= 1) {
            s  += __shfl_xor_sync(0xffffffffu, s,  o);
            ss += __shfl_xor_sync(0xffffffffu, ss, o);
        }
        if (li == 0) { sh[0][0] = s; sh[1][0] = ss; }
    }
    __syncthreads();
    float mean = sh[0][0] / (float)C;
    float var  = sh[1][0] / (float)C - mean * mean;
    float rstd = rsqrtf(var + 1e-5f);
    uint2* hr = (uint2*)(hi + row * (long)C);
    uint2* lr = (uint2*)(lo + row * (long)C);
    const float4* w4 = (const float4*)w;
    const float4* b4 = (const float4*)b;
    cnt = 0;
#pragma unroll 3
    for (int c4 = threadIdx.x; c4 < n4; c4 += 256, cnt++) {
        float4 a = v[cnt];
        float4 ww = w4[c4], bb = b4[c4];
        float y0 = (a.x - mean) * rstd * ww.x + bb.x;
        float y1 = (a.y - mean) * rstd * ww.y + bb.y;
        float y2 = (a.z - mean) * rstd * ww.z + bb.z;
        float y3 = (a.w - mean) * rstd * ww.w + bb.w;
        f16 h0 = __float2half_rn(y0), h1 = __float2half_rn(y1);
        f16 h2 = __float2half_rn(y2), h3 = __float2half_rn(y3);
        uint2 hv, lv;
        hv.x = pack_h2(h0, h1); hv.y = pack_h2(h2, h3);
        lv.x = pack_h2(__float2half_rn(y0 - __half2float(h0)),
                       __float2half_rn(y1 - __half2float(h1)));
        lv.y = pack_h2(__float2half_rn(y2 - __half2float(h2)),
                       __float2half_rn(y3 - __half2float(h3)));
        hr[c4] = hv;
        lr[c4] = lv;
    }
}

// ======= weight transpose (hi only): W[K,N] -> fp16 [N,K] ==================
__global__ void splitT_kernel(const float* __restrict__ W, f16* __restrict__ hi,
                              int K, int N) {
    __shared__ float t[32][33];
    int k0 = blockIdx.x * 32, n0 = blockIdx.y * 32;
    int tx = threadIdx.x, ty = threadIdx.y;   // 32 x 8
#pragma unroll
    for (int i = 0; i < 4; i++)
        t[ty + 8 * i][tx] = W[(long)(k0 + ty + 8 * i) * N + n0 + tx];
    __syncthreads();
#pragma unroll
    for (int i = 0; i < 4; i++) {
        float v = t[tx][ty + 8 * i];
        hi[(long)(n0 + ty + 8 * i) * K + k0 + tx] = __float2half_rn(v);
    }
}

// ---------------- zero fill ------------------------------------------------
__global__ void zero_kernel(float4* __restrict__ p, long n4) {
    long i = (long)blockIdx.x * blockDim.x + threadIdx.x;
    long stride = (long)gridDim.x * blockDim.x;
    float4 z = make_float4(0.f, 0.f, 0.f, 0.f);
    for (; i < n4; i += stride) p[i] = z;
}

// ================= mma.sync 2x-fp16 GEMM ===================================
// D = (Ahi+Alo)[M,K] x (Bh[Nrows,K])^T + bias   (B fp16 hi only).
// MODE 0: fp32 out. MODE 2: fused QKV (Q hi/lo scaled 0.125; K,V hi).
#define GSTAGES 4
#define TILE_B   16384                   // one operand tile: 128 rows x 128 B
#define GSTAGE_B (3 * TILE_B)            // Ah, Al, Bh
#define GSMEM    (GSTAGES * GSTAGE_B)    // 196608

template <int MODE>
__global__ void __launch_bounds__(256, 1)
gemm2x_kernel(const f16* __restrict__ Ahi, const f16* __restrict__ Alo,
              const f16* __restrict__ Bh,
              const float* __restrict__ bias0, const float* __restrict__ bias1,
              const float* __restrict__ bias2, float* __restrict__ C,
              f16* __restrict__ h0, f16* __restrict__ l0,
              f16* __restrict__ h1, f16* __restrict__ h2,
              int Kdim, int Ncols, int relu) {
    extern __shared__ char smraw[];
    const uint32_t sb = s2u(smraw);
    const int tid = threadIdx.x;
    const int m0 = blockIdx.y * 128, n0 = blockIdx.x * 128;
    const int nk = Kdim >> 6;                 // chunks of 64 fp16
    const long rowb = (long)Kdim * 2;         // bytes per gmem row

    const char* pAh = (const char*)Ahi + (long)m0 * rowb;
    const char* pAl = (const char*)Alo + (long)m0 * rowb;
    const char* pBh = (const char*)Bh  + (long)n0 * rowb;

    int lrow[4], lkb[4];
    uint32_t ldst[4];
#pragma unroll
    for (int j = 0; j < 4; j++) {
        int u = tid + 256 * j;
        lrow[j] = u >> 3;
        lkb[j]  = (u & 7) * 16;
        ldst[j] = (uint32_t)(lrow[j] * 128 + (lkb[j] ^ ((lrow[j] & 7) * 16)));
    }

#define LOAD_CHUNK(slot, ci) do {                                            \
    uint32_t stg_ = sb + (slot) * GSTAGE_B;                                  \
    long koff_ = (long)(ci) * 128;                                           \
    _Pragma("unroll")                                                        \
    for (int j = 0; j < 4; j++) {                                            \
        long go = (long)lrow[j] * rowb + koff_ + lkb[j];                     \
        CP16(stg_ + ldst[j],              pAh + go);                         \
        CP16(stg_ + TILE_B + ldst[j],     pAl + go);                         \
        CP16(stg_ + 2 * TILE_B + ldst[j], pBh + go);                         \
    }                                                                        \
} while (0)

    const int wid = tid >> 5, l = tid & 31;
    const int wm = wid & 3, wn = wid >> 2;
    const int quad = l >> 3, rim = l & 7;
    const int rimx = rim * 16;
    const int kbq = (quad >> 1) * 16;

    uint32_t aoff[2], boff[4];
#pragma unroll
    for (int mf = 0; mf < 2; mf++)
        aoff[mf] = (uint32_t)((wm * 32 + mf * 16 + (quad & 1) * 8 + rim) * 128);
#pragma unroll
    for (int np = 0; np < 4; np++)
        boff[np] = (uint32_t)((wn * 64 + np * 16 + (quad & 1) * 8 + rim) * 128);

    float acc[2][8][4];
#pragma unroll
    for (int mf = 0; mf < 2; mf++)
#pragma unroll
        for (int nf = 0; nf < 8; nf++)
#pragma unroll
            for (int c = 0; c < 4; c++) acc[mf][nf][c] = 0.f;

#pragma unroll
    for (int s = 0; s < GSTAGES - 1; s++) {
        LOAD_CHUNK(s, s);
        CP_COMMIT();
    }

    int slot = 0;
    for (int i = 0; i < nk; i++) {
        CP_WAIT2();
        __syncthreads();
        int nc = i + GSTAGES - 1;
        if (nc < nk) LOAD_CHUNK((nc & 3), nc);
        CP_COMMIT();

        const uint32_t stg = sb + slot * GSTAGE_B;
        const uint32_t aH = stg, aL = stg + TILE_B, bH = stg + 2 * TILE_B;

#pragma unroll
        for (int ks = 0; ks < 4; ks++) {
            const uint32_t kx = (uint32_t)((ks * 32 + kbq) ^ rimx);
            uint32_t ah[2][4], al[2][4], bh[4][4];
#pragma unroll
            for (int mf = 0; mf < 2; mf++) {
                LDSM4(ah[mf], aH + aoff[mf] + kx);
                LDSM4(al[mf], aL + aoff[mf] + kx);
            }
#pragma unroll
            for (int np = 0; np < 4; np++)
                LDSM4(bh[np], bH + boff[np] + kx);
#pragma unroll
            for (int mf = 0; mf < 2; mf++)
#pragma unroll
                for (int nf = 0; nf < 8; nf++) {
                    int np = nf >> 1, hh = nf & 1;
                    MMA16816(acc[mf][nf], ah[mf], bh[np][hh], bh[np][hh + 2]);
                }
#pragma unroll
            for (int mf = 0; mf < 2; mf++)
#pragma unroll
                for (int nf = 0; nf < 8; nf++) {
                    int np = nf >> 1, hh = nf & 1;
                    MMA16816(acc[mf][nf], al[mf], bh[np][hh], bh[np][hh + 2]);
                }
        }
        __syncthreads();
        slot = (slot + 1) & 3;
    }

    // ---------------- epilogue -----------------------------------------
    const float* bp = bias0;
    f16 *chi = h0, *clo = l0;
    float alpha = 1.f;
    int outb = n0;
    if (MODE == 2) {
        int mat = n0 / DM;
        outb = n0 - mat * DM;
        bp  = (mat == 0) ? bias0 : (mat == 1) ? bias1 : bias2;
        chi = (mat == 0) ? h0 : (mat == 1) ? h1 : h2;
        clo = (mat == 0) ? l0 : nullptr;
        alpha = (mat == 0) ? 0.125f : 1.f;
    }
    const int g = l >> 2, t4 = l & 3;
#pragma unroll
    for (int mf = 0; mf < 2; mf++) {
        int row = m0 + wm * 32 + mf * 16 + g;
#pragma unroll
        for (int nf = 0; nf < 8; nf++) {
            int col = outb + wn * 64 + nf * 8 + 2 * t4;
            float b0v = bp[col], b1v = bp[col + 1];
            float v0 = acc[mf][nf][0] + b0v;
            float v1 = acc[mf][nf][1] + b1v;
            float v2 = acc[mf][nf][2] + b0v;
            float v3 = acc[mf][nf][3] + b1v;
            if (MODE == 0 && relu) {
                v0 = fmaxf(v0, 0.f); v1 = fmaxf(v1, 0.f);
                v2 = fmaxf(v2, 0.f); v3 = fmaxf(v3, 0.f);
            }
            if (MODE == 2) {
                v0 *= alpha; v1 *= alpha; v2 *= alpha; v3 *= alpha;
                f16 c0 = __float2half_rn(v0), c1 = __float2half_rn(v1);
                f16 c2 = __float2half_rn(v2), c3 = __float2half_rn(v3);
                *(uint32_t*)(chi + (long)row * Ncols + col)       = pack_h2(c0, c1);
                *(uint32_t*)(chi + (long)(row + 8) * Ncols + col) = pack_h2(c2, c3);
                if (clo) {
                    f16 r0 = __float2half_rn(v0 - __half2float(c0));
                    f16 r1 = __float2half_rn(v1 - __half2float(c1));
                    f16 r2 = __float2half_rn(v2 - __half2float(c2));
                    f16 r3 = __float2half_rn(v3 - __half2float(c3));
                    *(uint32_t*)(clo + (long)row * Ncols + col)       = pack_h2(r0, r1);
                    *(uint32_t*)(clo + (long)(row + 8) * Ncols + col) = pack_h2(r2, r3);
                }
            } else {
                *(float2*)(C + (long)row * Ncols + col)       = make_float2(v0, v1);
                *(float2*)(C + (long)(row + 8) * Ncols + col) = make_float2(v2, v3);
            }
        }
    }
#undef LOAD_CHUNK
}

// ============== tensor-core dilated flash attention ========================
// CTA = 256 threads / 128 queries; 2 CTAs/SM (softmax of one CTA hides behind
// the other's MMA). Q hi resident in regs, Q lo re-read from smem per tile.
// K/V plain fp16 streamed (double-buffered).
__constant__ int c_seg[3] = {2048, 4096, 8192};
__constant__ int c_dil[3] = {1, 2, 4};
#define LOG2E 1.4426950408889634f

#define ASM_QH  0
#define ASM_QL  16384
#define ASM_KV  32768
#define ASM_BUF 16384       // per KV buffer: Kh 0-8K, Vh 8K-16K
#define ASMEM   (ASM_KV + 2 * ASM_BUF)   // 65536

__global__ void __launch_bounds__(256, 2)
attn_tc_kernel(const f16* __restrict__ Qh, const f16* __restrict__ Ql,
               const f16* __restrict__ Kh, const f16* __restrict__ Vh,
               float* __restrict__ O) {
    extern __shared__ char smraw[];
    const uint32_t sb = s2u(smraw);

    int z = blockIdx.z;
    int bb = z / 7, t = z % 7;
    int grp, seg;
    if (t < 4)       { grp = 0; seg = t; }
    else if (t < 6)  { grp = 1; seg = t - 4; }
    else             { grp = 2; seg = 0; }
    const int sl = c_seg[grp], rdil = c_dil[grp];
    const int off = grp % rdil;
    const int head = grp * 4 + blockIdx.y;
    const int q0 = blockIdx.x * 128;
    const long segbase = (long)bb * NSEQ + (long)seg * sl;

    const int tid = threadIdx.x;
    // Q loader: 256 threads cover 128 rows x 128 B
    const int qrow_l = tid >> 1;
    const int qkb0 = (tid & 1) * 64;
    uint32_t qdst[4];
#pragma unroll
    for (int j = 0; j < 4; j++) {
        int kb = qkb0 + j * 16;
        qdst[j] = (uint32_t)(qrow_l * 128 + (kb ^ ((qrow_l & 7) * 16)));
    }
    // KV loader: 256 threads cover 64 rows x 128 B per operand
    const int krow_l = tid >> 2;
    const int kkb0 = (tid & 3) * 32;
    uint32_t kdst[2];
#pragma unroll
    for (int j = 0; j < 2; j++) {
        int kb = kkb0 + j * 16;
        kdst[j] = (uint32_t)(krow_l * 128 + (kb ^ ((krow_l & 7) * 16)));
    }

    // ---- load Q tile (hi+lo) ----
    {
        long fo = (segbase + off + (long)(q0 + qrow_l) * rdil) * DM + head * HD;
        const char* gh = (const char*)(Qh + fo);
        const char* gl = (const char*)(Ql + fo);
#pragma unroll
        for (int j = 0; j < 4; j++) {
            CP16(sb + ASM_QH + qdst[j], gh + qkb0 + j * 16);
            CP16(sb + ASM_QL + qdst[j], gl + qkb0 + j * 16);
        }
    }
    CP_COMMIT();

#define LOAD_KV(ti, buf) do {                                                \
    long fo_ = (segbase + off + (long)((ti) * 64 + krow_l) * rdil) * DM + head * HD; \
    uint32_t bs_ = sb + ASM_KV + (buf) * ASM_BUF;                            \
    const char* gkh_ = (const char*)(Kh + fo_);                              \
    const char* gvh_ = (const char*)(Vh + fo_);                              \
    _Pragma("unroll")                                                        \
    for (int j = 0; j < 2; j++) {                                            \
        CP16(bs_ + kdst[j],        gkh_ + kkb0 + j * 16);                    \
        CP16(bs_ + 8192 + kdst[j], gvh_ + kkb0 + j * 16);                    \
    }                                                                        \
} while (0)

    LOAD_KV(0, 0);
    CP_COMMIT();
    CP_WAIT1();          // Q group retired (<=1 pending = KV tile 0)
    __syncthreads();

    // ---- per-warp fragment addressing ----
    const int l = tid & 31, w = tid >> 5;
    const int mi = l >> 3, rr = l & 7;
    const int rbase = (mi & 1) * 8 + rr;    // row within a 16-row block
    const int cxor = rr * 16;               // SW128 xor term
    const int ksel = (mi >> 1) * 16;        // 8-col (16B) selector
    const uint32_t qrow = (uint32_t)((w * 16 + rbase) * 128);

    // Q hi fragments resident; Q lo re-read per tile (keeps regs <= 128)
    uint32_t qfh[4][4];
#pragma unroll
    for (int ks = 0; ks < 4; ks++) {
        uint32_t cb = (uint32_t)((ks * 32 + ksel) ^ cxor);
        LDSM4(qfh[ks], sb + ASM_QH + qrow + cb);
    }

    float Oa[8][4];
#pragma unroll
    for (int nf = 0; nf < 8; nf++)
#pragma unroll
        for (int c = 0; c < 4; c++) Oa[nf][c] = 0.f;
    float m0 = -1e30f, m1 = -1e30f, l0 = 0.f, l1 = 0.f;

    for (int kt = 0; kt < 32; kt++) {
        if (kt + 1 < 32) LOAD_KV(kt + 1, (kt + 1) & 1);
        CP_COMMIT();
        CP_WAIT1();
        __syncthreads();

        const uint32_t bs = sb + ASM_KV + (kt & 1) * ASM_BUF;

        // ---- S = Q K^T (2-pass), fp32 acc; 16q x 64kv per warp ----
        float S[8][4];
#pragma unroll
        for (int nf = 0; nf < 8; nf++)
#pragma unroll
            for (int c = 0; c < 4; c++) S[nf][c] = 0.f;

#pragma unroll
        for (int ks = 0; ks < 4; ks++) {
            uint32_t cb = (uint32_t)((ks * 32 + ksel) ^ cxor);
            uint32_t bh[4][4], qfl[4];
            LDSM4(qfl, sb + ASM_QL + qrow + cb);
#pragma unroll
            for (int np = 0; np < 4; np++) {
                uint32_t ro = (uint32_t)((np * 16 + rbase) * 128);
                LDSM4(bh[np], bs + ro + cb);
            }
#pragma unroll
            for (int nf = 0; nf < 8; nf++) {
                int np = nf >> 1, hh = nf & 1;
                MMA16816(S[nf], qfh[ks], bh[np][hh], bh[np][hh + 2]);
            }
#pragma unroll
            for (int nf = 0; nf < 8; nf++) {
                int np = nf >> 1, hh = nf & 1;
                MMA16816(S[nf], qfl, bh[np][hh], bh[np][hh + 2]);
            }
        }

        // ---- online softmax in base-2 (rows r=l>>2 and r+8) ----
        float mx0 = -1e30f, mx1 = -1e30f;
#pragma unroll
        for (int nf = 0; nf < 8; nf++) {
            mx0 = fmaxf(mx0, fmaxf(S[nf][0], S[nf][1]));
            mx1 = fmaxf(mx1, fmaxf(S[nf][2], S[nf][3]));
        }
        mx0 = fmaxf(mx0, __shfl_xor_sync(0xffffffffu, mx0, 1));
        mx0 = fmaxf(mx0, __shfl_xor_sync(0xffffffffu, mx0, 2));
        mx1 = fmaxf(mx1, __shfl_xor_sync(0xffffffffu, mx1, 1));
        mx1 = fmaxf(mx1, __shfl_xor_sync(0xffffffffu, mx1, 2));
        float nm0 = fmaxf(m0, mx0), nm1 = fmaxf(m1, mx1);
        float fac0 = exp2f((m0 - nm0) * LOG2E), fac1 = exp2f((m1 - nm1) * LOG2E);
        m0 = nm0; m1 = nm1;
        float c0 = nm0 * LOG2E, c1 = nm1 * LOG2E;
        float rs0 = 0.f, rs1 = 0.f;
#pragma unroll
        for (int nf = 0; nf < 8; nf++) {
            S[nf][0] = exp2f(S[nf][0] * LOG2E - c0); rs0 += S[nf][0];
            S[nf][1] = exp2f(S[nf][1] * LOG2E - c0); rs0 += S[nf][1];
            S[nf][2] = exp2f(S[nf][2] * LOG2E - c1); rs1 += S[nf][2];
            S[nf][3] = exp2f(S[nf][3] * LOG2E - c1); rs1 += S[nf][3];
        }
        rs0 += __shfl_xor_sync(0xffffffffu, rs0, 1);
        rs0 += __shfl_xor_sync(0xffffffffu, rs0, 2);
        rs1 += __shfl_xor_sync(0xffffffffu, rs1, 1);
        rs1 += __shfl_xor_sync(0xffffffffu, rs1, 2);
        l0 = l0 * fac0 + rs0;
        l1 = l1 * fac1 + rs1;
#pragma unroll
        for (int nf = 0; nf < 8; nf++) {
            Oa[nf][0] *= fac0; Oa[nf][1] *= fac0;
            Oa[nf][2] *= fac1; Oa[nf][3] *= fac1;
        }

        // ---- O += P V (2-pass: Ph, Pl); P frags from S regs ----
#pragma unroll
        for (int j = 0; j < 4; j++) {
            uint32_t pah[4], pal[4];
            {
                const float* s0 = S[2 * j];
                const float* s1 = S[2 * j + 1];
                f16 h00 = __float2half_rn(s0[0]), h01 = __float2half_rn(s0[1]);
                f16 h02 = __float2half_rn(s0[2]), h03 = __float2half_rn(s0[3]);
                f16 h10 = __float2half_rn(s1[0]), h11 = __float2half_rn(s1[1]);
                f16 h12 = __float2half_rn(s1[2]), h13 = __float2half_rn(s1[3]);
                pah[0] = pack_h2(h00, h01);
                pah[1] = pack_h2(h02, h03);
                pah[2] = pack_h2(h10, h11);
                pah[3] = pack_h2(h12, h13);
                pal[0] = pack_h2(__float2half_rn(s0[0] - __half2float(h00)),
                                 __float2half_rn(s0[1] - __half2float(h01)));
                pal[1] = pack_h2(__float2half_rn(s0[2] - __half2float(h02)),
                                 __float2half_rn(s0[3] - __half2float(h03)));
                pal[2] = pack_h2(__float2half_rn(s1[0] - __half2float(h10)),
                                 __float2half_rn(s1[1] - __half2float(h11)));
                pal[3] = pack_h2(__float2half_rn(s1[2] - __half2float(h12)),
                                 __float2half_rn(s1[3] - __half2float(h13)));
            }
            uint32_t vh[4][4];
#pragma unroll
            for (int np = 0; np < 4; np++) {
                uint32_t ro = (uint32_t)((j * 16 + rbase) * 128);
                uint32_t cb = (uint32_t)((np * 32 + ksel) ^ cxor);
                LDSM4T(vh[np], bs + 8192 + ro + cb);
            }
#pragma unroll
            for (int nf = 0; nf < 8; nf++) {
                int np = nf >> 1, hh = nf & 1;
                MMA16816(Oa[nf], pah, vh[np][hh * 2], vh[np][hh * 2 + 1]);
            }
#pragma unroll
            for (int nf = 0; nf < 8; nf++) {
                int np = nf >> 1, hh = nf & 1;
                MMA16816(Oa[nf], pal, vh[np][hh * 2], vh[np][hh * 2 + 1]);
            }
        }
        __syncthreads();
    }

    // ---- epilogue ----
    float inv0 = 1.f / l0, inv1 = 1.f / l1;
    int r0 = q0 + w * 16 + (l >> 2);
    long n0tok = segbase + off + (long)r0 * rdil;
    long n1tok = segbase + off + (long)(r0 + 8) * rdil;
    float* o0 = O + n0tok * DM + head * HD;
    float* o1 = O + n1tok * DM + head * HD;
    int cbase = (l & 3) * 2;
#pragma unroll
    for (int nf = 0; nf < 8; nf++) {
        int col = nf * 8 + cbase;
        *(float2*)(o0 + col) = make_float2(Oa[nf][0] * inv0, Oa[nf][1] * inv0);
        *(float2*)(o1 + col) = make_float2(Oa[nf][2] * inv1, Oa[nf][3] * inv1);
    }
#undef LOAD_KV
}

// ---------------- host orchestration ---------------------------------------
extern "C" void kernel_launch(void* const* d_in, const int* in_sizes, int n_in,
                              void* d_out, int out_size) {
    const float* src  = (const float*)d_in[0];
    const float* ln1w = (const float*)d_in[1];
    const float* ln1b = (const float*)d_in[2];
    const float* Wq   = (const float*)d_in[3];
    const float* bq   = (const float*)d_in[4];
    const float* Wk   = (const float*)d_in[5];
    const float* bk   = (const float*)d_in[6];
    const float* Wv   = (const float*)d_in[7];
    const float* bv   = (const float*)d_in[8];
    const float* lnAw = (const float*)d_in[9];
    const float* lnAb = (const float*)d_in[10];
    const float* Wo   = (const float*)d_in[11];
    const float* bo   = (const float*)d_in[12];
    const float* ln2w = (const float*)d_in[13];
    const float* ln2b = (const float*)d_in[14];
    const float* W1   = (const float*)d_in[15];
    const float* b1   = (const float*)d_in[16];
    const float* ln3w = (const float*)d_in[17];
    const float* ln3b = (const float*)d_in[18];
    const float* W2   = (const float*)d_in[19];
    const float* b2   = (const float*)d_in[20];
    float* out = (float*)d_out;

    float *px, *patt, *pf1;
    f16 *ahi, *alo, *qh, *ql, *kh, *vh;
    f16 *wqkvh, *woh, *w1h, *w2h;
    cudaGetSymbolAddress((void**)&px,    g_x);
    cudaGetSymbolAddress((void**)&patt,  g_att);
    cudaGetSymbolAddress((void**)&pf1,   g_f1);
    cudaGetSymbolAddress((void**)&ahi,   g_ahi);
    cudaGetSymbolAddress((void**)&alo,   g_alo);
    cudaGetSymbolAddress((void**)&qh,    g_qh);
    cudaGetSymbolAddress((void**)&ql,    g_ql);
    cudaGetSymbolAddress((void**)&kh,    g_kh);
    cudaGetSymbolAddress((void**)&vh,    g_vh);
    cudaGetSymbolAddress((void**)&wqkvh, g_wqkvh);
    cudaGetSymbolAddress((void**)&woh,   g_woh);
    cudaGetSymbolAddress((void**)&w1h,   g_w1h);
    cudaGetSymbolAddress((void**)&w2h,   g_w2h);

    static bool attr_done = false;
    if (!attr_done) {
        cudaFuncSetAttribute(gemm2x_kernel<0>, cudaFuncAttributeMaxDynamicSharedMemorySize, GSMEM);
        cudaFuncSetAttribute(gemm2x_kernel<2>, cudaFuncAttributeMaxDynamicSharedMemorySize, GSMEM);
        cudaFuncSetAttribute(attn_tc_kernel, cudaFuncAttributeMaxDynamicSharedMemorySize, ASMEM);
        attr_done = true;
    }

    dim3 tT(32, 8);
    dim3 gW(DM / 32, DM / 32);
    dim3 gW1(DM / 32, DFF / 32);
    dim3 gW2(DFF / 32, DM / 32);
    dim3 gq(DM / 128, NTOK / 128);        // (6,128)
    dim3 gqkv(3 * DM / 128, NTOK / 128);  // (18,128)
    dim3 g1(DFF / 128, NTOK / 128);       // (24,128)

    // weight transpose (hi only; QKV packed along N)
    splitT_kernel<<<gW,  tT>>>(Wq, wqkvh,               DM, DM);
    splitT_kernel<<<gW,  tT>>>(Wk, wqkvh + DM * DM,     DM, DM);
    splitT_kernel<<<gW,  tT>>>(Wv, wqkvh + 2 * DM * DM, DM, DM);
    splitT_kernel<<<gW,  tT>>>(Wo, woh, DM, DM);
    splitT_kernel<<<gW1, tT>>>(W1, w1h, DM, DFF);
    splitT_kernel<<<gW2, tT>>>(W2, w2h, DFF, DM);

    // LN1 -> split, fused QKV projection (Q hi/lo pre-scaled 0.125; K,V hi)
    ln_split_kernel<<<NTOK, 256>>>(src, ln1w, ln1b, ahi, alo, DM);
    gemm2x_kernel<2><<<gqkv, 256, GSMEM>>>(ahi, alo, wqkvh,
                                           bq, bk, bv, nullptr,
                                           qh, ql, kh, vh, DM, DM, 0);

    // attention: zero + tensor-core dilated flash attention (128-q tiles)
    zero_kernel<<<4096, 256>>>((float4*)patt, (long)NTOK * DM / 4);
    attn_tc_kernel<<<dim3(16, 4, 14), 256, ASMEM>>>(qh, ql, kh, vh, patt);

    // MAGNETO sub-LN -> split, out projection
    ln_split_kernel<<<NTOK, 256>>>(patt, lnAw, lnAb, ahi, alo, DM);
    gemm2x_kernel<0><<<gq, 256, GSMEM>>>(ahi, alo, woh,
                                         bo, nullptr, nullptr, px,
                                         nullptr, nullptr, nullptr, nullptr,
                                         DM, DM, 0);

    // LN2 -> split, FF1 (relu)
    ln_split_kernel<<<NTOK, 256>>>(px, ln2w, ln2b, ahi, alo, DM);
    gemm2x_kernel<0><<<g1, 256, GSMEM>>>(ahi, alo, w1h,
                                         b1, nullptr, nullptr, pf1,
                                         nullptr, nullptr, nullptr, nullptr,
                                         DM, DFF, 1);

    // LN3 -> split, FF2
    ln_split_kernel<<<NTOK, 256>>>(pf1, ln3w, ln3b, ahi, alo, DFF);
    gemm2x_kernel<0><<<gq, 256, GSMEM>>>(ahi, alo, w2h,
                                         b2, nullptr, nullptr, out,
                                         nullptr, nullptr, nullptr, nullptr,
                                         DFF, DM, 0);
}

// round 13
// speedup vs baseline: 3.7650x; 1.0109x over previous
#include <cuda_runtime.h>
#include <cuda_fp16.h>
#include <cstdint>

#define NTOK 16384          // B*N = 2*8192
#define NSEQ 8192
#define DM   768
#define DFF  3072
#define NH   12
#define HD   64

typedef __half f16;

// ---------------- scratch (device globals; no allocation allowed) ----------
// g_att is zero-initialized at module load; attention writes exactly the
// dilated-selected positions each run and nothing else ever writes it, so
// unselected positions remain zero across all graph replays (no zero pass).
__device__ float g_x  [NTOK * DM];     // Wo output
__device__ float g_att[NTOK * DM];     // attention output (fp32)
__device__ float g_f1 [NTOK * DFF];
__device__ f16   g_ahi[NTOK * DFF];
__device__ f16   g_alo[NTOK * DFF];
__device__ f16   g_qh [NTOK * DM], g_ql[NTOK * DM];
__device__ f16   g_kh [NTOK * DM];
__device__ f16   g_vh [NTOK * DM];
__device__ f16   g_wqkvh[3 * DM * DM];     // packed Q,K,V weights (hi only)
__device__ f16   g_woh[DM * DM];
__device__ f16   g_w1h[DM * DFF];
__device__ f16   g_w2h[DFF * DM];

// ======================= PTX helpers =======================================
__device__ __forceinline__ uint32_t s2u(const void* p) {
    uint32_t a;
    asm("{ .reg .u64 t; cvta.to.shared.u64 t, %1; cvt.u32.u64 %0, t; }"
        : "=r"(a) : "l"(p));
    return a;
}

#define CP16(dst, src) \
    asm volatile("cp.async.cg.shared.global [%0], [%1], 16;" :: "r"(dst), "l"(src) : "memory")
#define CP_COMMIT() asm volatile("cp.async.commit_group;" ::: "memory")
#define CP_WAIT1()  asm volatile("cp.async.wait_group 1;" ::: "memory")
#define CP_WAIT2()  asm volatile("cp.async.wait_group 2;" ::: "memory")

#define LDSM4(r, a)                                                          \
    asm volatile("ldmatrix.sync.aligned.m8n8.x4.shared.b16 {%0,%1,%2,%3}, [%4];" \
        : "=r"((r)[0]), "=r"((r)[1]), "=r"((r)[2]), "=r"((r)[3]) : "r"(a))

#define LDSM4T(r, a)                                                         \
    asm volatile("ldmatrix.sync.aligned.m8n8.x4.trans.shared.b16 {%0,%1,%2,%3}, [%4];" \
        : "=r"((r)[0]), "=r"((r)[1]), "=r"((r)[2]), "=r"((r)[3]) : "r"(a))

#define MMA16816(c, a, b0, b1)                                               \
    asm volatile("mma.sync.aligned.m16n8k16.row.col.f32.f16.f16.f32 "        \
        "{%0,%1,%2,%3}, {%4,%5,%6,%7}, {%8,%9}, {%0,%1,%2,%3};"              \
        : "+f"((c)[0]), "+f"((c)[1]), "+f"((c)[2]), "+f"((c)[3])             \
        : "r"((a)[0]), "r"((a)[1]), "r"((a)[2]), "r"((a)[3]),                \
          "r"(b0), "r"(b1))

__device__ __forceinline__ uint32_t h2u(__half2 h) {
    return *reinterpret_cast<uint32_t*>(&h);
}

// packed hi/lo split of a float pair (rn rounding — bit-identical to scalar)
__device__ __forceinline__ void split2(float a, float b, uint32_t& hi, uint32_t& lo) {
    __half2 h = __floats2half2_rn(a, b);
    float2 f = __half22float2(h);
    hi = h2u(h);
    lo = h2u(__floats2half2_rn(a - f.x, b - f.y));
}

// ========== LayerNorm fused with fp16 hi/lo split (vectorized) =============
__global__ void ln_split_kernel(const float* __restrict__ x, const float* __restrict__ w,
                                const float* __restrict__ b, f16* __restrict__ hi,
                                f16* __restrict__ lo, int C) {
    long row = blockIdx.x;
    const float4* xr = (const float4*)(x + row * (long)C);
    const int n4 = C >> 2;
    float4 v[3];
    float s = 0.f, ss = 0.f;
    int cnt = 0;
#pragma unroll 3
    for (int c4 = threadIdx.x; c4 < n4; c4 += 256, cnt++) {
        float4 a = xr[c4];
        v[cnt] = a;
        s  += a.x + a.y + a.z + a.w;
        ss += a.x * a.x + a.y * a.y + a.z * a.z + a.w * a.w;
    }
    for (int o = 16; o; o >>= 1) {
        s  += __shfl_xor_sync(0xffffffffu, s,  o);
        ss += __shfl_xor_sync(0xffffffffu, ss, o);
    }
    __shared__ float sh[2][8];
    int wi = threadIdx.x >> 5, li = threadIdx.x & 31;
    if (li == 0) { sh[0][wi] = s; sh[1][wi] = ss; }
    __syncthreads();
    if (threadIdx.x < 32) {
        s  = (li < 8) ? sh[0][li] : 0.f;
        ss = (li < 8) ? sh[1][li] : 0.f;
        for (int o = 4; o; o >>= 1) {
            s  += __shfl_xor_sync(0xffffffffu, s,  o);
            ss += __shfl_xor_sync(0xffffffffu, ss, o);
        }
        if (li == 0) { sh[0][0] = s; sh[1][0] = ss; }
    }
    __syncthreads();
    float mean = sh[0][0] / (float)C;
    float var  = sh[1][0] / (float)C - mean * mean;
    float rstd = rsqrtf(var + 1e-5f);
    uint2* hr = (uint2*)(hi + row * (long)C);
    uint2* lr = (uint2*)(lo + row * (long)C);
    const float4* w4 = (const float4*)w;
    const float4* b4 = (const float4*)b;
    cnt = 0;
#pragma unroll 3
    for (int c4 = threadIdx.x; c4 < n4; c4 += 256, cnt++) {
        float4 a = v[cnt];
        float4 ww = w4[c4], bb = b4[c4];
        float y0 = (a.x - mean) * rstd * ww.x + bb.x;
        float y1 = (a.y - mean) * rstd * ww.y + bb.y;
        float y2 = (a.z - mean) * rstd * ww.z + bb.z;
        float y3 = (a.w - mean) * rstd * ww.w + bb.w;
        uint2 hv, lv;
        split2(y0, y1, hv.x, lv.x);
        split2(y2, y3, hv.y, lv.y);
        hr[c4] = hv;
        lr[c4] = lv;
    }
}

// ======= weight transpose (hi only): W[K,N] -> fp16 [N,K] ==================
__global__ void splitT_kernel(const float* __restrict__ W, f16* __restrict__ hi,
                              int K, int N) {
    __shared__ float t[32][33];
    int k0 = blockIdx.x * 32, n0 = blockIdx.y * 32;
    int tx = threadIdx.x, ty = threadIdx.y;   // 32 x 8
#pragma unroll
    for (int i = 0; i < 4; i++)
        t[ty + 8 * i][tx] = W[(long)(k0 + ty + 8 * i) * N + n0 + tx];
    __syncthreads();
#pragma unroll
    for (int i = 0; i < 4; i++) {
        float v = t[tx][ty + 8 * i];
        hi[(long)(n0 + ty + 8 * i) * K + k0 + tx] = __float2half_rn(v);
    }
}

// ================= mma.sync 2x-fp16 GEMM ===================================
// D = (Ahi+Alo)[M,K] x (Bh[Nrows,K])^T + bias   (B fp16 hi only).
// MODE 0: fp32 out. MODE 2: fused QKV (Q hi/lo scaled 0.125; K,V hi).
// One __syncthreads per chunk: next load (issued after the top sync) targets
// slot (i+4)&3 == i&3, and the top sync proves all warps finished reading it.
#define GSTAGES 4
#define TILE_B   16384                   // one operand tile: 128 rows x 128 B
#define GSTAGE_B (3 * TILE_B)            // Ah, Al, Bh
#define GSMEM    (GSTAGES * GSTAGE_B)    // 196608

template <int MODE>
__global__ void __launch_bounds__(256, 1)
gemm2x_kernel(const f16* __restrict__ Ahi, const f16* __restrict__ Alo,
              const f16* __restrict__ Bh,
              const float* __restrict__ bias0, const float* __restrict__ bias1,
              const float* __restrict__ bias2, float* __restrict__ C,
              f16* __restrict__ h0, f16* __restrict__ l0,
              f16* __restrict__ h1, f16* __restrict__ h2,
              int Kdim, int Ncols, int relu) {
    extern __shared__ char smraw[];
    const uint32_t sb = s2u(smraw);
    const int tid = threadIdx.x;
    const int m0 = blockIdx.y * 128, n0 = blockIdx.x * 128;
    const int nk = Kdim >> 6;                 // chunks of 64 fp16
    const long rowb = (long)Kdim * 2;         // bytes per gmem row

    const char* pAh = (const char*)Ahi + (long)m0 * rowb;
    const char* pAl = (const char*)Alo + (long)m0 * rowb;
    const char* pBh = (const char*)Bh  + (long)n0 * rowb;

    int lrow[4], lkb[4];
    uint32_t ldst[4];
#pragma unroll
    for (int j = 0; j < 4; j++) {
        int u = tid + 256 * j;
        lrow[j] = u >> 3;
        lkb[j]  = (u & 7) * 16;
        ldst[j] = (uint32_t)(lrow[j] * 128 + (lkb[j] ^ ((lrow[j] & 7) * 16)));
    }

#define LOAD_CHUNK(slot, ci) do {                                            \
    uint32_t stg_ = sb + (slot) * GSTAGE_B;                                  \
    long koff_ = (long)(ci) * 128;                                           \
    _Pragma("unroll")                                                        \
    for (int j = 0; j < 4; j++) {                                            \
        long go = (long)lrow[j] * rowb + koff_ + lkb[j];                     \
        CP16(stg_ + ldst[j],              pAh + go);                         \
        CP16(stg_ + TILE_B + ldst[j],     pAl + go);                         \
        CP16(stg_ + 2 * TILE_B + ldst[j], pBh + go);                         \
    }                                                                        \
} while (0)

    const int wid = tid >> 5, l = tid & 31;
    const int wm = wid & 3, wn = wid >> 2;
    const int quad = l >> 3, rim = l & 7;
    const int rimx = rim * 16;
    const int kbq = (quad >> 1) * 16;

    uint32_t aoff[2], boff[4];
#pragma unroll
    for (int mf = 0; mf < 2; mf++)
        aoff[mf] = (uint32_t)((wm * 32 + mf * 16 + (quad & 1) * 8 + rim) * 128);
#pragma unroll
    for (int np = 0; np < 4; np++)
        boff[np] = (uint32_t)((wn * 64 + np * 16 + (quad & 1) * 8 + rim) * 128);

    float acc[2][8][4];
#pragma unroll
    for (int mf = 0; mf < 2; mf++)
#pragma unroll
        for (int nf = 0; nf < 8; nf++)
#pragma unroll
            for (int c = 0; c < 4; c++) acc[mf][nf][c] = 0.f;

#pragma unroll
    for (int s = 0; s < GSTAGES - 1; s++) {
        LOAD_CHUNK(s, s);
        CP_COMMIT();
    }

    int slot = 0;
    for (int i = 0; i < nk; i++) {
        CP_WAIT2();
        __syncthreads();
        int nc = i + GSTAGES - 1;
        if (nc < nk) LOAD_CHUNK((nc & 3), nc);
        CP_COMMIT();

        const uint32_t stg = sb + slot * GSTAGE_B;
        const uint32_t aH = stg, aL = stg + TILE_B, bH = stg + 2 * TILE_B;

#pragma unroll
        for (int ks = 0; ks < 4; ks++) {
            const uint32_t kx = (uint32_t)((ks * 32 + kbq) ^ rimx);
            uint32_t ah[2][4], al[2][4], bh[4][4];
#pragma unroll
            for (int mf = 0; mf < 2; mf++) {
                LDSM4(ah[mf], aH + aoff[mf] + kx);
                LDSM4(al[mf], aL + aoff[mf] + kx);
            }
#pragma unroll
            for (int np = 0; np < 4; np++)
                LDSM4(bh[np], bH + boff[np] + kx);
#pragma unroll
            for (int mf = 0; mf < 2; mf++)
#pragma unroll
                for (int nf = 0; nf < 8; nf++) {
                    int np = nf >> 1, hh = nf & 1;
                    MMA16816(acc[mf][nf], ah[mf], bh[np][hh], bh[np][hh + 2]);
                }
#pragma unroll
            for (int mf = 0; mf < 2; mf++)
#pragma unroll
                for (int nf = 0; nf < 8; nf++) {
                    int np = nf >> 1, hh = nf & 1;
                    MMA16816(acc[mf][nf], al[mf], bh[np][hh], bh[np][hh + 2]);
                }
        }
        // no bottom sync: next iteration's top sync is the write-after-read guard
        slot = (slot + 1) & 3;
    }

    // ---------------- epilogue -----------------------------------------
    const float* bp = bias0;
    f16 *chi = h0, *clo = l0;
    float alpha = 1.f;
    int outb = n0;
    if (MODE == 2) {
        int mat = n0 / DM;
        outb = n0 - mat * DM;
        bp  = (mat == 0) ? bias0 : (mat == 1) ? bias1 : bias2;
        chi = (mat == 0) ? h0 : (mat == 1) ? h1 : h2;
        clo = (mat == 0) ? l0 : nullptr;
        alpha = (mat == 0) ? 0.125f : 1.f;
    }
    const int g = l >> 2, t4 = l & 3;
#pragma unroll
    for (int mf = 0; mf < 2; mf++) {
        int row = m0 + wm * 32 + mf * 16 + g;
#pragma unroll
        for (int nf = 0; nf < 8; nf++) {
            int col = outb + wn * 64 + nf * 8 + 2 * t4;
            float b0v = bp[col], b1v = bp[col + 1];
            float v0 = acc[mf][nf][0] + b0v;
            float v1 = acc[mf][nf][1] + b1v;
            float v2 = acc[mf][nf][2] + b0v;
            float v3 = acc[mf][nf][3] + b1v;
            if (MODE == 0 && relu) {
                v0 = fmaxf(v0, 0.f); v1 = fmaxf(v1, 0.f);
                v2 = fmaxf(v2, 0.f); v3 = fmaxf(v3, 0.f);
            }
            if (MODE == 2) {
                v0 *= alpha; v1 *= alpha; v2 *= alpha; v3 *= alpha;
                if (clo) {
                    uint32_t ha, la, hb, lb;
                    split2(v0, v1, ha, la);
                    split2(v2, v3, hb, lb);
                    *(uint32_t*)(chi + (long)row * Ncols + col)       = ha;
                    *(uint32_t*)(chi + (long)(row + 8) * Ncols + col) = hb;
                    *(uint32_t*)(clo + (long)row * Ncols + col)       = la;
                    *(uint32_t*)(clo + (long)(row + 8) * Ncols + col) = lb;
                } else {
                    *(uint32_t*)(chi + (long)row * Ncols + col)       = h2u(__floats2half2_rn(v0, v1));
                    *(uint32_t*)(chi + (long)(row + 8) * Ncols + col) = h2u(__floats2half2_rn(v2, v3));
                }
            } else {
                *(float2*)(C + (long)row * Ncols + col)       = make_float2(v0, v1);
                *(float2*)(C + (long)(row + 8) * Ncols + col) = make_float2(v2, v3);
            }
        }
    }
#undef LOAD_CHUNK
}

// ============== tensor-core dilated flash attention ========================
// CTA = 256 threads / 128 queries; 2 CTAs/SM. 3 KV buffers -> one sync per
// tile (the top sync guards the buffer the new load overwrites, which was
// last read two iterations ago). Q hi resident, Q lo re-read from smem.
__constant__ int c_seg[3] = {2048, 4096, 8192};
__constant__ int c_dil[3] = {1, 2, 4};
#define LOG2E 1.4426950408889634f

#define ASM_QH  0
#define ASM_QL  16384
#define ASM_KV  32768
#define ASM_BUF 16384       // per KV buffer: Kh 0-8K, Vh 8K-16K
#define ASMEM   (ASM_KV + 3 * ASM_BUF)   // 81920

__global__ void __launch_bounds__(256, 2)
attn_tc_kernel(const f16* __restrict__ Qh, const f16* __restrict__ Ql,
               const f16* __restrict__ Kh, const f16* __restrict__ Vh,
               float* __restrict__ O) {
    extern __shared__ char smraw[];
    const uint32_t sb = s2u(smraw);

    int z = blockIdx.z;
    int bb = z / 7, t = z % 7;
    int grp, seg;
    if (t < 4)       { grp = 0; seg = t; }
    else if (t < 6)  { grp = 1; seg = t - 4; }
    else             { grp = 2; seg = 0; }
    const int sl = c_seg[grp], rdil = c_dil[grp];
    const int off = grp % rdil;
    const int head = grp * 4 + blockIdx.y;
    const int q0 = blockIdx.x * 128;
    const long segbase = (long)bb * NSEQ + (long)seg * sl;

    const int tid = threadIdx.x;
    // Q loader: 256 threads cover 128 rows x 128 B
    const int qrow_l = tid >> 1;
    const int qkb0 = (tid & 1) * 64;
    uint32_t qdst[4];
#pragma unroll
    for (int j = 0; j < 4; j++) {
        int kb = qkb0 + j * 16;
        qdst[j] = (uint32_t)(qrow_l * 128 + (kb ^ ((qrow_l & 7) * 16)));
    }
    // KV loader: 256 threads cover 64 rows x 128 B per operand
    const int krow_l = tid >> 2;
    const int kkb0 = (tid & 3) * 32;
    uint32_t kdst[2];
#pragma unroll
    for (int j = 0; j < 2; j++) {
        int kb = kkb0 + j * 16;
        kdst[j] = (uint32_t)(krow_l * 128 + (kb ^ ((krow_l & 7) * 16)));
    }

    // ---- load Q tile (hi+lo): group 0 ----
    {
        long fo = (segbase + off + (long)(q0 + qrow_l) * rdil) * DM + head * HD;
        const char* gh = (const char*)(Qh + fo);
        const char* gl = (const char*)(Ql + fo);
#pragma unroll
        for (int j = 0; j < 4; j++) {
            CP16(sb + ASM_QH + qdst[j], gh + qkb0 + j * 16);
            CP16(sb + ASM_QL + qdst[j], gl + qkb0 + j * 16);
        }
    }
    CP_COMMIT();

#define LOAD_KV(ti, buf) do {                                                \
    long fo_ = (segbase + off + (long)((ti) * 64 + krow_l) * rdil) * DM + head * HD; \
    uint32_t bs_ = sb + ASM_KV + (buf) * ASM_BUF;                            \
    const char* gkh_ = (const char*)(Kh + fo_);                              \
    const char* gvh_ = (const char*)(Vh + fo_);                              \
    _Pragma("unroll")                                                        \
    for (int j = 0; j < 2; j++) {                                            \
        CP16(bs_ + kdst[j],        gkh_ + kkb0 + j * 16);                    \
        CP16(bs_ + 8192 + kdst[j], gvh_ + kkb0 + j * 16);                    \
    }                                                                        \
} while (0)

    LOAD_KV(0, 0);
    CP_COMMIT();           // group 1
    LOAD_KV(1, 1);
    CP_COMMIT();           // group 2
    CP_WAIT2();            // Q (group 0) retired
    __syncthreads();

    // ---- per-warp fragment addressing ----
    const int l = tid & 31, w = tid >> 5;
    const int mi = l >> 3, rr = l & 7;
    const int rbase = (mi & 1) * 8 + rr;    // row within a 16-row block
    const int cxor = rr * 16;               // SW128 xor term
    const int ksel = (mi >> 1) * 16;        // 8-col (16B) selector
    const uint32_t qrow = (uint32_t)((w * 16 + rbase) * 128);

    // Q hi fragments resident; Q lo re-read per tile
    uint32_t qfh[4][4];
#pragma unroll
    for (int ks = 0; ks < 4; ks++) {
        uint32_t cb = (uint32_t)((ks * 32 + ksel) ^ cxor);
        LDSM4(qfh[ks], sb + ASM_QH + qrow + cb);
    }

    float Oa[8][4];
#pragma unroll
    for (int nf = 0; nf < 8; nf++)
#pragma unroll
        for (int c = 0; c < 4; c++) Oa[nf][c] = 0.f;
    float m0 = -1e30f, m1 = -1e30f, l0 = 0.f, l1 = 0.f;

    int bufc = 0;            // buffer of current tile kt
    for (int kt = 0; kt < 32; kt++) {
        CP_WAIT1();          // tile kt landed (kt+1 may be in flight)
        __syncthreads();     // also guards buffer (kt+2)%3 (read at kt-1)
        if (kt + 2 < 32) {
            int nb = bufc + 2;
            if (nb >= 3) nb -= 3;
            LOAD_KV(kt + 2, nb);
        }
        CP_COMMIT();

        const uint32_t bs = sb + ASM_KV + bufc * ASM_BUF;

        // ---- S = Q K^T (2-pass), fp32 acc; 16q x 64kv per warp ----
        float S[8][4];
#pragma unroll
        for (int nf = 0; nf < 8; nf++)
#pragma unroll
            for (int c = 0; c < 4; c++) S[nf][c] = 0.f;

#pragma unroll
        for (int ks = 0; ks < 4; ks++) {
            uint32_t cb = (uint32_t)((ks * 32 + ksel) ^ cxor);
            uint32_t bh[4][4], qfl[4];
            LDSM4(qfl, sb + ASM_QL + qrow + cb);
#pragma unroll
            for (int np = 0; np < 4; np++) {
                uint32_t ro = (uint32_t)((np * 16 + rbase) * 128);
                LDSM4(bh[np], bs + ro + cb);
            }
#pragma unroll
            for (int nf = 0; nf < 8; nf++) {
                int np = nf >> 1, hh = nf & 1;
                MMA16816(S[nf], qfh[ks], bh[np][hh], bh[np][hh + 2]);
            }
#pragma unroll
            for (int nf = 0; nf < 8; nf++) {
                int np = nf >> 1, hh = nf & 1;
                MMA16816(S[nf], qfl, bh[np][hh], bh[np][hh + 2]);
            }
        }

        // ---- online softmax in base-2 (rows r=l>>2 and r+8) ----
        float mx0 = -1e30f, mx1 = -1e30f;
#pragma unroll
        for (int nf = 0; nf < 8; nf++) {
            mx0 = fmaxf(mx0, fmaxf(S[nf][0], S[nf][1]));
            mx1 = fmaxf(mx1, fmaxf(S[nf][2], S[nf][3]));
        }
        mx0 = fmaxf(mx0, __shfl_xor_sync(0xffffffffu, mx0, 1));
        mx0 = fmaxf(mx0, __shfl_xor_sync(0xffffffffu, mx0, 2));
        mx1 = fmaxf(mx1, __shfl_xor_sync(0xffffffffu, mx1, 1));
        mx1 = fmaxf(mx1, __shfl_xor_sync(0xffffffffu, mx1, 2));
        float nm0 = fmaxf(m0, mx0), nm1 = fmaxf(m1, mx1);
        float fac0 = exp2f((m0 - nm0) * LOG2E), fac1 = exp2f((m1 - nm1) * LOG2E);
        m0 = nm0; m1 = nm1;
        float c0 = nm0 * LOG2E, c1 = nm1 * LOG2E;
        float rs0 = 0.f, rs1 = 0.f;
#pragma unroll
        for (int nf = 0; nf < 8; nf++) {
            S[nf][0] = exp2f(S[nf][0] * LOG2E - c0); rs0 += S[nf][0];
            S[nf][1] = exp2f(S[nf][1] * LOG2E - c0); rs0 += S[nf][1];
            S[nf][2] = exp2f(S[nf][2] * LOG2E - c1); rs1 += S[nf][2];
            S[nf][3] = exp2f(S[nf][3] * LOG2E - c1); rs1 += S[nf][3];
        }
        rs0 += __shfl_xor_sync(0xffffffffu, rs0, 1);
        rs0 += __shfl_xor_sync(0xffffffffu, rs0, 2);
        rs1 += __shfl_xor_sync(0xffffffffu, rs1, 1);
        rs1 += __shfl_xor_sync(0xffffffffu, rs1, 2);
        l0 = l0 * fac0 + rs0;
        l1 = l1 * fac1 + rs1;
#pragma unroll
        for (int nf = 0; nf < 8; nf++) {
            Oa[nf][0] *= fac0; Oa[nf][1] *= fac0;
            Oa[nf][2] *= fac1; Oa[nf][3] *= fac1;
        }

        // ---- O += P V (2-pass: Ph, Pl); packed hi/lo split ----
#pragma unroll
        for (int j = 0; j < 4; j++) {
            uint32_t pah[4], pal[4];
            {
                const float* s0 = S[2 * j];
                const float* s1 = S[2 * j + 1];
                split2(s0[0], s0[1], pah[0], pal[0]);
                split2(s0[2], s0[3], pah[1], pal[1]);
                split2(s1[0], s1[1], pah[2], pal[2]);
                split2(s1[2], s1[3], pah[3], pal[3]);
            }
            uint32_t vh[4][4];
#pragma unroll
            for (int np = 0; np < 4; np++) {
                uint32_t ro = (uint32_t)((j * 16 + rbase) * 128);
                uint32_t cb = (uint32_t)((np * 32 + ksel) ^ cxor);
                LDSM4T(vh[np], bs + 8192 + ro + cb);
            }
#pragma unroll
            for (int nf = 0; nf < 8; nf++) {
                int np = nf >> 1, hh = nf & 1;
                MMA16816(Oa[nf], pah, vh[np][hh * 2], vh[np][hh * 2 + 1]);
            }
#pragma unroll
            for (int nf = 0; nf < 8; nf++) {
                int np = nf >> 1, hh = nf & 1;
                MMA16816(Oa[nf], pal, vh[np][hh * 2], vh[np][hh * 2 + 1]);
            }
        }
        // no bottom sync: 3 buffers + top sync cover the overwrite hazard
        if (++bufc == 3) bufc = 0;
    }

    // ---- epilogue ----
    float inv0 = 1.f / l0, inv1 = 1.f / l1;
    int r0 = q0 + w * 16 + (l >> 2);
    long n0tok = segbase + off + (long)r0 * rdil;
    long n1tok = segbase + off + (long)(r0 + 8) * rdil;
    float* o0 = O + n0tok * DM + head * HD;
    float* o1 = O + n1tok * DM + head * HD;
    int cbase = (l & 3) * 2;
#pragma unroll
    for (int nf = 0; nf < 8; nf++) {
        int col = nf * 8 + cbase;
        *(float2*)(o0 + col) = make_float2(Oa[nf][0] * inv0, Oa[nf][1] * inv0);
        *(float2*)(o1 + col) = make_float2(Oa[nf][2] * inv1, Oa[nf][3] * inv1);
    }
#undef LOAD_KV
}

// ---------------- host orchestration ---------------------------------------
extern "C" void kernel_launch(void* const* d_in, const int* in_sizes, int n_in,
                              void* d_out, int out_size) {
    const float* src  = (const float*)d_in[0];
    const float* ln1w = (const float*)d_in[1];
    const float* ln1b = (const float*)d_in[2];
    const float* Wq   = (const float*)d_in[3];
    const float* bq   = (const float*)d_in[4];
    const float* Wk   = (const float*)d_in[5];
    const float* bk   = (const float*)d_in[6];
    const float* Wv   = (const float*)d_in[7];
    const float* bv   = (const float*)d_in[8];
    const float* lnAw = (const float*)d_in[9];
    const float* lnAb = (const float*)d_in[10];
    const float* Wo   = (const float*)d_in[11];
    const float* bo   = (const float*)d_in[12];
    const float* ln2w = (const float*)d_in[13];
    const float* ln2b = (const float*)d_in[14];
    const float* W1   = (const float*)d_in[15];
    const float* b1   = (const float*)d_in[16];
    const float* ln3w = (const float*)d_in[17];
    const float* ln3b = (const float*)d_in[18];
    const float* W2   = (const float*)d_in[19];
    const float* b2   = (const float*)d_in[20];
    float* out = (float*)d_out;

    float *px, *patt, *pf1;
    f16 *ahi, *alo, *qh, *ql, *kh, *vh;
    f16 *wqkvh, *woh, *w1h, *w2h;
    cudaGetSymbolAddress((void**)&px,    g_x);
    cudaGetSymbolAddress((void**)&patt,  g_att);
    cudaGetSymbolAddress((void**)&pf1,   g_f1);
    cudaGetSymbolAddress((void**)&ahi,   g_ahi);
    cudaGetSymbolAddress((void**)&alo,   g_alo);
    cudaGetSymbolAddress((void**)&qh,    g_qh);
    cudaGetSymbolAddress((void**)&ql,    g_ql);
    cudaGetSymbolAddress((void**)&kh,    g_kh);
    cudaGetSymbolAddress((void**)&vh,    g_vh);
    cudaGetSymbolAddress((void**)&wqkvh, g_wqkvh);
    cudaGetSymbolAddress((void**)&woh,   g_woh);
    cudaGetSymbolAddress((void**)&w1h,   g_w1h);
    cudaGetSymbolAddress((void**)&w2h,   g_w2h);

    static bool attr_done = false;
    if (!attr_done) {
        cudaFuncSetAttribute(gemm2x_kernel<0>, cudaFuncAttributeMaxDynamicSharedMemorySize, GSMEM);
        cudaFuncSetAttribute(gemm2x_kernel<2>, cudaFuncAttributeMaxDynamicSharedMemorySize, GSMEM);
        cudaFuncSetAttribute(attn_tc_kernel, cudaFuncAttributeMaxDynamicSharedMemorySize, ASMEM);
        attr_done = true;
    }

    dim3 tT(32, 8);
    dim3 gW(DM / 32, DM / 32);
    dim3 gW1(DM / 32, DFF / 32);
    dim3 gW2(DFF / 32, DM / 32);
    dim3 gq(DM / 128, NTOK / 128);        // (6,128)
    dim3 gqkv(3 * DM / 128, NTOK / 128);  // (18,128)
    dim3 g1(DFF / 128, NTOK / 128);       // (24,128)

    // weight transpose (hi only; QKV packed along N)
    splitT_kernel<<<gW,  tT>>>(Wq, wqkvh,               DM, DM);
    splitT_kernel<<<gW,  tT>>>(Wk, wqkvh + DM * DM,     DM, DM);
    splitT_kernel<<<gW,  tT>>>(Wv, wqkvh + 2 * DM * DM, DM, DM);
    splitT_kernel<<<gW,  tT>>>(Wo, woh, DM, DM);
    splitT_kernel<<<gW1, tT>>>(W1, w1h, DM, DFF);
    splitT_kernel<<<gW2, tT>>>(W2, w2h, DFF, DM);

    // LN1 -> split, fused QKV projection (Q hi/lo pre-scaled 0.125; K,V hi)
    ln_split_kernel<<<NTOK, 256>>>(src, ln1w, ln1b, ahi, alo, DM);
    gemm2x_kernel<2><<<gqkv, 256, GSMEM>>>(ahi, alo, wqkvh,
                                           bq, bk, bv, nullptr,
                                           qh, ql, kh, vh, DM, DM, 0);

    // tensor-core dilated flash attention (g_att unselected positions stay 0)
    attn_tc_kernel<<<dim3(16, 4, 14), 256, ASMEM>>>(qh, ql, kh, vh, patt);

    // MAGNETO sub-LN -> split, out projection
    ln_split_kernel<<<NTOK, 256>>>(patt, lnAw, lnAb, ahi, alo, DM);
    gemm2x_kernel<0><<<gq, 256, GSMEM>>>(ahi, alo, woh,
                                         bo, nullptr, nullptr, px,
                                         nullptr, nullptr, nullptr, nullptr,
                                         DM, DM, 0);

    // LN2 -> split, FF1 (relu)
    ln_split_kernel<<<NTOK, 256>>>(px, ln2w, ln2b, ahi, alo, DM);
    gemm2x_kernel<0><<<g1, 256, GSMEM>>>(ahi, alo, w1h,
                                         b1, nullptr, nullptr, pf1,
                                         nullptr, nullptr, nullptr, nullptr,
                                         DM, DFF, 1);

    // LN3 -> split, FF2
    ln_split_kernel<<<NTOK, 256>>>(pf1, ln3w, ln3b, ahi, alo, DFF);
    gemm2x_kernel<0><<<gq, 256, GSMEM>>>(ahi, alo, w2h,
                                         b2, nullptr, nullptr, out,
                                         nullptr, nullptr, nullptr, nullptr,
                                         DFF, DM, 0);
}

// round 15
// speedup vs baseline: 3.7652x; 1.0000x over previous
#include <cuda_runtime.h>
#include <cuda_fp16.h>
#include <cstdint>

#define NTOK 16384          // B*N = 2*8192
#define NSEQ 8192
#define DM   768
#define DFF  3072
#define NH   12
#define HD   64

typedef __half f16;

// ---------------- scratch (device globals; no allocation allowed) ----------
// g_att is zero-initialized at module load; attention writes exactly the
// dilated-selected positions each run and nothing else ever writes it, so
// unselected positions remain zero across all graph replays (no zero pass).
__device__ float g_x  [NTOK * DM];     // Wo output
__device__ float g_att[NTOK * DM];     // attention output (fp32)
__device__ float g_f1 [NTOK * DFF];
__device__ f16   g_ahi[NTOK * DFF];
__device__ f16   g_alo[NTOK * DFF];
__device__ f16   g_qh [NTOK * DM], g_ql[NTOK * DM];
__device__ f16   g_kh [NTOK * DM];
__device__ f16   g_vh [NTOK * DM];
__device__ f16   g_wqkvh[3 * DM * DM];     // packed Q,K,V weights (hi only)
__device__ f16   g_woh[DM * DM];
__device__ f16   g_w1h[DM * DFF];
__device__ f16   g_w2h[DFF * DM];

// ======================= PTX helpers =======================================
__device__ __forceinline__ uint32_t s2u(const void* p) {
    uint32_t a;
    asm("{ .reg .u64 t; cvta.to.shared.u64 t, %1; cvt.u32.u64 %0, t; }"
        : "=r"(a) : "l"(p));
    return a;
}

#define CP16(dst, src) \
    asm volatile("cp.async.cg.shared.global [%0], [%1], 16;" :: "r"(dst), "l"(src) : "memory")
#define CP_COMMIT() asm volatile("cp.async.commit_group;" ::: "memory")
#define CP_WAIT1()  asm volatile("cp.async.wait_group 1;" ::: "memory")
#define CP_WAIT2()  asm volatile("cp.async.wait_group 2;" ::: "memory")

#define LDSM4(r, a)                                                          \
    asm volatile("ldmatrix.sync.aligned.m8n8.x4.shared.b16 {%0,%1,%2,%3}, [%4];" \
        : "=r"((r)[0]), "=r"((r)[1]), "=r"((r)[2]), "=r"((r)[3]) : "r"(a))

#define LDSM4T(r, a)                                                         \
    asm volatile("ldmatrix.sync.aligned.m8n8.x4.trans.shared.b16 {%0,%1,%2,%3}, [%4];" \
        : "=r"((r)[0]), "=r"((r)[1]), "=r"((r)[2]), "=r"((r)[3]) : "r"(a))

#define MMA16816(c, a, b0, b1)                                               \
    asm volatile("mma.sync.aligned.m16n8k16.row.col.f32.f16.f16.f32 "        \
        "{%0,%1,%2,%3}, {%4,%5,%6,%7}, {%8,%9}, {%0,%1,%2,%3};"              \
        : "+f"((c)[0]), "+f"((c)[1]), "+f"((c)[2]), "+f"((c)[3])             \
        : "r"((a)[0]), "r"((a)[1]), "r"((a)[2]), "r"((a)[3]),                \
          "r"(b0), "r"(b1))

__device__ __forceinline__ uint32_t h2u(__half2 h) {
    return *reinterpret_cast<uint32_t*>(&h);
}

// packed hi/lo split of a float pair (rn rounding — bit-identical to scalar)
__device__ __forceinline__ void split2(float a, float b, uint32_t& hi, uint32_t& lo) {
    __half2 h = __floats2half2_rn(a, b);
    float2 f = __half22float2(h);
    hi = h2u(h);
    lo = h2u(__floats2half2_rn(a - f.x, b - f.y));
}

// ========== LayerNorm fused with fp16 hi/lo split (vectorized) =============
__global__ void ln_split_kernel(const float* __restrict__ x, const float* __restrict__ w,
                                const float* __restrict__ b, f16* __restrict__ hi,
                                f16* __restrict__ lo, int C) {
    long row = blockIdx.x;
    const float4* xr = (const float4*)(x + row * (long)C);
    const int n4 = C >> 2;
    float4 v[3];
    float s = 0.f, ss = 0.f;
    int cnt = 0;
#pragma unroll 3
    for (int c4 = threadIdx.x; c4 < n4; c4 += 256, cnt++) {
        float4 a = xr[c4];
        v[cnt] = a;
        s  += a.x + a.y + a.z + a.w;
        ss += a.x * a.x + a.y * a.y + a.z * a.z + a.w * a.w;
    }
    for (int o = 16; o; o >>= 1) {
        s  += __shfl_xor_sync(0xffffffffu, s,  o);
        ss += __shfl_xor_sync(0xffffffffu, ss, o);
    }
    __shared__ float sh[2][8];
    int wi = threadIdx.x >> 5, li = threadIdx.x & 31;
    if (li == 0) { sh[0][wi] = s; sh[1][wi] = ss; }
    __syncthreads();
    if (threadIdx.x < 32) {
        s  = (li < 8) ? sh[0][li] : 0.f;
        ss = (li < 8) ? sh[1][li] : 0.f;
        for (int o = 4; o; o >>= 1) {
            s  += __shfl_xor_sync(0xffffffffu, s,  o);
            ss += __shfl_xor_sync(0xffffffffu, ss, o);
        }
        if (li == 0) { sh[0][0] = s; sh[1][0] = ss; }
    }
    __syncthreads();
    float mean = sh[0][0] / (float)C;
    float var  = sh[1][0] / (float)C - mean * mean;
    float rstd = rsqrtf(var + 1e-5f);
    uint2* hr = (uint2*)(hi + row * (long)C);
    uint2* lr = (uint2*)(lo + row * (long)C);
    const float4* w4 = (const float4*)w;
    const float4* b4 = (const float4*)b;
    cnt = 0;
#pragma unroll 3
    for (int c4 = threadIdx.x; c4 < n4; c4 += 256, cnt++) {
        float4 a = v[cnt];
        float4 ww = w4[c4], bb = b4[c4];
        float y0 = (a.x - mean) * rstd * ww.x + bb.x;
        float y1 = (a.y - mean) * rstd * ww.y + bb.y;
        float y2 = (a.z - mean) * rstd * ww.z + bb.z;
        float y3 = (a.w - mean) * rstd * ww.w + bb.w;
        uint2 hv, lv;
        split2(y0, y1, hv.x, lv.x);
        split2(y2, y3, hv.y, lv.y);
        hr[c4] = hv;
        lr[c4] = lv;
    }
}

// ======= weight transpose (hi only): W[K,N] -> fp16 [N,K] ==================
__global__ void splitT_kernel(const float* __restrict__ W, f16* __restrict__ hi,
                              int K, int N) {
    __shared__ float t[32][33];
    int k0 = blockIdx.x * 32, n0 = blockIdx.y * 32;
    int tx = threadIdx.x, ty = threadIdx.y;   // 32 x 8
#pragma unroll
    for (int i = 0; i < 4; i++)
        t[ty + 8 * i][tx] = W[(long)(k0 + ty + 8 * i) * N + n0 + tx];
    __syncthreads();
#pragma unroll
    for (int i = 0; i < 4; i++) {
        float v = t[tx][ty + 8 * i];
        hi[(long)(n0 + ty + 8 * i) * K + k0 + tx] = __float2half_rn(v);
    }
}

// ================= mma.sync 2x-fp16 GEMM ===================================
// D = (Ahi+Alo)[M,K] x (Bh[Nrows,K])^T + bias   (B fp16 hi only).
// MODE 0: fp32 out. MODE 2: fused QKV (Q hi/lo scaled 0.125; K,V hi).
// One __syncthreads per chunk; fragment registers double-buffered across ks
// so ks+1's LDSMs issue under ks's MMA burst.
#define GSTAGES 4
#define TILE_B   16384                   // one operand tile: 128 rows x 128 B
#define GSTAGE_B (3 * TILE_B)            // Ah, Al, Bh
#define GSMEM    (GSTAGES * GSTAGE_B)    // 196608

template <int MODE>
__global__ void __launch_bounds__(256, 1)
gemm2x_kernel(const f16* __restrict__ Ahi, const f16* __restrict__ Alo,
              const f16* __restrict__ Bh,
              const float* __restrict__ bias0, const float* __restrict__ bias1,
              const float* __restrict__ bias2, float* __restrict__ C,
              f16* __restrict__ h0, f16* __restrict__ l0,
              f16* __restrict__ h1, f16* __restrict__ h2,
              int Kdim, int Ncols, int relu) {
    extern __shared__ char smraw[];
    const uint32_t sb = s2u(smraw);
    const int tid = threadIdx.x;
    const int m0 = blockIdx.y * 128, n0 = blockIdx.x * 128;
    const int nk = Kdim >> 6;                 // chunks of 64 fp16
    const long rowb = (long)Kdim * 2;         // bytes per gmem row

    const char* pAh = (const char*)Ahi + (long)m0 * rowb;
    const char* pAl = (const char*)Alo + (long)m0 * rowb;
    const char* pBh = (const char*)Bh  + (long)n0 * rowb;

    int lrow[4], lkb[4];
    uint32_t ldst[4];
#pragma unroll
    for (int j = 0; j < 4; j++) {
        int u = tid + 256 * j;
        lrow[j] = u >> 3;
        lkb[j]  = (u & 7) * 16;
        ldst[j] = (uint32_t)(lrow[j] * 128 + (lkb[j] ^ ((lrow[j] & 7) * 16)));
    }

#define LOAD_CHUNK(slot, ci) do {                                            \
    uint32_t stg_ = sb + (slot) * GSTAGE_B;                                  \
    long koff_ = (long)(ci) * 128;                                           \
    _Pragma("unroll")                                                        \
    for (int j = 0; j < 4; j++) {                                            \
        long go = (long)lrow[j] * rowb + koff_ + lkb[j];                     \
        CP16(stg_ + ldst[j],              pAh + go);                         \
        CP16(stg_ + TILE_B + ldst[j],     pAl + go);                         \
        CP16(stg_ + 2 * TILE_B + ldst[j], pBh + go);                         \
    }                                                                        \
} while (0)

    const int wid = tid >> 5, l = tid & 31;
    const int wm = wid & 3, wn = wid >> 2;
    const int quad = l >> 3, rim = l & 7;
    const int rimx = rim * 16;
    const int kbq = (quad >> 1) * 16;

    uint32_t aoff[2], boff[4];
#pragma unroll
    for (int mf = 0; mf < 2; mf++)
        aoff[mf] = (uint32_t)((wm * 32 + mf * 16 + (quad & 1) * 8 + rim) * 128);
#pragma unroll
    for (int np = 0; np < 4; np++)
        boff[np] = (uint32_t)((wn * 64 + np * 16 + (quad & 1) * 8 + rim) * 128);

    float acc[2][8][4];
#pragma unroll
    for (int mf = 0; mf < 2; mf++)
#pragma unroll
        for (int nf = 0; nf < 8; nf++)
#pragma unroll
            for (int c = 0; c < 4; c++) acc[mf][nf][c] = 0.f;

#pragma unroll
    for (int s = 0; s < GSTAGES - 1; s++) {
        LOAD_CHUNK(s, s);
        CP_COMMIT();
    }

    int slot = 0;
    for (int i = 0; i < nk; i++) {
        CP_WAIT2();
        __syncthreads();
        int nc = i + GSTAGES - 1;
        if (nc < nk) LOAD_CHUNK((nc & 3), nc);
        CP_COMMIT();

        const uint32_t stg = sb + slot * GSTAGE_B;
        const uint32_t aH = stg, aL = stg + TILE_B, bH = stg + 2 * TILE_B;

        // fragment double-buffer across ks
        uint32_t ah[2][2][4], al[2][2][4], bh[2][4][4];
        {
            const uint32_t kx = (uint32_t)(kbq ^ rimx);
#pragma unroll
            for (int mf = 0; mf < 2; mf++) {
                LDSM4(ah[0][mf], aH + aoff[mf] + kx);
                LDSM4(al[0][mf], aL + aoff[mf] + kx);
            }
#pragma unroll
            for (int np = 0; np < 4; np++)
                LDSM4(bh[0][np], bH + boff[np] + kx);
        }
#pragma unroll
        for (int ks = 0; ks < 4; ks++) {
            const int cur = ks & 1, nxt = cur ^ 1;
            if (ks < 3) {
                const uint32_t kx = (uint32_t)(((ks + 1) * 32 + kbq) ^ rimx);
#pragma unroll
                for (int mf = 0; mf < 2; mf++) {
                    LDSM4(ah[nxt][mf], aH + aoff[mf] + kx);
                    LDSM4(al[nxt][mf], aL + aoff[mf] + kx);
                }
#pragma unroll
                for (int np = 0; np < 4; np++)
                    LDSM4(bh[nxt][np], bH + boff[np] + kx);
            }
#pragma unroll
            for (int mf = 0; mf < 2; mf++)
#pragma unroll
                for (int nf = 0; nf < 8; nf++) {
                    int np = nf >> 1, hh = nf & 1;
                    MMA16816(acc[mf][nf], ah[cur][mf], bh[cur][np][hh], bh[cur][np][hh + 2]);
                }
#pragma unroll
            for (int mf = 0; mf < 2; mf++)
#pragma unroll
                for (int nf = 0; nf < 8; nf++) {
                    int np = nf >> 1, hh = nf & 1;
                    MMA16816(acc[mf][nf], al[cur][mf], bh[cur][np][hh], bh[cur][np][hh + 2]);
                }
        }
        // no bottom sync: next iteration's top sync is the write-after-read guard
        slot = (slot + 1) & 3;
    }

    // ---------------- epilogue -----------------------------------------
    const float* bp = bias0;
    f16 *chi = h0, *clo = l0;
    float alpha = 1.f;
    int outb = n0;
    if (MODE == 2) {
        int mat = n0 / DM;
        outb = n0 - mat * DM;
        bp  = (mat == 0) ? bias0 : (mat == 1) ? bias1 : bias2;
        chi = (mat == 0) ? h0 : (mat == 1) ? h1 : h2;
        clo = (mat == 0) ? l0 : nullptr;
        alpha = (mat == 0) ? 0.125f : 1.f;
    }
    const int g = l >> 2, t4 = l & 3;
#pragma unroll
    for (int mf = 0; mf < 2; mf++) {
        int row = m0 + wm * 32 + mf * 16 + g;
#pragma unroll
        for (int nf = 0; nf < 8; nf++) {
            int col = outb + wn * 64 + nf * 8 + 2 * t4;
            float b0v = bp[col], b1v = bp[col + 1];
            float v0 = acc[mf][nf][0] + b0v;
            float v1 = acc[mf][nf][1] + b1v;
            float v2 = acc[mf][nf][2] + b0v;
            float v3 = acc[mf][nf][3] + b1v;
            if (MODE == 0 && relu) {
                v0 = fmaxf(v0, 0.f); v1 = fmaxf(v1, 0.f);
                v2 = fmaxf(v2, 0.f); v3 = fmaxf(v3, 0.f);
            }
            if (MODE == 2) {
                v0 *= alpha; v1 *= alpha; v2 *= alpha; v3 *= alpha;
                if (clo) {
                    uint32_t ha, la, hb, lb;
                    split2(v0, v1, ha, la);
                    split2(v2, v3, hb, lb);
                    *(uint32_t*)(chi + (long)row * Ncols + col)       = ha;
                    *(uint32_t*)(chi + (long)(row + 8) * Ncols + col) = hb;
                    *(uint32_t*)(clo + (long)row * Ncols + col)       = la;
                    *(uint32_t*)(clo + (long)(row + 8) * Ncols + col) = lb;
                } else {
                    *(uint32_t*)(chi + (long)row * Ncols + col)       = h2u(__floats2half2_rn(v0, v1));
                    *(uint32_t*)(chi + (long)(row + 8) * Ncols + col) = h2u(__floats2half2_rn(v2, v3));
                }
            } else {
                *(float2*)(C + (long)row * Ncols + col)       = make_float2(v0, v1);
                *(float2*)(C + (long)(row + 8) * Ncols + col) = make_float2(v2, v3);
            }
        }
    }
#undef LOAD_CHUNK
}

// ============== tensor-core dilated flash attention ========================
// CTA = 256 threads / 128 queries; 2 CTAs/SM. 3 KV buffers -> one sync per
// tile. Q hi resident, Q lo re-read from smem.
__constant__ int c_seg[3] = {2048, 4096, 8192};
__constant__ int c_dil[3] = {1, 2, 4};
#define LOG2E 1.4426950408889634f

#define ASM_QH  0
#define ASM_QL  16384
#define ASM_KV  32768
#define ASM_BUF 16384       // per KV buffer: Kh 0-8K, Vh 8K-16K
#define ASMEM   (ASM_KV + 3 * ASM_BUF)   // 81920

__global__ void __launch_bounds__(256, 2)
attn_tc_kernel(const f16* __restrict__ Qh, const f16* __restrict__ Ql,
               const f16* __restrict__ Kh, const f16* __restrict__ Vh,
               float* __restrict__ O) {
    extern __shared__ char smraw[];
    const uint32_t sb = s2u(smraw);

    int z = blockIdx.z;
    int bb = z / 7, t = z % 7;
    int grp, seg;
    if (t < 4)       { grp = 0; seg = t; }
    else if (t < 6)  { grp = 1; seg = t - 4; }
    else             { grp = 2; seg = 0; }
    const int sl = c_seg[grp], rdil = c_dil[grp];
    const int off = grp % rdil;
    const int head = grp * 4 + blockIdx.y;
    const int q0 = blockIdx.x * 128;
    const long segbase = (long)bb * NSEQ + (long)seg * sl;

    const int tid = threadIdx.x;
    // Q loader: 256 threads cover 128 rows x 128 B
    const int qrow_l = tid >> 1;
    const int qkb0 = (tid & 1) * 64;
    uint32_t qdst[4];
#pragma unroll
    for (int j = 0; j < 4; j++) {
        int kb = qkb0 + j * 16;
        qdst[j] = (uint32_t)(qrow_l * 128 + (kb ^ ((qrow_l & 7) * 16)));
    }
    // KV loader: 256 threads cover 64 rows x 128 B per operand
    const int krow_l = tid >> 2;
    const int kkb0 = (tid & 3) * 32;
    uint32_t kdst[2];
#pragma unroll
    for (int j = 0; j < 2; j++) {
        int kb = kkb0 + j * 16;
        kdst[j] = (uint32_t)(krow_l * 128 + (kb ^ ((krow_l & 7) * 16)));
    }

    // ---- load Q tile (hi+lo): group 0 ----
    {
        long fo = (segbase + off + (long)(q0 + qrow_l) * rdil) * DM + head * HD;
        const char* gh = (const char*)(Qh + fo);
        const char* gl = (const char*)(Ql + fo);
#pragma unroll
        for (int j = 0; j < 4; j++) {
            CP16(sb + ASM_QH + qdst[j], gh + qkb0 + j * 16);
            CP16(sb + ASM_QL + qdst[j], gl + qkb0 + j * 16);
        }
    }
    CP_COMMIT();

#define LOAD_KV(ti, buf) do {                                                \
    long fo_ = (segbase + off + (long)((ti) * 64 + krow_l) * rdil) * DM + head * HD; \
    uint32_t bs_ = sb + ASM_KV + (buf) * ASM_BUF;                            \
    const char* gkh_ = (const char*)(Kh + fo_);                              \
    const char* gvh_ = (const char*)(Vh + fo_);                              \
    _Pragma("unroll")                                                        \
    for (int j = 0; j < 2; j++) {                                            \
        CP16(bs_ + kdst[j],        gkh_ + kkb0 + j * 16);                    \
        CP16(bs_ + 8192 + kdst[j], gvh_ + kkb0 + j * 16);                    \
    }                                                                        \
} while (0)

    LOAD_KV(0, 0);
    CP_COMMIT();           // group 1
    LOAD_KV(1, 1);
    CP_COMMIT();           // group 2
    CP_WAIT2();            // Q (group 0) retired
    __syncthreads();

    // ---- per-warp fragment addressing ----
    const int l = tid & 31, w = tid >> 5;
    const int mi = l >> 3, rr = l & 7;
    const int rbase = (mi & 1) * 8 + rr;    // row within a 16-row block
    const int cxor = rr * 16;               // SW128 xor term
    const int ksel = (mi >> 1) * 16;        // 8-col (16B) selector
    const uint32_t qrow = (uint32_t)((w * 16 + rbase) * 128);

    // Q hi fragments resident; Q lo re-read per tile
    uint32_t qfh[4][4];
#pragma unroll
    for (int ks = 0; ks < 4; ks++) {
        uint32_t cb = (uint32_t)((ks * 32 + ksel) ^ cxor);
        LDSM4(qfh[ks], sb + ASM_QH + qrow + cb);
    }

    float Oa[8][4];
#pragma unroll
    for (int nf = 0; nf < 8; nf++)
#pragma unroll
        for (int c = 0; c < 4; c++) Oa[nf][c] = 0.f;
    float m0 = -1e30f, m1 = -1e30f, l0 = 0.f, l1 = 0.f;

    int bufc = 0;            // buffer of current tile kt
    for (int kt = 0; kt < 32; kt++) {
        CP_WAIT1();          // tile kt landed (kt+1 may be in flight)
        __syncthreads();     // also guards buffer (kt+2)%3 (read at kt-1)
        if (kt + 2 < 32) {
            int nb = bufc + 2;
            if (nb >= 3) nb -= 3;
            LOAD_KV(kt + 2, nb);
        }
        CP_COMMIT();

        const uint32_t bs = sb + ASM_KV + bufc * ASM_BUF;

        // ---- S = Q K^T (2-pass), fp32 acc; 16q x 64kv per warp ----
        float S[8][4];
#pragma unroll
        for (int nf = 0; nf < 8; nf++)
#pragma unroll
            for (int c = 0; c < 4; c++) S[nf][c] = 0.f;

#pragma unroll
        for (int ks = 0; ks < 4; ks++) {
            uint32_t cb = (uint32_t)((ks * 32 + ksel) ^ cxor);
            uint32_t bh[4][4], qfl[4];
            LDSM4(qfl, sb + ASM_QL + qrow + cb);
#pragma unroll
            for (int np = 0; np < 4; np++) {
                uint32_t ro = (uint32_t)((np * 16 + rbase) * 128);
                LDSM4(bh[np], bs + ro + cb);
            }
#pragma unroll
            for (int nf = 0; nf < 8; nf++) {
                int np = nf >> 1, hh = nf & 1;
                MMA16816(S[nf], qfh[ks], bh[np][hh], bh[np][hh + 2]);
            }
#pragma unroll
            for (int nf = 0; nf < 8; nf++) {
                int np = nf >> 1, hh = nf & 1;
                MMA16816(S[nf], qfl, bh[np][hh], bh[np][hh + 2]);
            }
        }

        // ---- online softmax in base-2 (rows r=l>>2 and r+8) ----
        float mx0 = -1e30f, mx1 = -1e30f;
#pragma unroll
        for (int nf = 0; nf < 8; nf++) {
            mx0 = fmaxf(mx0, fmaxf(S[nf][0], S[nf][1]));
            mx1 = fmaxf(mx1, fmaxf(S[nf][2], S[nf][3]));
        }
        mx0 = fmaxf(mx0, __shfl_xor_sync(0xffffffffu, mx0, 1));
        mx0 = fmaxf(mx0, __shfl_xor_sync(0xffffffffu, mx0, 2));
        mx1 = fmaxf(mx1, __shfl_xor_sync(0xffffffffu, mx1, 1));
        mx1 = fmaxf(mx1, __shfl_xor_sync(0xffffffffu, mx1, 2));
        float nm0 = fmaxf(m0, mx0), nm1 = fmaxf(m1, mx1);
        float fac0 = exp2f((m0 - nm0) * LOG2E), fac1 = exp2f((m1 - nm1) * LOG2E);
        m0 = nm0; m1 = nm1;
        float c0 = nm0 * LOG2E, c1 = nm1 * LOG2E;
        float rs0 = 0.f, rs1 = 0.f;
#pragma unroll
        for (int nf = 0; nf < 8; nf++) {
            S[nf][0] = exp2f(S[nf][0] * LOG2E - c0); rs0 += S[nf][0];
            S[nf][1] = exp2f(S[nf][1] * LOG2E - c0); rs0 += S[nf][1];
            S[nf][2] = exp2f(S[nf][2] * LOG2E - c1); rs1 += S[nf][2];
            S[nf][3] = exp2f(S[nf][3] * LOG2E - c1); rs1 += S[nf][3];
        }
        rs0 += __shfl_xor_sync(0xffffffffu, rs0, 1);
        rs0 += __shfl_xor_sync(0xffffffffu, rs0, 2);
        rs1 += __shfl_xor_sync(0xffffffffu, rs1, 1);
        rs1 += __shfl_xor_sync(0xffffffffu, rs1, 2);
        l0 = l0 * fac0 + rs0;
        l1 = l1 * fac1 + rs1;
#pragma unroll
        for (int nf = 0; nf < 8; nf++) {
            Oa[nf][0] *= fac0; Oa[nf][1] *= fac0;
            Oa[nf][2] *= fac1; Oa[nf][3] *= fac1;
        }

        // ---- O += P V (2-pass: Ph, Pl); packed hi/lo split ----
#pragma unroll
        for (int j = 0; j < 4; j++) {
            uint32_t pah[4], pal[4];
            {
                const float* s0 = S[2 * j];
                const float* s1 = S[2 * j + 1];
                split2(s0[0], s0[1], pah[0], pal[0]);
                split2(s0[2], s0[3], pah[1], pal[1]);
                split2(s1[0], s1[1], pah[2], pal[2]);
                split2(s1[2], s1[3], pah[3], pal[3]);
            }
            uint32_t vh[4][4];
#pragma unroll
            for (int np = 0; np < 4; np++) {
                uint32_t ro = (uint32_t)((j * 16 + rbase) * 128);
                uint32_t cb = (uint32_t)((np * 32 + ksel) ^ cxor);
                LDSM4T(vh[np], bs + 8192 + ro + cb);
            }
#pragma unroll
            for (int nf = 0; nf < 8; nf++) {
                int np = nf >> 1, hh = nf & 1;
                MMA16816(Oa[nf], pah, vh[np][hh * 2], vh[np][hh * 2 + 1]);
            }
#pragma unroll
            for (int nf = 0; nf < 8; nf++) {
                int np = nf >> 1, hh = nf & 1;
                MMA16816(Oa[nf], pal, vh[np][hh * 2], vh[np][hh * 2 + 1]);
            }
        }
        // no bottom sync: 3 buffers + top sync cover the overwrite hazard
        if (++bufc == 3) bufc = 0;
    }

    // ---- epilogue ----
    float inv0 = 1.f / l0, inv1 = 1.f / l1;
    int r0 = q0 + w * 16 + (l >> 2);
    long n0tok = segbase + off + (long)r0 * rdil;
    long n1tok = segbase + off + (long)(r0 + 8) * rdil;
    float* o0 = O + n0tok * DM + head * HD;
    float* o1 = O + n1tok * DM + head * HD;
    int cbase = (l & 3) * 2;
#pragma unroll
    for (int nf = 0; nf < 8; nf++) {
        int col = nf * 8 + cbase;
        *(float2*)(o0 + col) = make_float2(Oa[nf][0] * inv0, Oa[nf][1] * inv0);
        *(float2*)(o1 + col) = make_float2(Oa[nf][2] * inv1, Oa[nf][3] * inv1);
    }
#undef LOAD_KV
}

// ---------------- host orchestration ---------------------------------------
extern "C" void kernel_launch(void* const* d_in, const int* in_sizes, int n_in,
                              void* d_out, int out_size) {
    const float* src  = (const float*)d_in[0];
    const float* ln1w = (const float*)d_in[1];
    const float* ln1b = (const float*)d_in[2];
    const float* Wq   = (const float*)d_in[3];
    const float* bq   = (const float*)d_in[4];
    const float* Wk   = (const float*)d_in[5];
    const float* bk   = (const float*)d_in[6];
    const float* Wv   = (const float*)d_in[7];
    const float* bv   = (const float*)d_in[8];
    const float* lnAw = (const float*)d_in[9];
    const float* lnAb = (const float*)d_in[10];
    const float* Wo   = (const float*)d_in[11];
    const float* bo   = (const float*)d_in[12];
    const float* ln2w = (const float*)d_in[13];
    const float* ln2b = (const float*)d_in[14];
    const float* W1   = (const float*)d_in[15];
    const float* b1   = (const float*)d_in[16];
    const float* ln3w = (const float*)d_in[17];
    const float* ln3b = (const float*)d_in[18];
    const float* W2   = (const float*)d_in[19];
    const float* b2   = (const float*)d_in[20];
    float* out = (float*)d_out;

    float *px, *patt, *pf1;
    f16 *ahi, *alo, *qh, *ql, *kh, *vh;
    f16 *wqkvh, *woh, *w1h, *w2h;
    cudaGetSymbolAddress((void**)&px,    g_x);
    cudaGetSymbolAddress((void**)&patt,  g_att);
    cudaGetSymbolAddress((void**)&pf1,   g_f1);
    cudaGetSymbolAddress((void**)&ahi,   g_ahi);
    cudaGetSymbolAddress((void**)&alo,   g_alo);
    cudaGetSymbolAddress((void**)&qh,    g_qh);
    cudaGetSymbolAddress((void**)&ql,    g_ql);
    cudaGetSymbolAddress((void**)&kh,    g_kh);
    cudaGetSymbolAddress((void**)&vh,    g_vh);
    cudaGetSymbolAddress((void**)&wqkvh, g_wqkvh);
    cudaGetSymbolAddress((void**)&woh,   g_woh);
    cudaGetSymbolAddress((void**)&w1h,   g_w1h);
    cudaGetSymbolAddress((void**)&w2h,   g_w2h);

    static bool attr_done = false;
    if (!attr_done) {
        cudaFuncSetAttribute(gemm2x_kernel<0>, cudaFuncAttributeMaxDynamicSharedMemorySize, GSMEM);
        cudaFuncSetAttribute(gemm2x_kernel<2>, cudaFuncAttributeMaxDynamicSharedMemorySize, GSMEM);
        cudaFuncSetAttribute(attn_tc_kernel, cudaFuncAttributeMaxDynamicSharedMemorySize, ASMEM);
        attr_done = true;
    }

    dim3 tT(32, 8);
    dim3 gW(DM / 32, DM / 32);
    dim3 gW1(DM / 32, DFF / 32);
    dim3 gW2(DFF / 32, DM / 32);
    dim3 gq(DM / 128, NTOK / 128);        // (6,128)
    dim3 gqkv(3 * DM / 128, NTOK / 128);  // (18,128)
    dim3 g1(DFF / 128, NTOK / 128);       // (24,128)

    // Launch order places attn_tc_kernel at index 5 (ncu -s 5 -c 1 target).
    // 0-2: QKV weight transposes
    splitT_kernel<<<gW,  tT>>>(Wq, wqkvh,               DM, DM);
    splitT_kernel<<<gW,  tT>>>(Wk, wqkvh + DM * DM,     DM, DM);
    splitT_kernel<<<gW,  tT>>>(Wv, wqkvh + 2 * DM * DM, DM, DM);
    // 3: LN1 -> split
    ln_split_kernel<<<NTOK, 256>>>(src, ln1w, ln1b, ahi, alo, DM);
    // 4: fused QKV projection (Q hi/lo pre-scaled 0.125; K,V hi)
    gemm2x_kernel<2><<<gqkv, 256, GSMEM>>>(ahi, alo, wqkvh,
                                           bq, bk, bv, nullptr,
                                           qh, ql, kh, vh, DM, DM, 0);
    // 5: tensor-core dilated flash attention  <-- profiled launch
    attn_tc_kernel<<<dim3(16, 4, 14), 256, ASMEM>>>(qh, ql, kh, vh, patt);

    // 6: Wo weight transpose; 7: MAGNETO sub-LN; 8: out projection
    splitT_kernel<<<gW, tT>>>(Wo, woh, DM, DM);
    ln_split_kernel<<<NTOK, 256>>>(patt, lnAw, lnAb, ahi, alo, DM);
    gemm2x_kernel<0><<<gq, 256, GSMEM>>>(ahi, alo, woh,
                                         bo, nullptr, nullptr, px,
                                         nullptr, nullptr, nullptr, nullptr,
                                         DM, DM, 0);

    // 9: W1 transpose; 10: LN2; 11: FF1 (relu)
    splitT_kernel<<<gW1, tT>>>(W1, w1h, DM, DFF);
    ln_split_kernel<<<NTOK, 256>>>(px, ln2w, ln2b, ahi, alo, DM);
    gemm2x_kernel<0><<<g1, 256, GSMEM>>>(ahi, alo, w1h,
                                         b1, nullptr, nullptr, pf1,
                                         nullptr, nullptr, nullptr, nullptr,
                                         DM, DFF, 1);

    // 12: W2 transpose; 13: LN3; 14: FF2
    splitT_kernel<<<gW2, tT>>>(W2, w2h, DFF, DM);
    ln_split_kernel<<<NTOK, 256>>>(pf1, ln3w, ln3b, ahi, alo, DFF);
    gemm2x_kernel<0><<<gq, 256, GSMEM>>>(ahi, alo, w2h,
                                         b2, nullptr, nullptr, out,
                                         nullptr, nullptr, nullptr, nullptr,
                                         DFF, DM, 0);
}